// round 1
// baseline (speedup 1.0000x reference)
#include <cuda_runtime.h>
#include <math.h>

#define BB 8
#define LMAX 1024
#define DIM 512
#define HEADS 8
#define DH 64
#define NDEPTH 6
#define MLPD 2048
#define NC 1000
#define PDIM 768
#define NTOK (BB*LMAX)   // 8192

// Per-image valid token counts and patch-grid widths (from IMG_SIZES, P=16)
__constant__ int c_L[8]  = {1024, 768, 896, 576, 560, 512, 384, 640};
__constant__ int c_Wp[8] = {  32,  24,  32,  24,  28,  32,  16,  20};

// ---------------- scratch (static device memory; no allocations) ----------------
__device__ float g_tok[(size_t)NTOK*PDIM];
__device__ float g_lt [(size_t)NTOK*PDIM];
__device__ float g_t  [(size_t)NTOK*DIM];
__device__ float g_xn [(size_t)NTOK*DIM];
__device__ float g_q  [(size_t)NTOK*DIM];
__device__ float g_k  [(size_t)NTOK*DIM];
__device__ float g_v  [(size_t)NTOK*DIM];
__device__ float g_o  [(size_t)NTOK*DIM];
__device__ float g_mlp[(size_t)NTOK*MLPD];
__device__ float g_s  [(size_t)BB*HEADS*LMAX*LMAX];
__device__ float g_u  [DIM];
__device__ float g_qp [DIM];
__device__ float g_po [BB*DIM];
__device__ float g_pooled[BB*DIM];
__device__ float g_hn [BB*DIM];

// ---------------- patch packing ----------------
__global__ void pack_kernel(const float* __restrict__ img, float* __restrict__ tok){
    size_t i = (size_t)blockIdx.x*blockDim.x + threadIdx.x;
    if (i >= (size_t)NTOK*PDIM) return;
    int pd = (int)(i % PDIM);
    size_t bl = i / PDIM;
    int l = (int)(bl % LMAX);
    int b = (int)(bl / LMAX);
    int L = c_L[b], w = c_Wp[b];
    float v = 0.f;
    if (l < L){
        int c  = pd >> 8;
        int r  = pd & 255;
        int py = r >> 4, px = r & 15;
        int ph = l / w, pw = l % w;
        v = img[((size_t)(b*3 + c)*512 + (size_t)(ph*16 + py))*512 + (size_t)(pw*16 + px)];
    }
    tok[i] = v;
}

// ---------------- generic row LayerNorm (D <= 768), blockDim must be 256 ----------------
__global__ void ln_kernel(const float* __restrict__ x, const float* __restrict__ w,
                          const float* __restrict__ bb, float* __restrict__ y, int D){
    __shared__ float red[8];
    int row = blockIdx.x, tid = threadIdx.x, lane = tid & 31, wp = tid >> 5;
    const float* xr = x + (size_t)row*D;
    float lv[3]; float s = 0.f;
    #pragma unroll
    for (int i = 0; i < 3; i++){
        int idx = tid + i*256;
        float vv = (idx < D) ? xr[idx] : 0.f;
        lv[i] = vv; s += vv;
    }
    #pragma unroll
    for (int off = 16; off; off >>= 1) s += __shfl_xor_sync(0xffffffffu, s, off);
    if (lane == 0) red[wp] = s;
    __syncthreads();
    float tot = 0.f;
    #pragma unroll
    for (int i = 0; i < 8; i++) tot += red[i];
    float mu = tot / (float)D;
    __syncthreads();
    float vs = 0.f;
    #pragma unroll
    for (int i = 0; i < 3; i++){
        int idx = tid + i*256;
        if (idx < D){ float d = lv[i] - mu; vs += d*d; }
    }
    #pragma unroll
    for (int off = 16; off; off >>= 1) vs += __shfl_xor_sync(0xffffffffu, vs, off);
    if (lane == 0) red[wp] = vs;
    __syncthreads();
    float tv = 0.f;
    #pragma unroll
    for (int i = 0; i < 8; i++) tv += red[i];
    float rs = rsqrtf(tv / (float)D + 1e-5f);
    float* yr = y + (size_t)row*D;
    #pragma unroll
    for (int i = 0; i < 3; i++){
        int idx = tid + i*256;
        if (idx < D){
            float val = (lv[i] - mu)*rs*w[idx];
            if (bb) val += bb[idx];
            yr[idx] = val;
        }
    }
}

// ---------------- per-head LayerNorm over 64 dims (warp per row), in-place ----------------
__global__ void head_ln_kernel(float* __restrict__ x, const float* __restrict__ w, int rows){
    int gw = (int)(((size_t)blockIdx.x*blockDim.x + threadIdx.x) >> 5);
    int lane = threadIdx.x & 31;
    if (gw >= rows) return;
    float* p = x + (size_t)gw*64;
    float a = p[lane], b = p[lane + 32];
    float s = a + b;
    #pragma unroll
    for (int off = 16; off; off >>= 1) s += __shfl_xor_sync(0xffffffffu, s, off);
    float mu = s * (1.f/64.f);
    float da = a - mu, db = b - mu;
    float vs = da*da + db*db;
    #pragma unroll
    for (int off = 16; off; off >>= 1) vs += __shfl_xor_sync(0xffffffffu, vs, off);
    float rs = rsqrtf(vs * (1.f/64.f) + 1e-5f);
    p[lane]      = da * rs * w[lane];
    p[lane + 32] = db * rs * w[lane + 32];
}

// ---------------- pos embed + mask ----------------
__global__ void posmask_kernel(float* __restrict__ t, const float* __restrict__ ph,
                               const float* __restrict__ pw){
    int bl = blockIdx.x;
    int b = bl >> 10, l = bl & 1023;
    int L = c_L[b], w = c_Wp[b];
    float* r = t + (size_t)bl*DIM;
    int d = threadIdx.x;
    if (l < L) r[d] = r[d] + ph[(size_t)(l / w)*DIM + d] + pw[(size_t)(l % w)*DIM + d];
    else       r[d] = 0.f;
}

// ---------------- masked softmax over 1024 keys; blockDim 256 ----------------
__global__ void softmax_kernel(float* __restrict__ S){
    __shared__ float red[8], red2[8];
    int row = blockIdx.x;         // b*8192 + h*1024 + q
    int b = row >> 13;
    int L = c_L[b];
    float* s = S + (size_t)row*1024;
    int tid = threadIdx.x, lane = tid & 31, wp = tid >> 5;
    float4 v4 = ((const float4*)s)[tid];
    float vl[4] = {v4.x, v4.y, v4.z, v4.w};
    int k0 = tid*4;
    #pragma unroll
    for (int j = 0; j < 4; j++) if (k0 + j >= L) vl[j] = -1e9f;
    float m = fmaxf(fmaxf(vl[0], vl[1]), fmaxf(vl[2], vl[3]));
    #pragma unroll
    for (int off = 16; off; off >>= 1) m = fmaxf(m, __shfl_xor_sync(0xffffffffu, m, off));
    if (lane == 0) red[wp] = m;
    __syncthreads();
    float bm = -1e30f;
    #pragma unroll
    for (int i = 0; i < 8; i++) bm = fmaxf(bm, red[i]);
    float sum = 0.f;
    #pragma unroll
    for (int j = 0; j < 4; j++){ vl[j] = __expf(vl[j] - bm); sum += vl[j]; }
    #pragma unroll
    for (int off = 16; off; off >>= 1) sum += __shfl_xor_sync(0xffffffffu, sum, off);
    if (lane == 0) red2[wp] = sum;
    __syncthreads();
    float bs = 0.f;
    #pragma unroll
    for (int i = 0; i < 8; i++) bs += red2[i];
    float inv = 1.f / bs;
    float4 o4 = make_float4(vl[0]*inv, vl[1]*inv, vl[2]*inv, vl[3]*inv);
    ((float4*)s)[tid] = o4;
}

// ---------------- GEMM NT: C = alpha*(A @ W^T) [+bias][gelu][+R] ----------------
// A[M,K] (lda), W[N,K] (ldw). Batched via blockIdx.z: off = (z/zdiv)*hi + (z%zdiv)*lo.
__global__ __launch_bounds__(256) void gemm_nt_kernel(
    const float* __restrict__ A, int lda, long hiA, long loA,
    const float* __restrict__ W, int ldw, long hiW, long loW,
    const float* __restrict__ bias,
    const float* __restrict__ R, int ldr,
    float* __restrict__ C, int ldc, long hiC, long loC,
    int M, int N, int K, float alpha, int act, int zdiv)
{
    __shared__ __align__(16) float As[8][128];
    __shared__ __align__(16) float Bs[8][128];
    int z = blockIdx.z;
    int zh = z / zdiv, zl = z % zdiv;
    A += (size_t)zh*hiA + (size_t)zl*loA;
    W += (size_t)zh*hiW + (size_t)zl*loW;
    C += (size_t)zh*hiC + (size_t)zl*loC;
    int bm = blockIdx.y*128, bn = blockIdx.x*128;
    int tid = threadIdx.x;
    int tx = tid & 15, ty = tid >> 4;
    float acc[8][8];
    #pragma unroll
    for (int i = 0; i < 8; i++)
        #pragma unroll
        for (int j = 0; j < 8; j++) acc[i][j] = 0.f;
    int lr = tid >> 1;
    int lk = (tid & 1)*4;
    for (int k0 = 0; k0 < K; k0 += 8){
        float4 av = make_float4(0,0,0,0), bv = make_float4(0,0,0,0);
        if (bm + lr < M) av = *(const float4*)(A + (size_t)(bm + lr)*lda + k0 + lk);
        if (bn + lr < N) bv = *(const float4*)(W + (size_t)(bn + lr)*ldw + k0 + lk);
        As[lk+0][lr] = av.x; As[lk+1][lr] = av.y; As[lk+2][lr] = av.z; As[lk+3][lr] = av.w;
        Bs[lk+0][lr] = bv.x; Bs[lk+1][lr] = bv.y; Bs[lk+2][lr] = bv.z; Bs[lk+3][lr] = bv.w;
        __syncthreads();
        #pragma unroll
        for (int kk = 0; kk < 8; kk++){
            float a[8], b[8];
            #pragma unroll
            for (int i = 0; i < 8; i++) a[i] = As[kk][ty*8 + i];
            #pragma unroll
            for (int j = 0; j < 8; j++) b[j] = Bs[kk][tx*8 + j];
            #pragma unroll
            for (int i = 0; i < 8; i++)
                #pragma unroll
                for (int j = 0; j < 8; j++) acc[i][j] = fmaf(a[i], b[j], acc[i][j]);
        }
        __syncthreads();
    }
    #pragma unroll
    for (int i = 0; i < 8; i++){
        int m = bm + ty*8 + i;
        if (m >= M) continue;
        #pragma unroll
        for (int j = 0; j < 8; j++){
            int n = bn + tx*8 + j;
            if (n >= N) continue;
            float v = acc[i][j]*alpha;
            if (bias) v += bias[n];
            if (act) v = 0.5f*v*(1.f + erff(v*0.70710678118654752f));
            if (R) v += R[(size_t)m*ldr + n];
            C[(size_t)m*ldc + n] = v;
        }
    }
}

// ---------------- GEMM NN: C = A @ Bm  (A[M,K] lda, Bm[K,N] ldb) ----------------
__global__ __launch_bounds__(256) void gemm_nn_kernel(
    const float* __restrict__ A, int lda, long hiA, long loA,
    const float* __restrict__ Bm, int ldb, long hiB, long loB,
    float* __restrict__ C, int ldc, long hiC, long loC,
    int M, int N, int K, int zdiv)
{
    __shared__ __align__(16) float As[8][128];
    __shared__ __align__(16) float Bs[8][128];
    int z = blockIdx.z;
    int zh = z / zdiv, zl = z % zdiv;
    A  += (size_t)zh*hiA + (size_t)zl*loA;
    Bm += (size_t)zh*hiB + (size_t)zl*loB;
    C  += (size_t)zh*hiC + (size_t)zl*loC;
    int bm = blockIdx.y*128, bn = blockIdx.x*128;
    int tid = threadIdx.x;
    int tx = tid & 15, ty = tid >> 4;
    float acc[8][8];
    #pragma unroll
    for (int i = 0; i < 8; i++)
        #pragma unroll
        for (int j = 0; j < 8; j++) acc[i][j] = 0.f;
    int lr = tid >> 1;
    int lk = (tid & 1)*4;
    int bkk = tid >> 5;         // 0..7
    int bn4 = (tid & 31)*4;     // 0..124
    for (int k0 = 0; k0 < K; k0 += 8){
        float4 av = make_float4(0,0,0,0), bv = make_float4(0,0,0,0);
        if (bm + lr < M) av = *(const float4*)(A + (size_t)(bm + lr)*lda + k0 + lk);
        if (bn + bn4 < N) bv = *(const float4*)(Bm + (size_t)(k0 + bkk)*ldb + bn + bn4);
        As[lk+0][lr] = av.x; As[lk+1][lr] = av.y; As[lk+2][lr] = av.z; As[lk+3][lr] = av.w;
        Bs[bkk][bn4+0] = bv.x; Bs[bkk][bn4+1] = bv.y; Bs[bkk][bn4+2] = bv.z; Bs[bkk][bn4+3] = bv.w;
        __syncthreads();
        #pragma unroll
        for (int kk = 0; kk < 8; kk++){
            float a[8], b[8];
            #pragma unroll
            for (int i = 0; i < 8; i++) a[i] = As[kk][ty*8 + i];
            #pragma unroll
            for (int j = 0; j < 8; j++) b[j] = Bs[kk][tx*8 + j];
            #pragma unroll
            for (int i = 0; i < 8; i++)
                #pragma unroll
                for (int j = 0; j < 8; j++) acc[i][j] = fmaf(a[i], b[j], acc[i][j]);
        }
        __syncthreads();
    }
    #pragma unroll
    for (int i = 0; i < 8; i++){
        int m = bm + ty*8 + i;
        if (m >= M) continue;
        #pragma unroll
        for (int j = 0; j < 8; j++){
            int n = bn + tx*8 + j;
            if (n >= N) continue;
            C[(size_t)m*ldc + n] = acc[i][j];
        }
    }
}

// ---------------- pooling attention (Lq=1), one block per (h,b) ----------------
__global__ void pool_attn_kernel(const float* __restrict__ qhat, const float* __restrict__ K,
                                 const float* __restrict__ V, float* __restrict__ O){
    int h = blockIdx.x, b = blockIdx.y;
    __shared__ float sq[64];
    __shared__ float sa[1024];
    __shared__ float red[8], red2[8];
    __shared__ float racc[4][64];
    int tid = threadIdx.x, lane = tid & 31, wp = tid >> 5;
    if (tid < 64) sq[tid] = qhat[h*64 + tid];
    __syncthreads();
    int L = c_L[b];
    for (int kk = tid; kk < 1024; kk += 256){
        float dot = -1e9f;
        if (kk < L){
            const float* kr = K + ((size_t)(b*1024 + kk))*DIM + h*64;
            float ss = 0.f;
            #pragma unroll
            for (int d = 0; d < 64; d++) ss += sq[d]*kr[d];
            dot = ss*0.125f;
        }
        sa[kk] = dot;
    }
    __syncthreads();
    float m = -1e30f;
    for (int kk = tid; kk < 1024; kk += 256) m = fmaxf(m, sa[kk]);
    #pragma unroll
    for (int off = 16; off; off >>= 1) m = fmaxf(m, __shfl_xor_sync(0xffffffffu, m, off));
    if (lane == 0) red[wp] = m;
    __syncthreads();
    float bm = -1e30f;
    #pragma unroll
    for (int i = 0; i < 8; i++) bm = fmaxf(bm, red[i]);
    float sum = 0.f;
    for (int kk = tid; kk < 1024; kk += 256){
        float e = __expf(sa[kk] - bm);
        sa[kk] = e; sum += e;
    }
    #pragma unroll
    for (int off = 16; off; off >>= 1) sum += __shfl_xor_sync(0xffffffffu, sum, off);
    if (lane == 0) red2[wp] = sum;
    __syncthreads();
    float bs = 0.f;
    #pragma unroll
    for (int i = 0; i < 8; i++) bs += red2[i];
    float inv = 1.f / bs;
    int dd = tid & 63, part = tid >> 6;
    float acc = 0.f;
    for (int kk = part; kk < 1024; kk += 4)
        acc += sa[kk] * V[((size_t)(b*1024 + kk))*DIM + h*64 + dd];
    racc[part][dd] = acc;
    __syncthreads();
    if (part == 0)
        O[b*DIM + h*64 + dd] = (racc[0][dd] + racc[1][dd] + racc[2][dd] + racc[3][dd]) * inv;
}

// ---------------- host helpers ----------------
static void launch_nt(const float* A, int lda, long hiA, long loA,
                      const float* W, int ldw, long hiW, long loW,
                      const float* bias, const float* R, int ldr,
                      float* C, int ldc, long hiC, long loC,
                      int M, int N, int K, float alpha, int act, int nz, int zdiv){
    dim3 g((N + 127)/128, (M + 127)/128, nz);
    gemm_nt_kernel<<<g, 256>>>(A, lda, hiA, loA, W, ldw, hiW, loW, bias, R, ldr,
                               C, ldc, hiC, loC, M, N, K, alpha, act, zdiv);
}
static void launch_nn(const float* A, int lda, long hiA, long loA,
                      const float* Bm, int ldb, long hiB, long loB,
                      float* C, int ldc, long hiC, long loC,
                      int M, int N, int K, int nz, int zdiv){
    dim3 g((N + 127)/128, (M + 127)/128, nz);
    gemm_nn_kernel<<<g, 256>>>(A, lda, hiA, loA, Bm, ldb, hiB, loB,
                               C, ldc, hiC, loC, M, N, K, zdiv);
}

extern "C" void kernel_launch(void* const* d_in, const int* in_sizes, int n_in,
                              void* d_out, int out_size){
    const float* images   = (const float*)d_in[0];
    const float* pe_ln1_w = (const float*)d_in[1];
    const float* pe_ln1_b = (const float*)d_in[2];
    const float* pe_w     = (const float*)d_in[3];
    const float* pe_b     = (const float*)d_in[4];
    const float* pe_ln2_w = (const float*)d_in[5];
    const float* pe_ln2_b = (const float*)d_in[6];
    const float* pos_h    = (const float*)d_in[7];
    const float* pos_w    = (const float*)d_in[8];
    const float* attn_ln  = (const float*)d_in[9];
    const float* wq       = (const float*)d_in[10];
    const float* wk       = (const float*)d_in[11];
    const float* wv       = (const float*)d_in[12];
    const float* qn       = (const float*)d_in[13];
    const float* kn       = (const float*)d_in[14];
    const float* wo       = (const float*)d_in[15];
    const float* ff_ln    = (const float*)d_in[16];
    const float* ff_w1    = (const float*)d_in[17];
    const float* ff_b1    = (const float*)d_in[18];
    const float* ff_w2    = (const float*)d_in[19];
    const float* ff_b2    = (const float*)d_in[20];
    const float* final_ln = (const float*)d_in[21];
    const float* pool_q   = (const float*)d_in[22];
    const float* pool_ln  = (const float*)d_in[23];
    const float* pool_wq  = (const float*)d_in[24];
    const float* pool_wk  = (const float*)d_in[25];
    const float* pool_wv  = (const float*)d_in[26];
    const float* pool_qn  = (const float*)d_in[27];
    const float* pool_kn  = (const float*)d_in[28];
    const float* pool_wo  = (const float*)d_in[29];
    const float* head_ln  = (const float*)d_in[30];
    const float* head_w   = (const float*)d_in[31];
    float* out = (float*)d_out;

    float *tok,*lt,*t,*xn,*q,*k,*v,*o,*mlp,*s,*u,*qp,*po,*pooled,*hn;
    cudaGetSymbolAddress((void**)&tok, g_tok);
    cudaGetSymbolAddress((void**)&lt,  g_lt);
    cudaGetSymbolAddress((void**)&t,   g_t);
    cudaGetSymbolAddress((void**)&xn,  g_xn);
    cudaGetSymbolAddress((void**)&q,   g_q);
    cudaGetSymbolAddress((void**)&k,   g_k);
    cudaGetSymbolAddress((void**)&v,   g_v);
    cudaGetSymbolAddress((void**)&o,   g_o);
    cudaGetSymbolAddress((void**)&mlp, g_mlp);
    cudaGetSymbolAddress((void**)&s,   g_s);
    cudaGetSymbolAddress((void**)&u,   g_u);
    cudaGetSymbolAddress((void**)&qp,  g_qp);
    cudaGetSymbolAddress((void**)&po,  g_po);
    cudaGetSymbolAddress((void**)&pooled, g_pooled);
    cudaGetSymbolAddress((void**)&hn,  g_hn);

    const long QS = (long)LMAX*DIM;            // per-image stride in q/k/v/o (524288)
    const long SS = (long)LMAX*LMAX;           // per-head score stride (1048576)

    // ---- patch embed ----
    pack_kernel<<<((size_t)NTOK*PDIM + 255)/256, 256>>>(images, tok);
    ln_kernel<<<NTOK, 256>>>(tok, pe_ln1_w, pe_ln1_b, lt, PDIM);
    launch_nt(lt, PDIM, 0,0, pe_w, PDIM, 0,0, pe_b, nullptr,0, t, DIM, 0,0,
              NTOK, DIM, PDIM, 1.f, 0, 1, 1);
    ln_kernel<<<NTOK, 256>>>(t, pe_ln2_w, pe_ln2_b, t, DIM);
    posmask_kernel<<<NTOK, DIM>>>(t, pos_h, pos_w);

    // ---- transformer layers ----
    for (int l = 0; l < NDEPTH; l++){
        const float* wql = wq + (size_t)l*DIM*DIM;
        const float* wkl = wk + (size_t)l*DIM*DIM;
        const float* wvl = wv + (size_t)l*DIM*DIM;
        const float* wol = wo + (size_t)l*DIM*DIM;

        ln_kernel<<<NTOK, 256>>>(t, attn_ln + l*DIM, nullptr, xn, DIM);
        launch_nt(xn, DIM, 0,0, wql, DIM, 0,0, nullptr, nullptr,0, q, DIM, 0,0, NTOK, DIM, DIM, 1.f, 0, 1, 1);
        launch_nt(xn, DIM, 0,0, wkl, DIM, 0,0, nullptr, nullptr,0, k, DIM, 0,0, NTOK, DIM, DIM, 1.f, 0, 1, 1);
        launch_nt(xn, DIM, 0,0, wvl, DIM, 0,0, nullptr, nullptr,0, v, DIM, 0,0, NTOK, DIM, DIM, 1.f, 0, 1, 1);
        head_ln_kernel<<<(NTOK*HEADS*32 + 255)/256, 256>>>(q, qn + l*DH, NTOK*HEADS);
        head_ln_kernel<<<(NTOK*HEADS*32 + 255)/256, 256>>>(k, kn + l*DH, NTOK*HEADS);
        // scores: per (b,h)  S = (Q K^T)/8
        launch_nt(q, DIM, QS, DH, k, DIM, QS, DH, nullptr, nullptr,0,
                  s, LMAX, (long)HEADS*SS, SS, LMAX, LMAX, DH, 0.125f, 0, BB*HEADS, HEADS);
        softmax_kernel<<<BB*HEADS*LMAX, 256>>>(s);
        // O = A V
        launch_nn(s, LMAX, (long)HEADS*SS, SS, v, DIM, QS, DH,
                  o, DIM, QS, DH, LMAX, DH, LMAX, BB*HEADS, HEADS);
        // t += O wo^T
        launch_nt(o, DIM, 0,0, wol, DIM, 0,0, nullptr, t, DIM, t, DIM, 0,0,
                  NTOK, DIM, DIM, 1.f, 0, 1, 1);
        // MLP
        ln_kernel<<<NTOK, 256>>>(t, ff_ln + l*DIM, nullptr, xn, DIM);
        launch_nt(xn, DIM, 0,0, ff_w1 + (size_t)l*MLPD*DIM, DIM, 0,0, ff_b1 + l*MLPD,
                  nullptr,0, mlp, MLPD, 0,0, NTOK, MLPD, DIM, 1.f, 1, 1, 1);
        launch_nt(mlp, MLPD, 0,0, ff_w2 + (size_t)l*DIM*MLPD, MLPD, 0,0, ff_b2 + l*DIM,
                  t, DIM, t, DIM, 0,0, NTOK, DIM, MLPD, 1.f, 0, 1, 1);
    }

    // ---- final LN + pooling ----
    ln_kernel<<<NTOK, 256>>>(t, final_ln, nullptr, xn, DIM);
    ln_kernel<<<1, 256>>>(pool_q, pool_ln, nullptr, u, DIM);
    launch_nt(u, DIM, 0,0, pool_wq, DIM, 0,0, nullptr, nullptr,0, qp, DIM, 0,0, 1, DIM, DIM, 1.f, 0, 1, 1);
    head_ln_kernel<<<1, 256>>>(qp, pool_qn, HEADS);
    launch_nt(xn, DIM, 0,0, pool_wk, DIM, 0,0, nullptr, nullptr,0, k, DIM, 0,0, NTOK, DIM, DIM, 1.f, 0, 1, 1);
    head_ln_kernel<<<(NTOK*HEADS*32 + 255)/256, 256>>>(k, pool_kn, NTOK*HEADS);
    launch_nt(xn, DIM, 0,0, pool_wv, DIM, 0,0, nullptr, nullptr,0, v, DIM, 0,0, NTOK, DIM, DIM, 1.f, 0, 1, 1);
    pool_attn_kernel<<<dim3(HEADS, BB), 256>>>(qp, k, v, po);
    launch_nt(po, DIM, 0,0, pool_wo, DIM, 0,0, nullptr, nullptr,0, pooled, DIM, 0,0, BB, DIM, DIM, 1.f, 0, 1, 1);
    ln_kernel<<<BB, 256>>>(pooled, head_ln, nullptr, hn, DIM);
    launch_nt(hn, DIM, 0,0, head_w, DIM, 0,0, nullptr, nullptr,0, out, NC, 0,0, BB, NC, DIM, 1.f, 0, 1, 1);
}

// round 3
// speedup vs baseline: 3.0707x; 3.0707x over previous
#include <cuda_runtime.h>
#include <cuda_bf16.h>
#include <math.h>
#include <stdint.h>

#define BB 8
#define LMAX 1024
#define DIM 512
#define HEADS 8
#define DH 64
#define NDEPTH 6
#define MLPD 2048
#define NC 1000
#define PDIM 768
#define NTOK (BB*LMAX)   // 8192

__constant__ int c_L[8]  = {1024, 768, 896, 576, 560, 512, 384, 640};
__constant__ int c_Wp[8] = {  32,  24,  32,  24,  28,  32,  16,  20};

// ---------------- scratch ----------------
__device__ float g_tok[(size_t)NTOK*PDIM];
__device__ float g_lt [(size_t)NTOK*PDIM];
__device__ float g_t  [(size_t)NTOK*DIM];
__device__ float g_xn [(size_t)NTOK*DIM];
__device__ float g_q  [(size_t)NTOK*DIM];
__device__ float g_k  [(size_t)NTOK*DIM];
__device__ float g_v  [(size_t)NTOK*DIM];
__device__ float g_o  [(size_t)NTOK*DIM];
__device__ float g_mlp[(size_t)NTOK*MLPD];
__device__ float g_s  [(size_t)BB*HEADS*LMAX*LMAX];
__device__ float g_vt [(size_t)BB*HEADS*DH*LMAX];
__device__ float g_u  [DIM];
__device__ float g_qp [DIM];
__device__ float g_po [BB*DIM];
__device__ float g_pooled[BB*DIM];
__device__ float g_hn [BB*DIM];

// ================= helpers =================
__device__ __forceinline__ uint32_t smem_u32(const void* p){
    uint32_t a; asm("{ .reg .u64 t; cvta.to.shared.u64 t, %1; cvt.u32.u64 %0, t; }" : "=r"(a) : "l"(p));
    return a;
}
__device__ __forceinline__ void ldsm_x4(uint32_t* r, uint32_t addr){
    asm volatile("ldmatrix.sync.aligned.m8n8.x4.shared.b16 {%0,%1,%2,%3}, [%4];"
        : "=r"(r[0]),"=r"(r[1]),"=r"(r[2]),"=r"(r[3]) : "r"(addr));
}
__device__ __forceinline__ void ldsm_x2(uint32_t* r, uint32_t addr){
    asm volatile("ldmatrix.sync.aligned.m8n8.x2.shared.b16 {%0,%1}, [%2];"
        : "=r"(r[0]),"=r"(r[1]) : "r"(addr));
}
__device__ __forceinline__ void mma16816(float* c, const uint32_t* a, const uint32_t* b){
    asm volatile("mma.sync.aligned.m16n8k16.row.col.f32.bf16.bf16.f32 "
        "{%0,%1,%2,%3}, {%4,%5,%6,%7}, {%8,%9}, {%0,%1,%2,%3};"
        : "+f"(c[0]),"+f"(c[1]),"+f"(c[2]),"+f"(c[3])
        : "r"(a[0]),"r"(a[1]),"r"(a[2]),"r"(a[3]), "r"(b[0]),"r"(b[1]));
}
__device__ __forceinline__ uint32_t bf2u(__nv_bfloat162 v){ return *reinterpret_cast<uint32_t*>(&v); }

__device__ __forceinline__ void cvt8(float4 a, float4 b, uint4& hi, uint4& lo){
    __nv_bfloat162 h0 = __float22bfloat162_rn(make_float2(a.x, a.y));
    __nv_bfloat162 h1 = __float22bfloat162_rn(make_float2(a.z, a.w));
    __nv_bfloat162 h2 = __float22bfloat162_rn(make_float2(b.x, b.y));
    __nv_bfloat162 h3 = __float22bfloat162_rn(make_float2(b.z, b.w));
    float2 f0 = __bfloat1622float2(h0), f1 = __bfloat1622float2(h1);
    float2 f2 = __bfloat1622float2(h2), f3 = __bfloat1622float2(h3);
    __nv_bfloat162 l0 = __float22bfloat162_rn(make_float2(a.x - f0.x, a.y - f0.y));
    __nv_bfloat162 l1 = __float22bfloat162_rn(make_float2(a.z - f1.x, a.w - f1.y));
    __nv_bfloat162 l2 = __float22bfloat162_rn(make_float2(b.x - f2.x, b.y - f2.y));
    __nv_bfloat162 l3 = __float22bfloat162_rn(make_float2(b.z - f3.x, b.w - f3.y));
    hi = make_uint4(bf2u(h0), bf2u(h1), bf2u(h2), bf2u(h3));
    lo = make_uint4(bf2u(l0), bf2u(l1), bf2u(l2), bf2u(l3));
}

// ============== HMMA GEMM NT: C = alpha*(A @ W^T) [+bias][gelu][+R] ==============
// A[M,K] f32 (lda), W[N,K] f32 (ldw). M multiple of 128, K multiple of 64, N even.
// bf16-split: C = Ah*Wh + Ah*Wl + Al*Wh with f32 accumulate.
// batched via blockIdx.z: off = (z/zdiv)*hi + (z%zdiv)*lo.
#define PITCH 72                       // bf16 elements per SMEM row
#define TILEB (128*PITCH*2)            // 18432 bytes per tile
#define AH_OFF 0
#define AL_OFF (AH_OFF + TILEB)
#define WH_OFF (AL_OFF + TILEB)
#define WL_OFF (WH_OFF + TILEB)
#define SMEM_TOT (WL_OFF + TILEB)      // 73728

__global__ __launch_bounds__(256) void hgemm_nt(
    const float* __restrict__ A, int lda, long hiA, long loA,
    const float* __restrict__ W, int ldw, long hiW, long loW,
    const float* __restrict__ bias,
    const float* __restrict__ R, int ldr, long hiR, long loR,
    float* __restrict__ C, int ldc, long hiC, long loC,
    int N, int K, float alpha, int act, int zdiv)
{
    extern __shared__ char smem[];
    uint32_t sb = smem_u32(smem);
    int tid = threadIdx.x, lane = tid & 31, wid = tid >> 5;
    int z = blockIdx.z, zh = z / zdiv, zl = z % zdiv;
    A += (size_t)zh*hiA + (size_t)zl*loA;
    W += (size_t)zh*hiW + (size_t)zl*loW;
    C += (size_t)zh*hiC + (size_t)zl*loC;
    if (R) R += (size_t)zh*hiR + (size_t)zl*loR;
    int bm = blockIdx.y*128, bn = blockIdx.x*128;
    int wr = (wid & 1)*64;      // warp row base (64 rows)
    int wn = (wid >> 1)*32;     // warp col base (32 cols)

    float acc[4][4][4];
    #pragma unroll
    for (int i = 0; i < 4; i++)
        #pragma unroll
        for (int j = 0; j < 4; j++)
            #pragma unroll
            for (int p = 0; p < 4; p++) acc[i][j][p] = 0.f;

    int nk = K >> 6;
    for (int kc = 0; kc < nk; kc++){
        // ---- stage A and W (64-col chunk) as hi/lo bf16, swizzle-free pitched rows ----
        #pragma unroll
        for (int it = 0; it < 4; it++){
            int slot = it*256 + tid;          // 0..1023
            int row = slot >> 3, seg = slot & 7;
            uint32_t off = (uint32_t)(row*(PITCH*2) + seg*16);
            uint4 hi, lo;
            {   // A tile (M always covered)
                const float* ap = A + (size_t)(bm + row)*lda + kc*64 + seg*8;
                float4 x = *(const float4*)ap;
                float4 y = *(const float4*)(ap + 4);
                cvt8(x, y, hi, lo);
                *(uint4*)(smem + AH_OFF + off) = hi;
                *(uint4*)(smem + AL_OFF + off) = lo;
            }
            {   // W tile (zero-pad rows >= N)
                int gn = bn + row;
                float4 x = make_float4(0,0,0,0), y = make_float4(0,0,0,0);
                if (gn < N){
                    const float* wp = W + (size_t)gn*ldw + kc*64 + seg*8;
                    x = *(const float4*)wp;
                    y = *(const float4*)(wp + 4);
                }
                cvt8(x, y, hi, lo);
                *(uint4*)(smem + WH_OFF + off) = hi;
                *(uint4*)(smem + WL_OFF + off) = lo;
            }
        }
        __syncthreads();

        #pragma unroll
        for (int ks = 0; ks < 4; ks++){
            uint32_t a_hi[4][4], a_lo[4][4];
            int grp = lane >> 3, wi = lane & 7;
            #pragma unroll
            for (int mi = 0; mi < 4; mi++){
                uint32_t off = (uint32_t)((wr + mi*16 + wi + (grp & 1)*8)*(PITCH*2)
                                          + (ks*16 + (grp >> 1)*8)*2);
                ldsm_x4(a_hi[mi], sb + AH_OFF + off);
                ldsm_x4(a_lo[mi], sb + AL_OFF + off);
            }
            uint32_t b_hi[4][2], b_lo[4][2];
            #pragma unroll
            for (int ni = 0; ni < 4; ni++){
                uint32_t off = (uint32_t)((wn + ni*8 + (lane & 7))*(PITCH*2)
                                          + (ks*16 + ((lane >> 3) & 1)*8)*2);
                ldsm_x2(b_hi[ni], sb + WH_OFF + off);
                ldsm_x2(b_lo[ni], sb + WL_OFF + off);
            }
            #pragma unroll
            for (int mi = 0; mi < 4; mi++)
                #pragma unroll
                for (int ni = 0; ni < 4; ni++){
                    mma16816(acc[mi][ni], a_hi[mi], b_hi[ni]);
                    mma16816(acc[mi][ni], a_hi[mi], b_lo[ni]);
                    mma16816(acc[mi][ni], a_lo[mi], b_hi[ni]);
                }
        }
        __syncthreads();
    }

    // ---- epilogue ----
    #pragma unroll
    for (int mi = 0; mi < 4; mi++){
        #pragma unroll
        for (int ni = 0; ni < 4; ni++){
            int n0 = bn + wn + ni*8 + (lane & 3)*2;
            if (n0 >= N) continue;
            #pragma unroll
            for (int hh = 0; hh < 2; hh++){
                int m = bm + wr + mi*16 + (lane >> 2) + hh*8;
                float v0 = acc[mi][ni][hh*2 + 0]*alpha;
                float v1 = acc[mi][ni][hh*2 + 1]*alpha;
                if (bias){ v0 += bias[n0]; v1 += bias[n0 + 1]; }
                if (act){
                    v0 = 0.5f*v0*(1.f + erff(v0*0.70710678118654752f));
                    v1 = 0.5f*v1*(1.f + erff(v1*0.70710678118654752f));
                }
                if (R){
                    const float* rp = R + (size_t)m*ldr + n0;
                    v0 += rp[0]; v1 += rp[1];
                }
                *(float2*)(C + (size_t)m*ldc + n0) = make_float2(v0, v1);
            }
        }
    }
}

// ---------------- patch packing ----------------
__global__ void pack_kernel(const float* __restrict__ img, float* __restrict__ tok){
    size_t i = (size_t)blockIdx.x*blockDim.x + threadIdx.x;
    if (i >= (size_t)NTOK*PDIM) return;
    int pd = (int)(i % PDIM);
    size_t bl = i / PDIM;
    int l = (int)(bl % LMAX);
    int b = (int)(bl / LMAX);
    int L = c_L[b], w = c_Wp[b];
    float v = 0.f;
    if (l < L){
        int c  = pd >> 8;
        int r  = pd & 255;
        int py = r >> 4, px = r & 15;
        int ph = l / w, pw = l % w;
        v = img[((size_t)(b*3 + c)*512 + (size_t)(ph*16 + py))*512 + (size_t)(pw*16 + px)];
    }
    tok[i] = v;
}

// ---------------- row LayerNorm (D <= 768), blockDim 256 ----------------
__global__ void ln_kernel(const float* __restrict__ x, const float* __restrict__ w,
                          const float* __restrict__ bb, float* __restrict__ y, int D){
    __shared__ float red[8];
    int row = blockIdx.x, tid = threadIdx.x, lane = tid & 31, wp = tid >> 5;
    const float* xr = x + (size_t)row*D;
    float lv[3]; float s = 0.f;
    #pragma unroll
    for (int i = 0; i < 3; i++){
        int idx = tid + i*256;
        float vv = (idx < D) ? xr[idx] : 0.f;
        lv[i] = vv; s += vv;
    }
    #pragma unroll
    for (int off = 16; off; off >>= 1) s += __shfl_xor_sync(0xffffffffu, s, off);
    if (lane == 0) red[wp] = s;
    __syncthreads();
    float tot = 0.f;
    #pragma unroll
    for (int i = 0; i < 8; i++) tot += red[i];
    float mu = tot / (float)D;
    __syncthreads();
    float vs = 0.f;
    #pragma unroll
    for (int i = 0; i < 3; i++){
        int idx = tid + i*256;
        if (idx < D){ float d = lv[i] - mu; vs += d*d; }
    }
    #pragma unroll
    for (int off = 16; off; off >>= 1) vs += __shfl_xor_sync(0xffffffffu, vs, off);
    if (lane == 0) red[wp] = vs;
    __syncthreads();
    float tv = 0.f;
    #pragma unroll
    for (int i = 0; i < 8; i++) tv += red[i];
    float rs = rsqrtf(tv / (float)D + 1e-5f);
    float* yr = y + (size_t)row*D;
    #pragma unroll
    for (int i = 0; i < 3; i++){
        int idx = tid + i*256;
        if (idx < D){
            float val = (lv[i] - mu)*rs*w[idx];
            if (bb) val += bb[idx];
            yr[idx] = val;
        }
    }
}

// ---------------- per-head LayerNorm over 64 dims ----------------
__global__ void head_ln_kernel(float* __restrict__ x, const float* __restrict__ w, int rows){
    int gw = (int)(((size_t)blockIdx.x*blockDim.x + threadIdx.x) >> 5);
    int lane = threadIdx.x & 31;
    if (gw >= rows) return;
    float* p = x + (size_t)gw*64;
    float a = p[lane], b = p[lane + 32];
    float s = a + b;
    #pragma unroll
    for (int off = 16; off; off >>= 1) s += __shfl_xor_sync(0xffffffffu, s, off);
    float mu = s * (1.f/64.f);
    float da = a - mu, db = b - mu;
    float vs = da*da + db*db;
    #pragma unroll
    for (int off = 16; off; off >>= 1) vs += __shfl_xor_sync(0xffffffffu, vs, off);
    float rs = rsqrtf(vs * (1.f/64.f) + 1e-5f);
    p[lane]      = da * rs * w[lane];
    p[lane + 32] = db * rs * w[lane + 32];
}

// ---------------- pos embed + mask ----------------
__global__ void posmask_kernel(float* __restrict__ t, const float* __restrict__ ph,
                               const float* __restrict__ pw){
    int bl = blockIdx.x;
    int b = bl >> 10, l = bl & 1023;
    int L = c_L[b], w = c_Wp[b];
    float* r = t + (size_t)bl*DIM;
    int d = threadIdx.x;
    if (l < L) r[d] = r[d] + ph[(size_t)(l / w)*DIM + d] + pw[(size_t)(l % w)*DIM + d];
    else       r[d] = 0.f;
}

// ---------------- masked softmax over 1024 keys ----------------
__global__ void softmax_kernel(float* __restrict__ S){
    __shared__ float red[8], red2[8];
    int row = blockIdx.x;
    int b = row >> 13;
    int L = c_L[b];
    float* s = S + (size_t)row*1024;
    int tid = threadIdx.x, lane = tid & 31, wp = tid >> 5;
    float4 v4 = ((const float4*)s)[tid];
    float vl[4] = {v4.x, v4.y, v4.z, v4.w};
    int k0 = tid*4;
    #pragma unroll
    for (int j = 0; j < 4; j++) if (k0 + j >= L) vl[j] = -1e9f;
    float m = fmaxf(fmaxf(vl[0], vl[1]), fmaxf(vl[2], vl[3]));
    #pragma unroll
    for (int off = 16; off; off >>= 1) m = fmaxf(m, __shfl_xor_sync(0xffffffffu, m, off));
    if (lane == 0) red[wp] = m;
    __syncthreads();
    float bm = -1e30f;
    #pragma unroll
    for (int i = 0; i < 8; i++) bm = fmaxf(bm, red[i]);
    float sum = 0.f;
    #pragma unroll
    for (int j = 0; j < 4; j++){ vl[j] = __expf(vl[j] - bm); sum += vl[j]; }
    #pragma unroll
    for (int off = 16; off; off >>= 1) sum += __shfl_xor_sync(0xffffffffu, sum, off);
    if (lane == 0) red2[wp] = sum;
    __syncthreads();
    float bs = 0.f;
    #pragma unroll
    for (int i = 0; i < 8; i++) bs += red2[i];
    float inv = 1.f / bs;
    ((float4*)s)[tid] = make_float4(vl[0]*inv, vl[1]*inv, vl[2]*inv, vl[3]*inv);
}

// ---------------- V transpose: vt[z][d][k] = v[b*1024+k][h*64+d], z=b*8+h ----------------
__global__ void transpose_v_kernel(const float* __restrict__ v, float* __restrict__ vt){
    __shared__ float tile[32][33];
    int z = blockIdx.z, b = z >> 3, h = z & 7;
    const float* vs = v + (size_t)b*LMAX*DIM + h*64;
    float* vd = vt + (size_t)z*DH*LMAX;
    int k0 = blockIdx.x*32, d0 = blockIdx.y*32;
    int tx = threadIdx.x, ty = threadIdx.y;
    #pragma unroll
    for (int i = 0; i < 32; i += 8)
        tile[ty + i][tx] = vs[(size_t)(k0 + ty + i)*DIM + d0 + tx];
    __syncthreads();
    #pragma unroll
    for (int i = 0; i < 32; i += 8)
        vd[(size_t)(d0 + ty + i)*LMAX + k0 + tx] = tile[tx][ty + i];
}

// ---------------- f32 SIMT GEMM NT (small M only) ----------------
__global__ __launch_bounds__(256) void gemm_nt_kernel(
    const float* __restrict__ A, int lda,
    const float* __restrict__ W, int ldw,
    const float* __restrict__ bias,
    float* __restrict__ C, int ldc,
    int M, int N, int K)
{
    __shared__ __align__(16) float As[8][128];
    __shared__ __align__(16) float Bs[8][128];
    int bm = blockIdx.y*128, bn = blockIdx.x*128;
    int tid = threadIdx.x;
    int tx = tid & 15, ty = tid >> 4;
    float acc[8][8];
    #pragma unroll
    for (int i = 0; i < 8; i++)
        #pragma unroll
        for (int j = 0; j < 8; j++) acc[i][j] = 0.f;
    int lr = tid >> 1;
    int lk = (tid & 1)*4;
    for (int k0 = 0; k0 < K; k0 += 8){
        float4 av = make_float4(0,0,0,0), bv = make_float4(0,0,0,0);
        if (bm + lr < M) av = *(const float4*)(A + (size_t)(bm + lr)*lda + k0 + lk);
        if (bn + lr < N) bv = *(const float4*)(W + (size_t)(bn + lr)*ldw + k0 + lk);
        As[lk+0][lr] = av.x; As[lk+1][lr] = av.y; As[lk+2][lr] = av.z; As[lk+3][lr] = av.w;
        Bs[lk+0][lr] = bv.x; Bs[lk+1][lr] = bv.y; Bs[lk+2][lr] = bv.z; Bs[lk+3][lr] = bv.w;
        __syncthreads();
        #pragma unroll
        for (int kk = 0; kk < 8; kk++){
            float a[8], b[8];
            #pragma unroll
            for (int i = 0; i < 8; i++) a[i] = As[kk][ty*8 + i];
            #pragma unroll
            for (int j = 0; j < 8; j++) b[j] = Bs[kk][tx*8 + j];
            #pragma unroll
            for (int i = 0; i < 8; i++)
                #pragma unroll
                for (int j = 0; j < 8; j++) acc[i][j] = fmaf(a[i], b[j], acc[i][j]);
        }
        __syncthreads();
    }
    #pragma unroll
    for (int i = 0; i < 8; i++){
        int m = bm + ty*8 + i;
        if (m >= M) continue;
        #pragma unroll
        for (int j = 0; j < 8; j++){
            int n = bn + tx*8 + j;
            if (n >= N) continue;
            float v = acc[i][j];
            if (bias) v += bias[n];
            C[(size_t)m*ldc + n] = v;
        }
    }
}

// ---------------- pooling attention (Lq=1) ----------------
__global__ void pool_attn_kernel(const float* __restrict__ qhat, const float* __restrict__ K,
                                 const float* __restrict__ V, float* __restrict__ O){
    int h = blockIdx.x, b = blockIdx.y;
    __shared__ float sq[64];
    __shared__ float sa[1024];
    __shared__ float red[8], red2[8];
    __shared__ float racc[4][64];
    int tid = threadIdx.x, lane = tid & 31, wp = tid >> 5;
    if (tid < 64) sq[tid] = qhat[h*64 + tid];
    __syncthreads();
    int L = c_L[b];
    for (int kk = tid; kk < 1024; kk += 256){
        float dot = -1e9f;
        if (kk < L){
            const float* kr = K + ((size_t)(b*1024 + kk))*DIM + h*64;
            float ss = 0.f;
            #pragma unroll
            for (int d = 0; d < 64; d++) ss += sq[d]*kr[d];
            dot = ss*0.125f;
        }
        sa[kk] = dot;
    }
    __syncthreads();
    float m = -1e30f;
    for (int kk = tid; kk < 1024; kk += 256) m = fmaxf(m, sa[kk]);
    #pragma unroll
    for (int off = 16; off; off >>= 1) m = fmaxf(m, __shfl_xor_sync(0xffffffffu, m, off));
    if (lane == 0) red[wp] = m;
    __syncthreads();
    float bm = -1e30f;
    #pragma unroll
    for (int i = 0; i < 8; i++) bm = fmaxf(bm, red[i]);
    float sum = 0.f;
    for (int kk = tid; kk < 1024; kk += 256){
        float e = __expf(sa[kk] - bm);
        sa[kk] = e; sum += e;
    }
    #pragma unroll
    for (int off = 16; off; off >>= 1) sum += __shfl_xor_sync(0xffffffffu, sum, off);
    if (lane == 0) red2[wp] = sum;
    __syncthreads();
    float bs = 0.f;
    #pragma unroll
    for (int i = 0; i < 8; i++) bs += red2[i];
    float inv = 1.f / bs;
    int dd = tid & 63, part = tid >> 6;
    float acc = 0.f;
    for (int kk = part; kk < 1024; kk += 4)
        acc += sa[kk] * V[((size_t)(b*1024 + kk))*DIM + h*64 + dd];
    racc[part][dd] = acc;
    __syncthreads();
    if (part == 0)
        O[b*DIM + h*64 + dd] = (racc[0][dd] + racc[1][dd] + racc[2][dd] + racc[3][dd]) * inv;
}

// ---------------- host helpers ----------------
static void launch_tg(const float* A, int lda, long hiA, long loA,
                      const float* W, int ldw, long hiW, long loW,
                      const float* bias,
                      const float* R, int ldr, long hiR, long loR,
                      float* C, int ldc, long hiC, long loC,
                      int M, int N, int K, float alpha, int act, int nz, int zdiv){
    dim3 g((N + 127)/128, M/128, nz);
    hgemm_nt<<<g, 256, SMEM_TOT>>>(A, lda, hiA, loA, W, ldw, hiW, loW, bias,
                                   R, ldr, hiR, loR, C, ldc, hiC, loC, N, K, alpha, act, zdiv);
}
static void launch_small(const float* A, int lda, const float* W, int ldw,
                         const float* bias, float* C, int ldc, int M, int N, int K){
    dim3 g((N + 127)/128, (M + 127)/128, 1);
    gemm_nt_kernel<<<g, 256>>>(A, lda, W, ldw, bias, C, ldc, M, N, K);
}

extern "C" void kernel_launch(void* const* d_in, const int* in_sizes, int n_in,
                              void* d_out, int out_size){
    const float* images   = (const float*)d_in[0];
    const float* pe_ln1_w = (const float*)d_in[1];
    const float* pe_ln1_b = (const float*)d_in[2];
    const float* pe_w     = (const float*)d_in[3];
    const float* pe_b     = (const float*)d_in[4];
    const float* pe_ln2_w = (const float*)d_in[5];
    const float* pe_ln2_b = (const float*)d_in[6];
    const float* pos_h    = (const float*)d_in[7];
    const float* pos_w    = (const float*)d_in[8];
    const float* attn_ln  = (const float*)d_in[9];
    const float* wq       = (const float*)d_in[10];
    const float* wk       = (const float*)d_in[11];
    const float* wv       = (const float*)d_in[12];
    const float* qn       = (const float*)d_in[13];
    const float* kn       = (const float*)d_in[14];
    const float* wo       = (const float*)d_in[15];
    const float* ff_ln    = (const float*)d_in[16];
    const float* ff_w1    = (const float*)d_in[17];
    const float* ff_b1    = (const float*)d_in[18];
    const float* ff_w2    = (const float*)d_in[19];
    const float* ff_b2    = (const float*)d_in[20];
    const float* final_ln = (const float*)d_in[21];
    const float* pool_q   = (const float*)d_in[22];
    const float* pool_ln  = (const float*)d_in[23];
    const float* pool_wq  = (const float*)d_in[24];
    const float* pool_wk  = (const float*)d_in[25];
    const float* pool_wv  = (const float*)d_in[26];
    const float* pool_qn  = (const float*)d_in[27];
    const float* pool_kn  = (const float*)d_in[28];
    const float* pool_wo  = (const float*)d_in[29];
    const float* head_ln  = (const float*)d_in[30];
    const float* head_w   = (const float*)d_in[31];
    float* out = (float*)d_out;

    cudaFuncSetAttribute(hgemm_nt, cudaFuncAttributeMaxDynamicSharedMemorySize, SMEM_TOT);

    float *tok,*lt,*t,*xn,*q,*k,*v,*o,*mlp,*s,*vt,*u,*qp,*po,*pooled,*hn;
    cudaGetSymbolAddress((void**)&tok, g_tok);
    cudaGetSymbolAddress((void**)&lt,  g_lt);
    cudaGetSymbolAddress((void**)&t,   g_t);
    cudaGetSymbolAddress((void**)&xn,  g_xn);
    cudaGetSymbolAddress((void**)&q,   g_q);
    cudaGetSymbolAddress((void**)&k,   g_k);
    cudaGetSymbolAddress((void**)&v,   g_v);
    cudaGetSymbolAddress((void**)&o,   g_o);
    cudaGetSymbolAddress((void**)&mlp, g_mlp);
    cudaGetSymbolAddress((void**)&s,   g_s);
    cudaGetSymbolAddress((void**)&vt,  g_vt);
    cudaGetSymbolAddress((void**)&u,   g_u);
    cudaGetSymbolAddress((void**)&qp,  g_qp);
    cudaGetSymbolAddress((void**)&po,  g_po);
    cudaGetSymbolAddress((void**)&pooled, g_pooled);
    cudaGetSymbolAddress((void**)&hn,  g_hn);

    const long QS = (long)LMAX*DIM;
    const long SS = (long)LMAX*LMAX;
    const long VTS = (long)DH*LMAX;

    // ---- patch embed ----
    pack_kernel<<<((size_t)NTOK*PDIM + 255)/256, 256>>>(images, tok);
    ln_kernel<<<NTOK, 256>>>(tok, pe_ln1_w, pe_ln1_b, lt, PDIM);
    launch_tg(lt, PDIM, 0,0, pe_w, PDIM, 0,0, pe_b, nullptr,0,0,0,
              t, DIM, 0,0, NTOK, DIM, PDIM, 1.f, 0, 1, 1);
    ln_kernel<<<NTOK, 256>>>(t, pe_ln2_w, pe_ln2_b, t, DIM);
    posmask_kernel<<<NTOK, DIM>>>(t, pos_h, pos_w);

    // ---- transformer layers ----
    for (int l = 0; l < NDEPTH; l++){
        const float* wql = wq + (size_t)l*DIM*DIM;
        const float* wkl = wk + (size_t)l*DIM*DIM;
        const float* wvl = wv + (size_t)l*DIM*DIM;
        const float* wol = wo + (size_t)l*DIM*DIM;

        ln_kernel<<<NTOK, 256>>>(t, attn_ln + l*DIM, nullptr, xn, DIM);
        launch_tg(xn, DIM, 0,0, wql, DIM, 0,0, nullptr, nullptr,0,0,0,
                  q, DIM, 0,0, NTOK, DIM, DIM, 1.f, 0, 1, 1);
        launch_tg(xn, DIM, 0,0, wkl, DIM, 0,0, nullptr, nullptr,0,0,0,
                  k, DIM, 0,0, NTOK, DIM, DIM, 1.f, 0, 1, 1);
        launch_tg(xn, DIM, 0,0, wvl, DIM, 0,0, nullptr, nullptr,0,0,0,
                  v, DIM, 0,0, NTOK, DIM, DIM, 1.f, 0, 1, 1);
        head_ln_kernel<<<(NTOK*HEADS*32 + 255)/256, 256>>>(q, qn + l*DH, NTOK*HEADS);
        head_ln_kernel<<<(NTOK*HEADS*32 + 255)/256, 256>>>(k, kn + l*DH, NTOK*HEADS);
        // scores: per (b,h)  S = (Q K^T)/8
        launch_tg(q, DIM, QS, DH, k, DIM, QS, DH, nullptr, nullptr,0,0,0,
                  s, LMAX, (long)HEADS*SS, SS, LMAX, LMAX, DH, 0.125f, 0, BB*HEADS, HEADS);
        softmax_kernel<<<BB*HEADS*LMAX, 256>>>(s);
        // V transpose + O = A V  (as NT against V^T)
        transpose_v_kernel<<<dim3(32, 2, BB*HEADS), dim3(32, 8)>>>(v, vt);
        launch_tg(s, LMAX, (long)HEADS*SS, SS, vt, LMAX, (long)HEADS*VTS, VTS, nullptr,
                  nullptr,0,0,0, o, DIM, QS, DH, LMAX, DH, LMAX, 1.f, 0, BB*HEADS, HEADS);
        // t += O wo^T
        launch_tg(o, DIM, 0,0, wol, DIM, 0,0, nullptr, t, DIM, 0,0,
                  t, DIM, 0,0, NTOK, DIM, DIM, 1.f, 0, 1, 1);
        // MLP
        ln_kernel<<<NTOK, 256>>>(t, ff_ln + l*DIM, nullptr, xn, DIM);
        launch_tg(xn, DIM, 0,0, ff_w1 + (size_t)l*MLPD*DIM, DIM, 0,0, ff_b1 + l*MLPD,
                  nullptr,0,0,0, mlp, MLPD, 0,0, NTOK, MLPD, DIM, 1.f, 1, 1, 1);
        launch_tg(mlp, MLPD, 0,0, ff_w2 + (size_t)l*DIM*MLPD, MLPD, 0,0, ff_b2 + l*DIM,
                  t, DIM, 0,0, t, DIM, 0,0, NTOK, DIM, MLPD, 1.f, 0, 1, 1);
    }

    // ---- final LN + pooling ----
    ln_kernel<<<NTOK, 256>>>(t, final_ln, nullptr, xn, DIM);
    ln_kernel<<<1, 256>>>(pool_q, pool_ln, nullptr, u, DIM);
    launch_small(u, DIM, pool_wq, DIM, nullptr, qp, DIM, 1, DIM, DIM);
    head_ln_kernel<<<1, 256>>>(qp, pool_qn, HEADS);
    launch_tg(xn, DIM, 0,0, pool_wk, DIM, 0,0, nullptr, nullptr,0,0,0,
              k, DIM, 0,0, NTOK, DIM, DIM, 1.f, 0, 1, 1);
    head_ln_kernel<<<(NTOK*HEADS*32 + 255)/256, 256>>>(k, pool_kn, NTOK*HEADS);
    launch_tg(xn, DIM, 0,0, pool_wv, DIM, 0,0, nullptr, nullptr,0,0,0,
              v, DIM, 0,0, NTOK, DIM, DIM, 1.f, 0, 1, 1);
    pool_attn_kernel<<<dim3(HEADS, BB), 256>>>(qp, k, v, po);
    launch_small(po, DIM, pool_wo, DIM, nullptr, pooled, DIM, BB, DIM, DIM);
    ln_kernel<<<BB, 256>>>(pooled, head_ln, nullptr, hn, DIM);
    launch_small(hn, DIM, head_w, DIM, nullptr, out, NC, BB, NC, DIM);
}

// round 4
// speedup vs baseline: 3.6436x; 1.1866x over previous
#include <cuda_runtime.h>
#include <cuda_bf16.h>
#include <math.h>
#include <stdint.h>

#define BB 8
#define LMAX 1024
#define DIM 512
#define HEADS 8
#define DH 64
#define NDEPTH 6
#define MLPD 2048
#define NC 1000
#define PDIM 768
#define NTOK (BB*LMAX)   // 8192

__constant__ int c_L[8]  = {1024, 768, 896, 576, 560, 512, 384, 640};
__constant__ int c_Wp[8] = {  32,  24,  32,  24,  28,  32,  16,  20};

// ---------------- scratch ----------------
__device__ float g_tok[(size_t)NTOK*PDIM];
__device__ float g_lt [(size_t)NTOK*PDIM];
__device__ float g_t  [(size_t)NTOK*DIM];
__device__ float g_xn [(size_t)NTOK*DIM];
__device__ float g_q  [(size_t)NTOK*DIM];
__device__ float g_k  [(size_t)NTOK*DIM];
__device__ float g_v  [(size_t)NTOK*DIM];
__device__ float g_o  [(size_t)NTOK*DIM];
__device__ float g_mlp[(size_t)NTOK*MLPD];
__device__ float g_u  [DIM];
__device__ float g_qp [DIM];
__device__ float g_po [BB*DIM];
__device__ float g_pooled[BB*DIM];
__device__ float g_hn [BB*DIM];

// ================= helpers =================
__device__ __forceinline__ uint32_t smem_u32(const void* p){
    uint32_t a; asm("{ .reg .u64 t; cvta.to.shared.u64 t, %1; cvt.u32.u64 %0, t; }" : "=r"(a) : "l"(p));
    return a;
}
__device__ __forceinline__ void ldsm_x4(uint32_t* r, uint32_t addr){
    asm volatile("ldmatrix.sync.aligned.m8n8.x4.shared.b16 {%0,%1,%2,%3}, [%4];"
        : "=r"(r[0]),"=r"(r[1]),"=r"(r[2]),"=r"(r[3]) : "r"(addr));
}
__device__ __forceinline__ void ldsm_x2(uint32_t* r, uint32_t addr){
    asm volatile("ldmatrix.sync.aligned.m8n8.x2.shared.b16 {%0,%1}, [%2];"
        : "=r"(r[0]),"=r"(r[1]) : "r"(addr));
}
__device__ __forceinline__ void ldsm_x2t(uint32_t* r, uint32_t addr){
    asm volatile("ldmatrix.sync.aligned.m8n8.x2.trans.shared.b16 {%0,%1}, [%2];"
        : "=r"(r[0]),"=r"(r[1]) : "r"(addr));
}
__device__ __forceinline__ void mma16816(float* c, const uint32_t* a, const uint32_t* b){
    asm volatile("mma.sync.aligned.m16n8k16.row.col.f32.bf16.bf16.f32 "
        "{%0,%1,%2,%3}, {%4,%5,%6,%7}, {%8,%9}, {%0,%1,%2,%3};"
        : "+f"(c[0]),"+f"(c[1]),"+f"(c[2]),"+f"(c[3])
        : "r"(a[0]),"r"(a[1]),"r"(a[2]),"r"(a[3]), "r"(b[0]),"r"(b[1]));
}
__device__ __forceinline__ uint32_t bf2u(__nv_bfloat162 v){ return *reinterpret_cast<uint32_t*>(&v); }
__device__ __forceinline__ uint32_t packbf(float a, float b){
    return bf2u(__float22bfloat162_rn(make_float2(a, b)));
}
__device__ __forceinline__ void cvt8(float4 a, float4 b, uint4& hi, uint4& lo){
    __nv_bfloat162 h0 = __float22bfloat162_rn(make_float2(a.x, a.y));
    __nv_bfloat162 h1 = __float22bfloat162_rn(make_float2(a.z, a.w));
    __nv_bfloat162 h2 = __float22bfloat162_rn(make_float2(b.x, b.y));
    __nv_bfloat162 h3 = __float22bfloat162_rn(make_float2(b.z, b.w));
    float2 f0 = __bfloat1622float2(h0), f1 = __bfloat1622float2(h1);
    float2 f2 = __bfloat1622float2(h2), f3 = __bfloat1622float2(h3);
    __nv_bfloat162 l0 = __float22bfloat162_rn(make_float2(a.x - f0.x, a.y - f0.y));
    __nv_bfloat162 l1 = __float22bfloat162_rn(make_float2(a.z - f1.x, a.w - f1.y));
    __nv_bfloat162 l2 = __float22bfloat162_rn(make_float2(b.x - f2.x, b.y - f2.y));
    __nv_bfloat162 l3 = __float22bfloat162_rn(make_float2(b.z - f3.x, b.w - f3.y));
    hi = make_uint4(bf2u(h0), bf2u(h1), bf2u(h2), bf2u(h3));
    lo = make_uint4(bf2u(l0), bf2u(l1), bf2u(l2), bf2u(l3));
}

// ============== pipelined HMMA GEMM NT: C = alpha*(A @ W^T) [+bias][gelu][+R] ==============
#define PITCH 72
#define TILEB (128*PITCH*2)            // 18432
#define AH_OFF 0
#define AL_OFF (AH_OFF + TILEB)
#define WH_OFF (AL_OFF + TILEB)
#define WL_OFF (WH_OFF + TILEB)
#define BUF_B  (4*TILEB)               // 73728
#define SMEM_TOT (2*BUF_B)             // 147456

__global__ __launch_bounds__(256) void hgemm_nt(
    const float* __restrict__ A, int lda, long hiA, long loA,
    const float* __restrict__ W, int ldw, long hiW, long loW,
    const float* __restrict__ bias,
    const float* __restrict__ R, int ldr,
    float* __restrict__ C, int ldc,
    int N, int K, float alpha, int act, int tokrows)
{
    extern __shared__ char smem[];
    uint32_t sb = smem_u32(smem);
    int tid = threadIdx.x, lane = tid & 31, wid = tid >> 5;
    int bm = blockIdx.y*128, bn = blockIdx.x*128;
    if (tokrows){
        if ((bm & 1023) >= c_L[bm >> 10]) return;   // all 128 rows invalid
    }
    int wr = (wid & 1)*64;
    int wn = (wid >> 1)*32;

    float acc[4][4][4];
    #pragma unroll
    for (int i = 0; i < 4; i++)
        #pragma unroll
        for (int j = 0; j < 4; j++)
            #pragma unroll
            for (int p = 0; p < 4; p++) acc[i][j][p] = 0.f;

    float4 ra[4][2], rw[4][2];

#define LOADCHUNK(KC) do { \
    _Pragma("unroll") \
    for (int it = 0; it < 4; it++){ \
        int slot = it*256 + tid; int row = slot >> 3, seg = slot & 7; \
        const float* ap = A + (size_t)(bm + row)*lda + (KC)*64 + seg*8; \
        ra[it][0] = *(const float4*)ap; ra[it][1] = *(const float4*)(ap + 4); \
        int gn = bn + row; \
        if (gn < N){ \
            const float* wp = W + (size_t)gn*ldw + (KC)*64 + seg*8; \
            rw[it][0] = *(const float4*)wp; rw[it][1] = *(const float4*)(wp + 4); \
        } else { \
            rw[it][0] = make_float4(0,0,0,0); rw[it][1] = make_float4(0,0,0,0); \
        } \
    } } while(0)

#define STORECHUNK(BUFB) do { \
    _Pragma("unroll") \
    for (int it = 0; it < 4; it++){ \
        int slot = it*256 + tid; int row = slot >> 3, seg = slot & 7; \
        uint32_t off = (uint32_t)(row*(PITCH*2) + seg*16); \
        uint4 hi, lo; \
        cvt8(ra[it][0], ra[it][1], hi, lo); \
        *(uint4*)(smem + (BUFB) + AH_OFF + off) = hi; \
        *(uint4*)(smem + (BUFB) + AL_OFF + off) = lo; \
        cvt8(rw[it][0], rw[it][1], hi, lo); \
        *(uint4*)(smem + (BUFB) + WH_OFF + off) = hi; \
        *(uint4*)(smem + (BUFB) + WL_OFF + off) = lo; \
    } } while(0)

    int nk = K >> 6;
    LOADCHUNK(0);
    STORECHUNK(0);
    __syncthreads();

    for (int kc = 0; kc < nk; kc++){
        uint32_t cur = (uint32_t)((kc & 1)*BUF_B);
        if (kc + 1 < nk) LOADCHUNK(kc + 1);
        int grp = lane >> 3, wi = lane & 7;
        #pragma unroll
        for (int ks = 0; ks < 4; ks++){
            uint32_t a_hi[4][4], a_lo[4][4];
            #pragma unroll
            for (int mi = 0; mi < 4; mi++){
                uint32_t off = (uint32_t)((wr + mi*16 + wi + (grp & 1)*8)*(PITCH*2)
                                          + (ks*16 + (grp >> 1)*8)*2);
                ldsm_x4(a_hi[mi], sb + cur + AH_OFF + off);
                ldsm_x4(a_lo[mi], sb + cur + AL_OFF + off);
            }
            uint32_t b_hi[4][2], b_lo[4][2];
            #pragma unroll
            for (int ni = 0; ni < 4; ni++){
                uint32_t off = (uint32_t)((wn + ni*8 + (lane & 7))*(PITCH*2)
                                          + (ks*16 + ((lane >> 3) & 1)*8)*2);
                ldsm_x2(b_hi[ni], sb + cur + WH_OFF + off);
                ldsm_x2(b_lo[ni], sb + cur + WL_OFF + off);
            }
            #pragma unroll
            for (int mi = 0; mi < 4; mi++)
                #pragma unroll
                for (int ni = 0; ni < 4; ni++){
                    mma16816(acc[mi][ni], a_hi[mi], b_hi[ni]);
                    mma16816(acc[mi][ni], a_hi[mi], b_lo[ni]);
                    mma16816(acc[mi][ni], a_lo[mi], b_hi[ni]);
                }
        }
        if (kc + 1 < nk) STORECHUNK((uint32_t)(((kc + 1) & 1)*BUF_B));
        __syncthreads();
    }
#undef LOADCHUNK
#undef STORECHUNK

    // ---- epilogue ----
    #pragma unroll
    for (int mi = 0; mi < 4; mi++){
        #pragma unroll
        for (int ni = 0; ni < 4; ni++){
            int n0 = bn + wn + ni*8 + (lane & 3)*2;
            if (n0 >= N) continue;
            #pragma unroll
            for (int hh = 0; hh < 2; hh++){
                int m = bm + wr + mi*16 + (lane >> 2) + hh*8;
                float v0 = acc[mi][ni][hh*2 + 0]*alpha;
                float v1 = acc[mi][ni][hh*2 + 1]*alpha;
                if (bias){ v0 += bias[n0]; v1 += bias[n0 + 1]; }
                if (act){
                    v0 = 0.5f*v0*(1.f + erff(v0*0.70710678118654752f));
                    v1 = 0.5f*v1*(1.f + erff(v1*0.70710678118654752f));
                }
                if (R){
                    const float* rp = R + (size_t)m*ldr + n0;
                    v0 += rp[0]; v1 += rp[1];
                }
                *(float2*)(C + (size_t)m*ldc + n0) = make_float2(v0, v1);
            }
        }
    }
}

// ============== flash attention: O = softmax(QK^T/8 + mask) V, per (b,h) ==============
#define FP2 (PITCH*2)
#define FT TILEB
#define FQH 0
#define FQL (1*FT)
#define FKH (2*FT)
#define FKL (3*FT)
#define FVH (4*FT)
#define FVL (5*FT)
#define FSMEM (6*FT)    // 110592

__global__ __launch_bounds__(256) void flash_kernel(
    const float* __restrict__ Q, const float* __restrict__ K,
    const float* __restrict__ V, float* __restrict__ O)
{
    extern __shared__ char smem[];
    uint32_t sb = smem_u32(smem);
    int tid = threadIdx.x, lane = tid & 31, wid = tid >> 5;
    int qt = blockIdx.x;
    int bh = blockIdx.y;
    int b = bh >> 3, h = bh & 7;
    int L = c_L[b];
    if (qt*128 >= L) return;
    int ktiles = (L + 127) >> 7;

    // ---- stage Q (scaled 1/8), hi/lo ----
    #pragma unroll
    for (int it = 0; it < 4; it++){
        int slot = it*256 + tid; int row = slot >> 3, seg = slot & 7;
        const float* qp = Q + (size_t)(b*1024 + qt*128 + row)*DIM + h*64 + seg*8;
        float4 x = *(const float4*)qp;
        float4 y = *(const float4*)(qp + 4);
        x.x *= 0.125f; x.y *= 0.125f; x.z *= 0.125f; x.w *= 0.125f;
        y.x *= 0.125f; y.y *= 0.125f; y.z *= 0.125f; y.w *= 0.125f;
        uint4 hi, lo; cvt8(x, y, hi, lo);
        uint32_t off = (uint32_t)(row*FP2 + seg*16);
        *(uint4*)(smem + FQH + off) = hi;
        *(uint4*)(smem + FQL + off) = lo;
    }
    __syncthreads();

    int wr = wid*16;
    int grp = lane >> 3, wi = lane & 7;
    uint32_t aqh[4][4], aql[4][4];
    #pragma unroll
    for (int ks = 0; ks < 4; ks++){
        uint32_t off = (uint32_t)((wr + wi + (grp & 1)*8)*FP2 + (ks*16 + (grp >> 1)*8)*2);
        ldsm_x4(aqh[ks], sb + FQH + off);
        ldsm_x4(aql[ks], sb + FQL + off);
    }

    float m0 = -1e30f, m1 = -1e30f, l0 = 0.f, l1 = 0.f;
    float ao[8][4];
    #pragma unroll
    for (int i = 0; i < 8; i++)
        #pragma unroll
        for (int p = 0; p < 4; p++) ao[i][p] = 0.f;

    for (int kt = 0; kt < ktiles; kt++){
        __syncthreads();   // prior PV reads done before restaging K/V
        #pragma unroll
        for (int it = 0; it < 4; it++){
            int slot = it*256 + tid; int row = slot >> 3, seg = slot & 7;
            uint32_t off = (uint32_t)(row*FP2 + seg*16);
            uint4 hi, lo;
            const float* kp = K + (size_t)(b*1024 + kt*128 + row)*DIM + h*64 + seg*8;
            cvt8(*(const float4*)kp, *(const float4*)(kp + 4), hi, lo);
            *(uint4*)(smem + FKH + off) = hi;
            *(uint4*)(smem + FKL + off) = lo;
            const float* vp = V + (size_t)(b*1024 + kt*128 + row)*DIM + h*64 + seg*8;
            cvt8(*(const float4*)vp, *(const float4*)(vp + 4), hi, lo);
            *(uint4*)(smem + FVH + off) = hi;
            *(uint4*)(smem + FVL + off) = lo;
        }
        __syncthreads();

        // ---- S = Q K^T (warp: 16 rows x 128 cols) ----
        float s[16][4];
        #pragma unroll
        for (int i = 0; i < 16; i++)
            #pragma unroll
            for (int p = 0; p < 4; p++) s[i][p] = 0.f;
        #pragma unroll
        for (int ks = 0; ks < 4; ks++){
            #pragma unroll
            for (int ni = 0; ni < 16; ni++){
                uint32_t off = (uint32_t)((ni*8 + wi)*FP2 + (ks*16 + (grp & 1)*8)*2);
                uint32_t bh_[2], bl_[2];
                ldsm_x2(bh_, sb + FKH + off);
                ldsm_x2(bl_, sb + FKL + off);
                mma16816(s[ni], aqh[ks], bh_);
                mma16816(s[ni], aqh[ks], bl_);
                mma16816(s[ni], aql[ks], bh_);
            }
        }

        // ---- mask (partial tile only) ----
        if (kt == ktiles - 1 && (L & 127)){
            int kb = kt*128 + 2*(lane & 3);
            #pragma unroll
            for (int ni = 0; ni < 16; ni++){
                int kg = kb + ni*8;
                if (kg     >= L){ s[ni][0] = -1e9f; s[ni][2] = -1e9f; }
                if (kg + 1 >= L){ s[ni][1] = -1e9f; s[ni][3] = -1e9f; }
            }
        }

        // ---- online softmax stats ----
        float tm0 = -1e30f, tm1 = -1e30f;
        #pragma unroll
        for (int ni = 0; ni < 16; ni++){
            tm0 = fmaxf(tm0, fmaxf(s[ni][0], s[ni][1]));
            tm1 = fmaxf(tm1, fmaxf(s[ni][2], s[ni][3]));
        }
        tm0 = fmaxf(tm0, __shfl_xor_sync(0xffffffffu, tm0, 1));
        tm0 = fmaxf(tm0, __shfl_xor_sync(0xffffffffu, tm0, 2));
        tm1 = fmaxf(tm1, __shfl_xor_sync(0xffffffffu, tm1, 1));
        tm1 = fmaxf(tm1, __shfl_xor_sync(0xffffffffu, tm1, 2));
        float mn0 = fmaxf(m0, tm0), mn1 = fmaxf(m1, tm1);
        float sc0 = __expf(m0 - mn0), sc1 = __expf(m1 - mn1);
        m0 = mn0; m1 = mn1;
        float ts0 = 0.f, ts1 = 0.f;
        #pragma unroll
        for (int ni = 0; ni < 16; ni++){
            s[ni][0] = __expf(s[ni][0] - m0);
            s[ni][1] = __expf(s[ni][1] - m0);
            s[ni][2] = __expf(s[ni][2] - m1);
            s[ni][3] = __expf(s[ni][3] - m1);
            ts0 += s[ni][0] + s[ni][1];
            ts1 += s[ni][2] + s[ni][3];
        }
        ts0 += __shfl_xor_sync(0xffffffffu, ts0, 1);
        ts0 += __shfl_xor_sync(0xffffffffu, ts0, 2);
        ts1 += __shfl_xor_sync(0xffffffffu, ts1, 1);
        ts1 += __shfl_xor_sync(0xffffffffu, ts1, 2);
        l0 = l0*sc0 + ts0;
        l1 = l1*sc1 + ts1;
        #pragma unroll
        for (int i = 0; i < 8; i++){
            ao[i][0] *= sc0; ao[i][1] *= sc0;
            ao[i][2] *= sc1; ao[i][3] *= sc1;
        }

        // ---- O += P V ----
        #pragma unroll
        for (int kk = 0; kk < 8; kk++){
            float p00 = s[2*kk][0],   p01 = s[2*kk][1],   p02 = s[2*kk][2],   p03 = s[2*kk][3];
            float p10 = s[2*kk+1][0], p11 = s[2*kk+1][1], p12 = s[2*kk+1][2], p13 = s[2*kk+1][3];
            uint32_t aph[4], apl[4];
            aph[0] = packbf(p00, p01); aph[1] = packbf(p02, p03);
            aph[2] = packbf(p10, p11); aph[3] = packbf(p12, p13);
            {
                float2 f0 = __bfloat1622float2(*reinterpret_cast<__nv_bfloat162*>(&aph[0]));
                float2 f1 = __bfloat1622float2(*reinterpret_cast<__nv_bfloat162*>(&aph[1]));
                float2 f2 = __bfloat1622float2(*reinterpret_cast<__nv_bfloat162*>(&aph[2]));
                float2 f3 = __bfloat1622float2(*reinterpret_cast<__nv_bfloat162*>(&aph[3]));
                apl[0] = packbf(p00 - f0.x, p01 - f0.y);
                apl[1] = packbf(p02 - f1.x, p03 - f1.y);
                apl[2] = packbf(p10 - f2.x, p11 - f2.y);
                apl[3] = packbf(p12 - f3.x, p13 - f3.y);
            }
            #pragma unroll
            for (int ni = 0; ni < 8; ni++){
                uint32_t off = (uint32_t)((kk*16 + (lane & 15))*FP2 + ni*16);
                uint32_t vh_[2], vl_[2];
                ldsm_x2t(vh_, sb + FVH + off);
                ldsm_x2t(vl_, sb + FVL + off);
                mma16816(ao[ni], aph, vh_);
                mma16816(ao[ni], apl, vh_);
                mma16816(ao[ni], aph, vl_);
            }
        }
    }

    // ---- epilogue ----
    float il0 = 1.f / l0, il1 = 1.f / l1;
    int mrow = qt*128 + wr + (lane >> 2);
    #pragma unroll
    for (int ni = 0; ni < 8; ni++){
        int col = h*64 + ni*8 + 2*(lane & 3);
        *(float2*)(O + (size_t)(b*1024 + mrow)*DIM + col)
            = make_float2(ao[ni][0]*il0, ao[ni][1]*il0);
        *(float2*)(O + (size_t)(b*1024 + mrow + 8)*DIM + col)
            = make_float2(ao[ni][2]*il1, ao[ni][3]*il1);
    }
}

// ---------------- patch packing ----------------
__global__ void pack_kernel(const float* __restrict__ img, float* __restrict__ tok){
    size_t i = (size_t)blockIdx.x*blockDim.x + threadIdx.x;
    if (i >= (size_t)NTOK*PDIM) return;
    int pd = (int)(i % PDIM);
    size_t bl = i / PDIM;
    int l = (int)(bl % LMAX);
    int b = (int)(bl / LMAX);
    int L = c_L[b], w = c_Wp[b];
    float v = 0.f;
    if (l < L){
        int c  = pd >> 8;
        int r  = pd & 255;
        int py = r >> 4, px = r & 15;
        int ph = l / w, pw = l % w;
        v = img[((size_t)(b*3 + c)*512 + (size_t)(ph*16 + py))*512 + (size_t)(pw*16 + px)];
    }
    tok[i] = v;
}

// ---------------- row LayerNorm (D <= 768), blockDim 256 ----------------
__global__ void ln_kernel(const float* __restrict__ x, const float* __restrict__ w,
                          const float* __restrict__ bb, float* __restrict__ y, int D){
    __shared__ float red[8];
    int row = blockIdx.x, tid = threadIdx.x, lane = tid & 31, wp = tid >> 5;
    const float* xr = x + (size_t)row*D;
    float lv[3]; float s = 0.f;
    #pragma unroll
    for (int i = 0; i < 3; i++){
        int idx = tid + i*256;
        float vv = (idx < D) ? xr[idx] : 0.f;
        lv[i] = vv; s += vv;
    }
    #pragma unroll
    for (int off = 16; off; off >>= 1) s += __shfl_xor_sync(0xffffffffu, s, off);
    if (lane == 0) red[wp] = s;
    __syncthreads();
    float tot = 0.f;
    #pragma unroll
    for (int i = 0; i < 8; i++) tot += red[i];
    float mu = tot / (float)D;
    __syncthreads();
    float vs = 0.f;
    #pragma unroll
    for (int i = 0; i < 3; i++){
        int idx = tid + i*256;
        if (idx < D){ float d = lv[i] - mu; vs += d*d; }
    }
    #pragma unroll
    for (int off = 16; off; off >>= 1) vs += __shfl_xor_sync(0xffffffffu, vs, off);
    if (lane == 0) red[wp] = vs;
    __syncthreads();
    float tv = 0.f;
    #pragma unroll
    for (int i = 0; i < 8; i++) tv += red[i];
    float rs = rsqrtf(tv / (float)D + 1e-5f);
    float* yr = y + (size_t)row*D;
    #pragma unroll
    for (int i = 0; i < 3; i++){
        int idx = tid + i*256;
        if (idx < D){
            float val = (lv[i] - mu)*rs*w[idx];
            if (bb) val += bb[idx];
            yr[idx] = val;
        }
    }
}

// ---------------- per-head LayerNorm over 64 dims ----------------
__global__ void head_ln_kernel(float* __restrict__ x, const float* __restrict__ w, int rows){
    int gw = (int)(((size_t)blockIdx.x*blockDim.x + threadIdx.x) >> 5);
    int lane = threadIdx.x & 31;
    if (gw >= rows) return;
    float* p = x + (size_t)gw*64;
    float a = p[lane], b = p[lane + 32];
    float s = a + b;
    #pragma unroll
    for (int off = 16; off; off >>= 1) s += __shfl_xor_sync(0xffffffffu, s, off);
    float mu = s * (1.f/64.f);
    float da = a - mu, db = b - mu;
    float vs = da*da + db*db;
    #pragma unroll
    for (int off = 16; off; off >>= 1) vs += __shfl_xor_sync(0xffffffffu, vs, off);
    float rs = rsqrtf(vs * (1.f/64.f) + 1e-5f);
    p[lane]      = da * rs * w[lane];
    p[lane + 32] = db * rs * w[lane + 32];
}

// ---------------- pos embed + mask ----------------
__global__ void posmask_kernel(float* __restrict__ t, const float* __restrict__ ph,
                               const float* __restrict__ pw){
    int bl = blockIdx.x;
    int b = bl >> 10, l = bl & 1023;
    int L = c_L[b], w = c_Wp[b];
    float* r = t + (size_t)bl*DIM;
    int d = threadIdx.x;
    if (l < L) r[d] = r[d] + ph[(size_t)(l / w)*DIM + d] + pw[(size_t)(l % w)*DIM + d];
    else       r[d] = 0.f;
}

// ---------------- f32 SIMT GEMM NT (small M only) ----------------
__global__ __launch_bounds__(256) void gemm_nt_kernel(
    const float* __restrict__ A, int lda,
    const float* __restrict__ W, int ldw,
    const float* __restrict__ bias,
    float* __restrict__ C, int ldc,
    int M, int N, int K)
{
    __shared__ __align__(16) float As[8][128];
    __shared__ __align__(16) float Bs[8][128];
    int bm = blockIdx.y*128, bn = blockIdx.x*128;
    int tid = threadIdx.x;
    int tx = tid & 15, ty = tid >> 4;
    float acc[8][8];
    #pragma unroll
    for (int i = 0; i < 8; i++)
        #pragma unroll
        for (int j = 0; j < 8; j++) acc[i][j] = 0.f;
    int lr = tid >> 1;
    int lk = (tid & 1)*4;
    for (int k0 = 0; k0 < K; k0 += 8){
        float4 av = make_float4(0,0,0,0), bv = make_float4(0,0,0,0);
        if (bm + lr < M) av = *(const float4*)(A + (size_t)(bm + lr)*lda + k0 + lk);
        if (bn + lr < N) bv = *(const float4*)(W + (size_t)(bn + lr)*ldw + k0 + lk);
        As[lk+0][lr] = av.x; As[lk+1][lr] = av.y; As[lk+2][lr] = av.z; As[lk+3][lr] = av.w;
        Bs[lk+0][lr] = bv.x; Bs[lk+1][lr] = bv.y; Bs[lk+2][lr] = bv.z; Bs[lk+3][lr] = bv.w;
        __syncthreads();
        #pragma unroll
        for (int kk = 0; kk < 8; kk++){
            float a[8], b[8];
            #pragma unroll
            for (int i = 0; i < 8; i++) a[i] = As[kk][ty*8 + i];
            #pragma unroll
            for (int j = 0; j < 8; j++) b[j] = Bs[kk][tx*8 + j];
            #pragma unroll
            for (int i = 0; i < 8; i++)
                #pragma unroll
                for (int j = 0; j < 8; j++) acc[i][j] = fmaf(a[i], b[j], acc[i][j]);
        }
        __syncthreads();
    }
    #pragma unroll
    for (int i = 0; i < 8; i++){
        int m = bm + ty*8 + i;
        if (m >= M) continue;
        #pragma unroll
        for (int j = 0; j < 8; j++){
            int n = bn + tx*8 + j;
            if (n >= N) continue;
            float v = acc[i][j];
            if (bias) v += bias[n];
            C[(size_t)m*ldc + n] = v;
        }
    }
}

// ---------------- pooling attention (Lq=1) ----------------
__global__ void pool_attn_kernel(const float* __restrict__ qhat, const float* __restrict__ K,
                                 const float* __restrict__ V, float* __restrict__ O){
    int h = blockIdx.x, b = blockIdx.y;
    __shared__ float sq[64];
    __shared__ float sa[1024];
    __shared__ float red[8], red2[8];
    __shared__ float racc[4][64];
    int tid = threadIdx.x, lane = tid & 31, wp = tid >> 5;
    if (tid < 64) sq[tid] = qhat[h*64 + tid];
    __syncthreads();
    int L = c_L[b];
    for (int kk = tid; kk < 1024; kk += 256){
        float dot = -1e9f;
        if (kk < L){
            const float* kr = K + ((size_t)(b*1024 + kk))*DIM + h*64;
            float ss = 0.f;
            #pragma unroll
            for (int d = 0; d < 64; d++) ss += sq[d]*kr[d];
            dot = ss*0.125f;
        }
        sa[kk] = dot;
    }
    __syncthreads();
    float m = -1e30f;
    for (int kk = tid; kk < 1024; kk += 256) m = fmaxf(m, sa[kk]);
    #pragma unroll
    for (int off = 16; off; off >>= 1) m = fmaxf(m, __shfl_xor_sync(0xffffffffu, m, off));
    if (lane == 0) red[wp] = m;
    __syncthreads();
    float bm = -1e30f;
    #pragma unroll
    for (int i = 0; i < 8; i++) bm = fmaxf(bm, red[i]);
    float sum = 0.f;
    for (int kk = tid; kk < 1024; kk += 256){
        float e = __expf(sa[kk] - bm);
        sa[kk] = e; sum += e;
    }
    #pragma unroll
    for (int off = 16; off; off >>= 1) sum += __shfl_xor_sync(0xffffffffu, sum, off);
    if (lane == 0) red2[wp] = sum;
    __syncthreads();
    float bs = 0.f;
    #pragma unroll
    for (int i = 0; i < 8; i++) bs += red2[i];
    float inv = 1.f / bs;
    int dd = tid & 63, part = tid >> 6;
    float acc = 0.f;
    for (int kk = part; kk < 1024; kk += 4)
        acc += sa[kk] * V[((size_t)(b*1024 + kk))*DIM + h*64 + dd];
    racc[part][dd] = acc;
    __syncthreads();
    if (part == 0)
        O[b*DIM + h*64 + dd] = (racc[0][dd] + racc[1][dd] + racc[2][dd] + racc[3][dd]) * inv;
}

// ---------------- host helpers ----------------
static void launch_tg(const float* A, int lda,
                      const float* W, int ldw,
                      const float* bias, const float* R, int ldr,
                      float* C, int ldc,
                      int M, int N, int K, float alpha, int act, int tokrows){
    dim3 g((N + 127)/128, M/128, 1);
    hgemm_nt<<<g, 256, SMEM_TOT>>>(A, lda, 0, 0, W, ldw, 0, 0, bias,
                                   R, ldr, C, ldc, N, K, alpha, act, tokrows);
}
static void launch_small(const float* A, int lda, const float* W, int ldw,
                         const float* bias, float* C, int ldc, int M, int N, int K){
    dim3 g((N + 127)/128, (M + 127)/128, 1);
    gemm_nt_kernel<<<g, 256>>>(A, lda, W, ldw, bias, C, ldc, M, N, K);
}

extern "C" void kernel_launch(void* const* d_in, const int* in_sizes, int n_in,
                              void* d_out, int out_size){
    const float* images   = (const float*)d_in[0];
    const float* pe_ln1_w = (const float*)d_in[1];
    const float* pe_ln1_b = (const float*)d_in[2];
    const float* pe_w     = (const float*)d_in[3];
    const float* pe_b     = (const float*)d_in[4];
    const float* pe_ln2_w = (const float*)d_in[5];
    const float* pe_ln2_b = (const float*)d_in[6];
    const float* pos_h    = (const float*)d_in[7];
    const float* pos_w    = (const float*)d_in[8];
    const float* attn_ln  = (const float*)d_in[9];
    const float* wq       = (const float*)d_in[10];
    const float* wk       = (const float*)d_in[11];
    const float* wv       = (const float*)d_in[12];
    const float* qn       = (const float*)d_in[13];
    const float* kn       = (const float*)d_in[14];
    const float* wo       = (const float*)d_in[15];
    const float* ff_ln    = (const float*)d_in[16];
    const float* ff_w1    = (const float*)d_in[17];
    const float* ff_b1    = (const float*)d_in[18];
    const float* ff_w2    = (const float*)d_in[19];
    const float* ff_b2    = (const float*)d_in[20];
    const float* final_ln = (const float*)d_in[21];
    const float* pool_q   = (const float*)d_in[22];
    const float* pool_ln  = (const float*)d_in[23];
    const float* pool_wq  = (const float*)d_in[24];
    const float* pool_wk  = (const float*)d_in[25];
    const float* pool_wv  = (const float*)d_in[26];
    const float* pool_qn  = (const float*)d_in[27];
    const float* pool_kn  = (const float*)d_in[28];
    const float* pool_wo  = (const float*)d_in[29];
    const float* head_ln  = (const float*)d_in[30];
    const float* head_w   = (const float*)d_in[31];
    float* out = (float*)d_out;

    cudaFuncSetAttribute(hgemm_nt, cudaFuncAttributeMaxDynamicSharedMemorySize, SMEM_TOT);
    cudaFuncSetAttribute(flash_kernel, cudaFuncAttributeMaxDynamicSharedMemorySize, FSMEM);

    float *tok,*lt,*t,*xn,*q,*k,*v,*o,*mlp,*u,*qp,*po,*pooled,*hn;
    cudaGetSymbolAddress((void**)&tok, g_tok);
    cudaGetSymbolAddress((void**)&lt,  g_lt);
    cudaGetSymbolAddress((void**)&t,   g_t);
    cudaGetSymbolAddress((void**)&xn,  g_xn);
    cudaGetSymbolAddress((void**)&q,   g_q);
    cudaGetSymbolAddress((void**)&k,   g_k);
    cudaGetSymbolAddress((void**)&v,   g_v);
    cudaGetSymbolAddress((void**)&o,   g_o);
    cudaGetSymbolAddress((void**)&mlp, g_mlp);
    cudaGetSymbolAddress((void**)&u,   g_u);
    cudaGetSymbolAddress((void**)&qp,  g_qp);
    cudaGetSymbolAddress((void**)&po,  g_po);
    cudaGetSymbolAddress((void**)&pooled, g_pooled);
    cudaGetSymbolAddress((void**)&hn,  g_hn);

    // ---- patch embed ----
    pack_kernel<<<((size_t)NTOK*PDIM + 255)/256, 256>>>(images, tok);
    ln_kernel<<<NTOK, 256>>>(tok, pe_ln1_w, pe_ln1_b, lt, PDIM);
    launch_tg(lt, PDIM, pe_w, PDIM, pe_b, nullptr, 0, t, DIM, NTOK, DIM, PDIM, 1.f, 0, 1);
    ln_kernel<<<NTOK, 256>>>(t, pe_ln2_w, pe_ln2_b, t, DIM);
    posmask_kernel<<<NTOK, DIM>>>(t, pos_h, pos_w);

    // ---- transformer layers ----
    for (int l = 0; l < NDEPTH; l++){
        const float* wql = wq + (size_t)l*DIM*DIM;
        const float* wkl = wk + (size_t)l*DIM*DIM;
        const float* wvl = wv + (size_t)l*DIM*DIM;
        const float* wol = wo + (size_t)l*DIM*DIM;

        ln_kernel<<<NTOK, 256>>>(t, attn_ln + l*DIM, nullptr, xn, DIM);
        launch_tg(xn, DIM, wql, DIM, nullptr, nullptr, 0, q, DIM, NTOK, DIM, DIM, 1.f, 0, 1);
        launch_tg(xn, DIM, wkl, DIM, nullptr, nullptr, 0, k, DIM, NTOK, DIM, DIM, 1.f, 0, 1);
        launch_tg(xn, DIM, wvl, DIM, nullptr, nullptr, 0, v, DIM, NTOK, DIM, DIM, 1.f, 0, 1);
        head_ln_kernel<<<(NTOK*HEADS*32 + 255)/256, 256>>>(q, qn + l*DH, NTOK*HEADS);
        head_ln_kernel<<<(NTOK*HEADS*32 + 255)/256, 256>>>(k, kn + l*DH, NTOK*HEADS);
        flash_kernel<<<dim3(8, BB*HEADS), 256, FSMEM>>>(q, k, v, o);
        launch_tg(o, DIM, wol, DIM, nullptr, t, DIM, t, DIM, NTOK, DIM, DIM, 1.f, 0, 1);
        ln_kernel<<<NTOK, 256>>>(t, ff_ln + l*DIM, nullptr, xn, DIM);
        launch_tg(xn, DIM, ff_w1 + (size_t)l*MLPD*DIM, DIM, ff_b1 + l*MLPD,
                  nullptr, 0, mlp, MLPD, NTOK, MLPD, DIM, 1.f, 1, 1);
        launch_tg(mlp, MLPD, ff_w2 + (size_t)l*DIM*MLPD, MLPD, ff_b2 + l*DIM,
                  t, DIM, t, DIM, NTOK, DIM, MLPD, 1.f, 0, 1);
    }

    // ---- final LN + pooling ----
    ln_kernel<<<NTOK, 256>>>(t, final_ln, nullptr, xn, DIM);
    ln_kernel<<<1, 256>>>(pool_q, pool_ln, nullptr, u, DIM);
    launch_small(u, DIM, pool_wq, DIM, nullptr, qp, DIM, 1, DIM, DIM);
    head_ln_kernel<<<1, 256>>>(qp, pool_qn, HEADS);
    launch_tg(xn, DIM, pool_wk, DIM, nullptr, nullptr, 0, k, DIM, NTOK, DIM, DIM, 1.f, 0, 1);
    head_ln_kernel<<<(NTOK*HEADS*32 + 255)/256, 256>>>(k, pool_kn, NTOK*HEADS);
    launch_tg(xn, DIM, pool_wv, DIM, nullptr, nullptr, 0, v, DIM, NTOK, DIM, DIM, 1.f, 0, 1);
    pool_attn_kernel<<<dim3(HEADS, BB), 256>>>(qp, k, v, po);
    launch_small(po, DIM, pool_wo, DIM, nullptr, pooled, DIM, BB, DIM, DIM);
    ln_kernel<<<BB, 256>>>(pooled, head_ln, nullptr, hn, DIM);
    launch_small(hn, DIM, head_w, DIM, nullptr, out, NC, BB, NC, DIM);
}

// round 5
// speedup vs baseline: 6.3089x; 1.7315x over previous
#include <cuda_runtime.h>
#include <cuda_bf16.h>
#include <math.h>
#include <stdint.h>

#define BB 8
#define LMAX 1024
#define DIM 512
#define HEADS 8
#define DH 64
#define NDEPTH 6
#define MLPD 2048
#define NC 1000
#define PDIM 768
#define NTOK (BB*LMAX)   // 8192

__constant__ int c_L[8]  = {1024, 768, 896, 576, 560, 512, 384, 640};
__constant__ int c_Wp[8] = {  32,  24,  32,  24,  28,  32,  16,  20};

// weight-split buffer offsets (elements)
#define OFF_QKV 0L
#define OFF_WO  4718592L
#define OFF_FF1 6291456L
#define OFF_FF2 12582912L
#define OFF_PE  18874368L
#define OFF_PK  19267584L
#define OFF_PV  19529728L
#define WTOT    19791872L

// ---------------- scratch ----------------
__device__ __align__(128) float g_tok[(size_t)NTOK*PDIM];
__device__ __align__(128) float g_t  [(size_t)NTOK*DIM];
__device__ __align__(128) float g_qkv[(size_t)3*NTOK*DIM];
__device__ __align__(128) float g_u  [DIM];
__device__ __align__(128) float g_qp [DIM];
__device__ __align__(128) float g_po [BB*DIM];
__device__ __align__(128) float g_pooled[BB*DIM];
__device__ __align__(128) float g_hn [BB*DIM];
__device__ __align__(128) __nv_bfloat16 g_wh[WTOT];
__device__ __align__(128) __nv_bfloat16 g_wl[WTOT];
__device__ __align__(128) __nv_bfloat16 g_lth[(size_t)NTOK*PDIM];
__device__ __align__(128) __nv_bfloat16 g_ltl[(size_t)NTOK*PDIM];
__device__ __align__(128) __nv_bfloat16 g_xnh[(size_t)NTOK*DIM];
__device__ __align__(128) __nv_bfloat16 g_xnl[(size_t)NTOK*DIM];
__device__ __align__(128) __nv_bfloat16 g_mlph[(size_t)NTOK*MLPD];
__device__ __align__(128) __nv_bfloat16 g_mlpl[(size_t)NTOK*MLPD];
__device__ __align__(128) __nv_bfloat16 g_oh[(size_t)NTOK*DIM];
__device__ __align__(128) __nv_bfloat16 g_ol[(size_t)NTOK*DIM];

// ================= helpers =================
__device__ __forceinline__ uint32_t smem_u32(const void* p){
    uint32_t a; asm("{ .reg .u64 t; cvta.to.shared.u64 t, %1; cvt.u32.u64 %0, t; }" : "=r"(a) : "l"(p));
    return a;
}
__device__ __forceinline__ void ldsm_x4(uint32_t* r, uint32_t addr){
    asm volatile("ldmatrix.sync.aligned.m8n8.x4.shared.b16 {%0,%1,%2,%3}, [%4];"
        : "=r"(r[0]),"=r"(r[1]),"=r"(r[2]),"=r"(r[3]) : "r"(addr));
}
__device__ __forceinline__ void ldsm_x2(uint32_t* r, uint32_t addr){
    asm volatile("ldmatrix.sync.aligned.m8n8.x2.shared.b16 {%0,%1}, [%2];"
        : "=r"(r[0]),"=r"(r[1]) : "r"(addr));
}
__device__ __forceinline__ void ldsm_x2t(uint32_t* r, uint32_t addr){
    asm volatile("ldmatrix.sync.aligned.m8n8.x2.trans.shared.b16 {%0,%1}, [%2];"
        : "=r"(r[0]),"=r"(r[1]) : "r"(addr));
}
__device__ __forceinline__ void mma16816(float* c, const uint32_t* a, const uint32_t* b){
    asm volatile("mma.sync.aligned.m16n8k16.row.col.f32.bf16.bf16.f32 "
        "{%0,%1,%2,%3}, {%4,%5,%6,%7}, {%8,%9}, {%0,%1,%2,%3};"
        : "+f"(c[0]),"+f"(c[1]),"+f"(c[2]),"+f"(c[3])
        : "r"(a[0]),"r"(a[1]),"r"(a[2]),"r"(a[3]), "r"(b[0]),"r"(b[1]));
}
__device__ __forceinline__ void cp_async16(uint32_t dst, const void* src){
    asm volatile("cp.async.cg.shared.global [%0], [%1], 16;" :: "r"(dst), "l"(src) : "memory");
}
__device__ __forceinline__ void cp_commit(){ asm volatile("cp.async.commit_group;" ::: "memory"); }
template<int N> __device__ __forceinline__ void cp_wait(){
    asm volatile("cp.async.wait_group %0;" :: "n"(N) : "memory");
}
__device__ __forceinline__ uint32_t bf2u(__nv_bfloat162 v){ return *reinterpret_cast<uint32_t*>(&v); }
__device__ __forceinline__ uint32_t packbf(float a, float b){
    return bf2u(__float22bfloat162_rn(make_float2(a, b)));
}
__device__ __forceinline__ void cvt8(float4 a, float4 b, uint4& hi, uint4& lo){
    __nv_bfloat162 h0 = __float22bfloat162_rn(make_float2(a.x, a.y));
    __nv_bfloat162 h1 = __float22bfloat162_rn(make_float2(a.z, a.w));
    __nv_bfloat162 h2 = __float22bfloat162_rn(make_float2(b.x, b.y));
    __nv_bfloat162 h3 = __float22bfloat162_rn(make_float2(b.z, b.w));
    float2 f0 = __bfloat1622float2(h0), f1 = __bfloat1622float2(h1);
    float2 f2 = __bfloat1622float2(h2), f3 = __bfloat1622float2(h3);
    __nv_bfloat162 l0 = __float22bfloat162_rn(make_float2(a.x - f0.x, a.y - f0.y));
    __nv_bfloat162 l1 = __float22bfloat162_rn(make_float2(a.z - f1.x, a.w - f1.y));
    __nv_bfloat162 l2 = __float22bfloat162_rn(make_float2(b.x - f2.x, b.y - f2.y));
    __nv_bfloat162 l3 = __float22bfloat162_rn(make_float2(b.z - f3.x, b.w - f3.y));
    hi = make_uint4(bf2u(h0), bf2u(h1), bf2u(h2), bf2u(h3));
    lo = make_uint4(bf2u(l0), bf2u(l1), bf2u(l2), bf2u(l3));
}

// ---------------- f32 -> hi/lo bf16 split ----------------
__global__ void split_kernel(const float* __restrict__ src, __nv_bfloat16* __restrict__ h,
                             __nv_bfloat16* __restrict__ l, int n){
    int i = blockIdx.x*blockDim.x + threadIdx.x;
    if (i >= n) return;
    float v = src[i];
    __nv_bfloat16 hv = __float2bfloat16(v);
    h[i] = hv;
    l[i] = __float2bfloat16(v - __bfloat162float(hv));
}

// ============== cp.async HMMA GEMM NT on pre-split bf16 ==============
// C = (Ah+Al) @ (Wh+Wl)^T via 3-term split, f32 accum.
// M = NTOK fixed by grid.y, N = grid.x*128, K param. All dims multiples of 128/64.
#define BTILE (128*144)          // 18432
#define B_AH 0
#define B_AL BTILE
#define B_WH (2*BTILE)
#define B_WL (3*BTILE)
#define B_BUF (4*BTILE)          // 73728
#define B_SMEM (2*B_BUF)         // 147456

__global__ __launch_bounds__(256) void bgemm_nt(
    const __nv_bfloat16* __restrict__ Ah, const __nv_bfloat16* __restrict__ Al, int lda,
    const __nv_bfloat16* __restrict__ Wh, const __nv_bfloat16* __restrict__ Wl, int ldw, long wz,
    const float* __restrict__ bias,
    const float* __restrict__ R, int ldr,
    float* __restrict__ C, __nv_bfloat16* __restrict__ Ch, __nv_bfloat16* __restrict__ Cl,
    int ldc, long cz,
    int K, int act, int tokrows)
{
    extern __shared__ char smem[];
    uint32_t sb = smem_u32(smem);
    int tid = threadIdx.x, lane = tid & 31, wid = tid >> 5;
    int z = blockIdx.z;
    Wh += (size_t)z*wz; Wl += (size_t)z*wz;
    if (C)  C  += (size_t)z*cz;
    int bm = blockIdx.y*128, bn = blockIdx.x*128;
    if (tokrows && (bm & 1023) >= c_L[bm >> 10]) return;
    int wr = (wid & 1)*64;
    int wn = (wid >> 1)*32;

    float acc[4][4][4];
    #pragma unroll
    for (int i = 0; i < 4; i++)
        #pragma unroll
        for (int j = 0; j < 4; j++)
            #pragma unroll
            for (int p = 0; p < 4; p++) acc[i][j][p] = 0.f;

#define BSTAGE(KC, BUFB) do { \
    _Pragma("unroll") \
    for (int it = 0; it < 4; it++){ \
        int slot = it*256 + tid; int row = slot >> 3, seg = slot & 7; \
        uint32_t so = (uint32_t)(BUFB) + (uint32_t)(row*144 + seg*16); \
        cp_async16(sb + B_AH + so, Ah + (size_t)(bm + row)*lda + (KC)*64 + seg*8); \
        cp_async16(sb + B_AL + so, Al + (size_t)(bm + row)*lda + (KC)*64 + seg*8); \
        cp_async16(sb + B_WH + so, Wh + (size_t)(bn + row)*ldw + (KC)*64 + seg*8); \
        cp_async16(sb + B_WL + so, Wl + (size_t)(bn + row)*ldw + (KC)*64 + seg*8); \
    } } while(0)

    int nk = K >> 6;
    BSTAGE(0, 0);
    cp_commit();

    int grp = lane >> 3, wi = lane & 7;
    for (int kc = 0; kc < nk; kc++){
        if (kc + 1 < nk){
            BSTAGE(kc + 1, ((kc + 1) & 1)*B_BUF);
            cp_commit();
            cp_wait<1>();
        } else {
            cp_wait<0>();
        }
        __syncthreads();
        uint32_t cur = (uint32_t)((kc & 1)*B_BUF);
        #pragma unroll
        for (int ks = 0; ks < 4; ks++){
            uint32_t a_hi[4][4], a_lo[4][4];
            #pragma unroll
            for (int mi = 0; mi < 4; mi++){
                uint32_t off = (uint32_t)((wr + mi*16 + wi + (grp & 1)*8)*144
                                          + (ks*16 + (grp >> 1)*8)*2);
                ldsm_x4(a_hi[mi], sb + B_AH + cur + off);
                ldsm_x4(a_lo[mi], sb + B_AL + cur + off);
            }
            uint32_t b_hi[4][2], b_lo[4][2];
            #pragma unroll
            for (int ni = 0; ni < 4; ni++){
                uint32_t off = (uint32_t)((wn + ni*8 + (lane & 7))*144
                                          + (ks*16 + ((lane >> 3) & 1)*8)*2);
                ldsm_x2(b_hi[ni], sb + B_WH + cur + off);
                ldsm_x2(b_lo[ni], sb + B_WL + cur + off);
            }
            #pragma unroll
            for (int mi = 0; mi < 4; mi++)
                #pragma unroll
                for (int ni = 0; ni < 4; ni++){
                    mma16816(acc[mi][ni], a_hi[mi], b_hi[ni]);
                    mma16816(acc[mi][ni], a_hi[mi], b_lo[ni]);
                    mma16816(acc[mi][ni], a_lo[mi], b_hi[ni]);
                }
        }
        __syncthreads();
    }
#undef BSTAGE

    // ---- epilogue ----
    #pragma unroll
    for (int mi = 0; mi < 4; mi++){
        #pragma unroll
        for (int ni = 0; ni < 4; ni++){
            int gn = bn + wn + ni*8 + (lane & 3)*2;
            #pragma unroll
            for (int hh = 0; hh < 2; hh++){
                int m = bm + wr + mi*16 + (lane >> 2) + hh*8;
                float v0 = acc[mi][ni][hh*2 + 0];
                float v1 = acc[mi][ni][hh*2 + 1];
                if (bias){ v0 += bias[gn]; v1 += bias[gn + 1]; }
                if (act){
                    v0 = 0.5f*v0*(1.f + erff(v0*0.70710678118654752f));
                    v1 = 0.5f*v1*(1.f + erff(v1*0.70710678118654752f));
                }
                if (Ch){
                    uint32_t hp = packbf(v0, v1);
                    float2 hf = __bfloat1622float2(*reinterpret_cast<__nv_bfloat162*>(&hp));
                    uint32_t lp = packbf(v0 - hf.x, v1 - hf.y);
                    *(uint32_t*)(Ch + (size_t)m*ldc + gn) = hp;
                    *(uint32_t*)(Cl + (size_t)m*ldc + gn) = lp;
                } else {
                    if (R){
                        const float* rp = R + (size_t)m*ldr + gn;
                        v0 += rp[0]; v1 += rp[1];
                    }
                    *(float2*)(C + (size_t)m*ldc + gn) = make_float2(v0, v1);
                }
            }
        }
    }
}

// ============== flash attention with fused QK head-LN; writes split-bf16 O ==============
#define FP2 144
#define FT (128*144)
#define FQH 0
#define FQL (1*FT)
#define FKH (2*FT)
#define FKL (3*FT)
#define FVH (4*FT)
#define FVL (5*FT)
#define FSMEM (6*FT)    // 110592

__global__ __launch_bounds__(256) void flash_kernel(
    const float* __restrict__ Q, const float* __restrict__ K,
    const float* __restrict__ V,
    const float* __restrict__ qn, const float* __restrict__ kn,
    __nv_bfloat16* __restrict__ Oh, __nv_bfloat16* __restrict__ Ol)
{
    extern __shared__ char smem[];
    uint32_t sb = smem_u32(smem);
    int tid = threadIdx.x, lane = tid & 31, wid = tid >> 5;
    int qt = blockIdx.x;
    int bh = blockIdx.y;
    int b = bh >> 3, h = bh & 7;
    int L = c_L[b];
    if (qt*128 >= L) return;
    int ktiles = (L + 127) >> 7;

    // ---- stage Q with fused head-LN (x qn x 1/8), hi/lo ----
    #pragma unroll
    for (int it = 0; it < 4; it++){
        int slot = it*256 + tid; int row = slot >> 3, seg = slot & 7;
        const float* qp = Q + (size_t)(b*1024 + qt*128 + row)*DIM + h*64 + seg*8;
        float4 x = *(const float4*)qp;
        float4 y = *(const float4*)(qp + 4);
        float sum = x.x + x.y + x.z + x.w + y.x + y.y + y.z + y.w;
        sum += __shfl_xor_sync(0xffffffffu, sum, 1);
        sum += __shfl_xor_sync(0xffffffffu, sum, 2);
        sum += __shfl_xor_sync(0xffffffffu, sum, 4);
        float mu = sum * (1.f/64.f);
        x.x -= mu; x.y -= mu; x.z -= mu; x.w -= mu;
        y.x -= mu; y.y -= mu; y.z -= mu; y.w -= mu;
        float ss = x.x*x.x + x.y*x.y + x.z*x.z + x.w*x.w
                 + y.x*y.x + y.y*y.y + y.z*y.z + y.w*y.w;
        ss += __shfl_xor_sync(0xffffffffu, ss, 1);
        ss += __shfl_xor_sync(0xffffffffu, ss, 2);
        ss += __shfl_xor_sync(0xffffffffu, ss, 4);
        float rs = rsqrtf(ss * (1.f/64.f) + 1e-5f) * 0.125f;
        float4 w0 = *(const float4*)(qn + seg*8);
        float4 w1 = *(const float4*)(qn + seg*8 + 4);
        x.x *= rs*w0.x; x.y *= rs*w0.y; x.z *= rs*w0.z; x.w *= rs*w0.w;
        y.x *= rs*w1.x; y.y *= rs*w1.y; y.z *= rs*w1.z; y.w *= rs*w1.w;
        uint4 hi, lo; cvt8(x, y, hi, lo);
        uint32_t off = (uint32_t)(row*FP2 + seg*16);
        *(uint4*)(smem + FQH + off) = hi;
        *(uint4*)(smem + FQL + off) = lo;
    }
    __syncthreads();

    int wr = wid*16;
    int grp = lane >> 3, wi = lane & 7;
    uint32_t aqh[4][4], aql[4][4];
    #pragma unroll
    for (int ks = 0; ks < 4; ks++){
        uint32_t off = (uint32_t)((wr + wi + (grp & 1)*8)*FP2 + (ks*16 + (grp >> 1)*8)*2);
        ldsm_x4(aqh[ks], sb + FQH + off);
        ldsm_x4(aql[ks], sb + FQL + off);
    }

    float m0 = -1e30f, m1 = -1e30f, l0 = 0.f, l1 = 0.f;
    float ao[8][4];
    #pragma unroll
    for (int i = 0; i < 8; i++)
        #pragma unroll
        for (int p = 0; p < 4; p++) ao[i][p] = 0.f;

    for (int kt = 0; kt < ktiles; kt++){
        __syncthreads();
        #pragma unroll
        for (int it = 0; it < 4; it++){
            int slot = it*256 + tid; int row = slot >> 3, seg = slot & 7;
            uint32_t off = (uint32_t)(row*FP2 + seg*16);
            uint4 hi, lo;
            {   // K row with fused head-LN (x kn)
                const float* kp = K + (size_t)(b*1024 + kt*128 + row)*DIM + h*64 + seg*8;
                float4 x = *(const float4*)kp;
                float4 y = *(const float4*)(kp + 4);
                float sum = x.x + x.y + x.z + x.w + y.x + y.y + y.z + y.w;
                sum += __shfl_xor_sync(0xffffffffu, sum, 1);
                sum += __shfl_xor_sync(0xffffffffu, sum, 2);
                sum += __shfl_xor_sync(0xffffffffu, sum, 4);
                float mu = sum * (1.f/64.f);
                x.x -= mu; x.y -= mu; x.z -= mu; x.w -= mu;
                y.x -= mu; y.y -= mu; y.z -= mu; y.w -= mu;
                float ss = x.x*x.x + x.y*x.y + x.z*x.z + x.w*x.w
                         + y.x*y.x + y.y*y.y + y.z*y.z + y.w*y.w;
                ss += __shfl_xor_sync(0xffffffffu, ss, 1);
                ss += __shfl_xor_sync(0xffffffffu, ss, 2);
                ss += __shfl_xor_sync(0xffffffffu, ss, 4);
                float rs = rsqrtf(ss * (1.f/64.f) + 1e-5f);
                float4 w0 = *(const float4*)(kn + seg*8);
                float4 w1 = *(const float4*)(kn + seg*8 + 4);
                x.x *= rs*w0.x; x.y *= rs*w0.y; x.z *= rs*w0.z; x.w *= rs*w0.w;
                y.x *= rs*w1.x; y.y *= rs*w1.y; y.z *= rs*w1.z; y.w *= rs*w1.w;
                cvt8(x, y, hi, lo);
                *(uint4*)(smem + FKH + off) = hi;
                *(uint4*)(smem + FKL + off) = lo;
            }
            {   // V row raw
                const float* vp = V + (size_t)(b*1024 + kt*128 + row)*DIM + h*64 + seg*8;
                cvt8(*(const float4*)vp, *(const float4*)(vp + 4), hi, lo);
                *(uint4*)(smem + FVH + off) = hi;
                *(uint4*)(smem + FVL + off) = lo;
            }
        }
        __syncthreads();

        // ---- S = Q K^T ----
        float s[16][4];
        #pragma unroll
        for (int i = 0; i < 16; i++)
            #pragma unroll
            for (int p = 0; p < 4; p++) s[i][p] = 0.f;
        #pragma unroll
        for (int ks = 0; ks < 4; ks++){
            #pragma unroll
            for (int ni = 0; ni < 16; ni++){
                uint32_t off = (uint32_t)((ni*8 + wi)*FP2 + (ks*16 + (grp & 1)*8)*2);
                uint32_t bh_[2], bl_[2];
                ldsm_x2(bh_, sb + FKH + off);
                ldsm_x2(bl_, sb + FKL + off);
                mma16816(s[ni], aqh[ks], bh_);
                mma16816(s[ni], aqh[ks], bl_);
                mma16816(s[ni], aql[ks], bh_);
            }
        }

        // ---- mask (partial tile only) ----
        if (kt == ktiles - 1 && (L & 127)){
            int kb = kt*128 + 2*(lane & 3);
            #pragma unroll
            for (int ni = 0; ni < 16; ni++){
                int kg = kb + ni*8;
                if (kg     >= L){ s[ni][0] = -1e9f; s[ni][2] = -1e9f; }
                if (kg + 1 >= L){ s[ni][1] = -1e9f; s[ni][3] = -1e9f; }
            }
        }

        // ---- online softmax ----
        float tm0 = -1e30f, tm1 = -1e30f;
        #pragma unroll
        for (int ni = 0; ni < 16; ni++){
            tm0 = fmaxf(tm0, fmaxf(s[ni][0], s[ni][1]));
            tm1 = fmaxf(tm1, fmaxf(s[ni][2], s[ni][3]));
        }
        tm0 = fmaxf(tm0, __shfl_xor_sync(0xffffffffu, tm0, 1));
        tm0 = fmaxf(tm0, __shfl_xor_sync(0xffffffffu, tm0, 2));
        tm1 = fmaxf(tm1, __shfl_xor_sync(0xffffffffu, tm1, 1));
        tm1 = fmaxf(tm1, __shfl_xor_sync(0xffffffffu, tm1, 2));
        float mn0 = fmaxf(m0, tm0), mn1 = fmaxf(m1, tm1);
        float sc0 = __expf(m0 - mn0), sc1 = __expf(m1 - mn1);
        m0 = mn0; m1 = mn1;
        float ts0 = 0.f, ts1 = 0.f;
        #pragma unroll
        for (int ni = 0; ni < 16; ni++){
            s[ni][0] = __expf(s[ni][0] - m0);
            s[ni][1] = __expf(s[ni][1] - m0);
            s[ni][2] = __expf(s[ni][2] - m1);
            s[ni][3] = __expf(s[ni][3] - m1);
            ts0 += s[ni][0] + s[ni][1];
            ts1 += s[ni][2] + s[ni][3];
        }
        ts0 += __shfl_xor_sync(0xffffffffu, ts0, 1);
        ts0 += __shfl_xor_sync(0xffffffffu, ts0, 2);
        ts1 += __shfl_xor_sync(0xffffffffu, ts1, 1);
        ts1 += __shfl_xor_sync(0xffffffffu, ts1, 2);
        l0 = l0*sc0 + ts0;
        l1 = l1*sc1 + ts1;
        #pragma unroll
        for (int i = 0; i < 8; i++){
            ao[i][0] *= sc0; ao[i][1] *= sc0;
            ao[i][2] *= sc1; ao[i][3] *= sc1;
        }

        // ---- O += P V ----
        #pragma unroll
        for (int kk = 0; kk < 8; kk++){
            float p00 = s[2*kk][0],   p01 = s[2*kk][1],   p02 = s[2*kk][2],   p03 = s[2*kk][3];
            float p10 = s[2*kk+1][0], p11 = s[2*kk+1][1], p12 = s[2*kk+1][2], p13 = s[2*kk+1][3];
            uint32_t aph[4], apl[4];
            aph[0] = packbf(p00, p01); aph[1] = packbf(p02, p03);
            aph[2] = packbf(p10, p11); aph[3] = packbf(p12, p13);
            {
                float2 f0 = __bfloat1622float2(*reinterpret_cast<__nv_bfloat162*>(&aph[0]));
                float2 f1 = __bfloat1622float2(*reinterpret_cast<__nv_bfloat162*>(&aph[1]));
                float2 f2 = __bfloat1622float2(*reinterpret_cast<__nv_bfloat162*>(&aph[2]));
                float2 f3 = __bfloat1622float2(*reinterpret_cast<__nv_bfloat162*>(&aph[3]));
                apl[0] = packbf(p00 - f0.x, p01 - f0.y);
                apl[1] = packbf(p02 - f1.x, p03 - f1.y);
                apl[2] = packbf(p10 - f2.x, p11 - f2.y);
                apl[3] = packbf(p12 - f3.x, p13 - f3.y);
            }
            #pragma unroll
            for (int ni = 0; ni < 8; ni++){
                uint32_t off = (uint32_t)((kk*16 + (lane & 15))*FP2 + ni*16);
                uint32_t vh_[2], vl_[2];
                ldsm_x2t(vh_, sb + FVH + off);
                ldsm_x2t(vl_, sb + FVL + off);
                mma16816(ao[ni], aph, vh_);
                mma16816(ao[ni], apl, vh_);
                mma16816(ao[ni], aph, vl_);
            }
        }
    }

    // ---- epilogue: split-bf16 O ----
    float il0 = 1.f / l0, il1 = 1.f / l1;
    int mrow = qt*128 + wr + (lane >> 2);
    #pragma unroll
    for (int ni = 0; ni < 8; ni++){
        int col = h*64 + ni*8 + 2*(lane & 3);
        {
            float a0 = ao[ni][0]*il0, a1 = ao[ni][1]*il0;
            uint32_t hp = packbf(a0, a1);
            float2 hf = __bfloat1622float2(*reinterpret_cast<__nv_bfloat162*>(&hp));
            uint32_t lp = packbf(a0 - hf.x, a1 - hf.y);
            *(uint32_t*)(Oh + (size_t)(b*1024 + mrow)*DIM + col) = hp;
            *(uint32_t*)(Ol + (size_t)(b*1024 + mrow)*DIM + col) = lp;
        }
        {
            float a0 = ao[ni][2]*il1, a1 = ao[ni][3]*il1;
            uint32_t hp = packbf(a0, a1);
            float2 hf = __bfloat1622float2(*reinterpret_cast<__nv_bfloat162*>(&hp));
            uint32_t lp = packbf(a0 - hf.x, a1 - hf.y);
            *(uint32_t*)(Oh + (size_t)(b*1024 + mrow + 8)*DIM + col) = hp;
            *(uint32_t*)(Ol + (size_t)(b*1024 + mrow + 8)*DIM + col) = lp;
        }
    }
}

// ---------------- patch packing ----------------
__global__ void pack_kernel(const float* __restrict__ img, float* __restrict__ tok){
    size_t i = (size_t)blockIdx.x*blockDim.x + threadIdx.x;
    if (i >= (size_t)NTOK*PDIM) return;
    int pd = (int)(i % PDIM);
    size_t bl = i / PDIM;
    int l = (int)(bl % LMAX);
    int b = (int)(bl / LMAX);
    int L = c_L[b], w = c_Wp[b];
    float v = 0.f;
    if (l < L){
        int c  = pd >> 8;
        int r  = pd & 255;
        int py = r >> 4, px = r & 15;
        int ph = l / w, pw = l % w;
        v = img[((size_t)(b*3 + c)*512 + (size_t)(ph*16 + py))*512 + (size_t)(pw*16 + px)];
    }
    tok[i] = v;
}

// ---------------- row LayerNorm; writes f32 (y) or split bf16 (yh/yl) ----------------
__global__ void ln_kernel(const float* __restrict__ x, const float* __restrict__ w,
                          const float* __restrict__ bb, float* __restrict__ y,
                          __nv_bfloat16* __restrict__ yh, __nv_bfloat16* __restrict__ yl, int D){
    __shared__ float red[8];
    int row = blockIdx.x, tid = threadIdx.x, lane = tid & 31, wp = tid >> 5;
    const float* xr = x + (size_t)row*D;
    float lv[3]; float s = 0.f;
    #pragma unroll
    for (int i = 0; i < 3; i++){
        int idx = tid + i*256;
        float vv = (idx < D) ? xr[idx] : 0.f;
        lv[i] = vv; s += vv;
    }
    #pragma unroll
    for (int off = 16; off; off >>= 1) s += __shfl_xor_sync(0xffffffffu, s, off);
    if (lane == 0) red[wp] = s;
    __syncthreads();
    float tot = 0.f;
    #pragma unroll
    for (int i = 0; i < 8; i++) tot += red[i];
    float mu = tot / (float)D;
    __syncthreads();
    float vs = 0.f;
    #pragma unroll
    for (int i = 0; i < 3; i++){
        int idx = tid + i*256;
        if (idx < D){ float d = lv[i] - mu; vs += d*d; }
    }
    #pragma unroll
    for (int off = 16; off; off >>= 1) vs += __shfl_xor_sync(0xffffffffu, vs, off);
    if (lane == 0) red[wp] = vs;
    __syncthreads();
    float tv = 0.f;
    #pragma unroll
    for (int i = 0; i < 8; i++) tv += red[i];
    float rs = rsqrtf(tv / (float)D + 1e-5f);
    #pragma unroll
    for (int i = 0; i < 3; i++){
        int idx = tid + i*256;
        if (idx < D){
            float val = (lv[i] - mu)*rs*w[idx];
            if (bb) val += bb[idx];
            if (y) y[(size_t)row*D + idx] = val;
            else {
                __nv_bfloat16 hv = __float2bfloat16(val);
                yh[(size_t)row*D + idx] = hv;
                yl[(size_t)row*D + idx] = __float2bfloat16(val - __bfloat162float(hv));
            }
        }
    }
}

// ---------------- per-head LayerNorm over 64 dims ----------------
__global__ void head_ln_kernel(float* __restrict__ x, const float* __restrict__ w, int rows){
    int gw = (int)(((size_t)blockIdx.x*blockDim.x + threadIdx.x) >> 5);
    int lane = threadIdx.x & 31;
    if (gw >= rows) return;
    float* p = x + (size_t)gw*64;
    float a = p[lane], b = p[lane + 32];
    float s = a + b;
    #pragma unroll
    for (int off = 16; off; off >>= 1) s += __shfl_xor_sync(0xffffffffu, s, off);
    float mu = s * (1.f/64.f);
    float da = a - mu, db = b - mu;
    float vs = da*da + db*db;
    #pragma unroll
    for (int off = 16; off; off >>= 1) vs += __shfl_xor_sync(0xffffffffu, vs, off);
    float rs = rsqrtf(vs * (1.f/64.f) + 1e-5f);
    p[lane]      = da * rs * w[lane];
    p[lane + 32] = db * rs * w[lane + 32];
}

// ---------------- pos embed + mask ----------------
__global__ void posmask_kernel(float* __restrict__ t, const float* __restrict__ ph,
                               const float* __restrict__ pw){
    int bl = blockIdx.x;
    int b = bl >> 10, l = bl & 1023;
    int L = c_L[b], w = c_Wp[b];
    float* r = t + (size_t)bl*DIM;
    int d = threadIdx.x;
    if (l < L) r[d] = r[d] + ph[(size_t)(l / w)*DIM + d] + pw[(size_t)(l % w)*DIM + d];
    else       r[d] = 0.f;
}

// ---------------- f32 SIMT GEMM NT (small M only) ----------------
__global__ __launch_bounds__(256) void gemm_nt_kernel(
    const float* __restrict__ A, int lda,
    const float* __restrict__ W, int ldw,
    const float* __restrict__ bias,
    float* __restrict__ C, int ldc,
    int M, int N, int K)
{
    __shared__ __align__(16) float As[8][128];
    __shared__ __align__(16) float Bs[8][128];
    int bm = blockIdx.y*128, bn = blockIdx.x*128;
    int tid = threadIdx.x;
    int tx = tid & 15, ty = tid >> 4;
    float acc[8][8];
    #pragma unroll
    for (int i = 0; i < 8; i++)
        #pragma unroll
        for (int j = 0; j < 8; j++) acc[i][j] = 0.f;
    int lr = tid >> 1;
    int lk = (tid & 1)*4;
    for (int k0 = 0; k0 < K; k0 += 8){
        float4 av = make_float4(0,0,0,0), bv = make_float4(0,0,0,0);
        if (bm + lr < M) av = *(const float4*)(A + (size_t)(bm + lr)*lda + k0 + lk);
        if (bn + lr < N) bv = *(const float4*)(W + (size_t)(bn + lr)*ldw + k0 + lk);
        As[lk+0][lr] = av.x; As[lk+1][lr] = av.y; As[lk+2][lr] = av.z; As[lk+3][lr] = av.w;
        Bs[lk+0][lr] = bv.x; Bs[lk+1][lr] = bv.y; Bs[lk+2][lr] = bv.z; Bs[lk+3][lr] = bv.w;
        __syncthreads();
        #pragma unroll
        for (int kk = 0; kk < 8; kk++){
            float a[8], b[8];
            #pragma unroll
            for (int i = 0; i < 8; i++) a[i] = As[kk][ty*8 + i];
            #pragma unroll
            for (int j = 0; j < 8; j++) b[j] = Bs[kk][tx*8 + j];
            #pragma unroll
            for (int i = 0; i < 8; i++)
                #pragma unroll
                for (int j = 0; j < 8; j++) acc[i][j] = fmaf(a[i], b[j], acc[i][j]);
        }
        __syncthreads();
    }
    #pragma unroll
    for (int i = 0; i < 8; i++){
        int m = bm + ty*8 + i;
        if (m >= M) continue;
        #pragma unroll
        for (int j = 0; j < 8; j++){
            int n = bn + tx*8 + j;
            if (n >= N) continue;
            float v = acc[i][j];
            if (bias) v += bias[n];
            C[(size_t)m*ldc + n] = v;
        }
    }
}

// ---------------- pooling attention (Lq=1) ----------------
__global__ void pool_attn_kernel(const float* __restrict__ qhat, const float* __restrict__ K,
                                 const float* __restrict__ V, float* __restrict__ O){
    int h = blockIdx.x, b = blockIdx.y;
    __shared__ float sq[64];
    __shared__ float sa[1024];
    __shared__ float red[8], red2[8];
    __shared__ float racc[4][64];
    int tid = threadIdx.x, lane = tid & 31, wp = tid >> 5;
    if (tid < 64) sq[tid] = qhat[h*64 + tid];
    __syncthreads();
    int L = c_L[b];
    for (int kk = tid; kk < 1024; kk += 256){
        float dot = -1e9f;
        if (kk < L){
            const float* kr = K + ((size_t)(b*1024 + kk))*DIM + h*64;
            float ss = 0.f;
            #pragma unroll
            for (int d = 0; d < 64; d++) ss += sq[d]*kr[d];
            dot = ss*0.125f;
        }
        sa[kk] = dot;
    }
    __syncthreads();
    float m = -1e30f;
    for (int kk = tid; kk < 1024; kk += 256) m = fmaxf(m, sa[kk]);
    #pragma unroll
    for (int off = 16; off; off >>= 1) m = fmaxf(m, __shfl_xor_sync(0xffffffffu, m, off));
    if (lane == 0) red[wp] = m;
    __syncthreads();
    float bm = -1e30f;
    #pragma unroll
    for (int i = 0; i < 8; i++) bm = fmaxf(bm, red[i]);
    float sum = 0.f;
    for (int kk = tid; kk < 1024; kk += 256){
        float e = __expf(sa[kk] - bm);
        sa[kk] = e; sum += e;
    }
    #pragma unroll
    for (int off = 16; off; off >>= 1) sum += __shfl_xor_sync(0xffffffffu, sum, off);
    if (lane == 0) red2[wp] = sum;
    __syncthreads();
    float bs = 0.f;
    #pragma unroll
    for (int i = 0; i < 8; i++) bs += red2[i];
    float inv = 1.f / bs;
    int dd = tid & 63, part = tid >> 6;
    float acc = 0.f;
    for (int kk = part; kk < 1024; kk += 4)
        acc += sa[kk] * V[((size_t)(b*1024 + kk))*DIM + h*64 + dd];
    racc[part][dd] = acc;
    __syncthreads();
    if (part == 0)
        O[b*DIM + h*64 + dd] = (racc[0][dd] + racc[1][dd] + racc[2][dd] + racc[3][dd]) * inv;
}

// ---------------- host helpers ----------------
static void launch_split(const float* src, __nv_bfloat16* h, __nv_bfloat16* l, long n){
    split_kernel<<<(int)((n + 255)/256), 256>>>(src, h, l, (int)n);
}
static void launch_bg(const __nv_bfloat16* Ah, const __nv_bfloat16* Al, int lda,
                      const __nv_bfloat16* Wh, const __nv_bfloat16* Wl, int ldw, long wz,
                      const float* bias, const float* R, int ldr,
                      float* C, __nv_bfloat16* Ch, __nv_bfloat16* Cl, int ldc, long cz,
                      int N, int K, int act, int nz, int tokrows){
    dim3 g(N/128, NTOK/128, nz);
    bgemm_nt<<<g, 256, B_SMEM>>>(Ah, Al, lda, Wh, Wl, ldw, wz, bias, R, ldr,
                                 C, Ch, Cl, ldc, cz, K, act, tokrows);
}
static void launch_small(const float* A, int lda, const float* W, int ldw,
                         const float* bias, float* C, int ldc, int M, int N, int K){
    dim3 g((N + 127)/128, (M + 127)/128, 1);
    gemm_nt_kernel<<<g, 256>>>(A, lda, W, ldw, bias, C, ldc, M, N, K);
}

extern "C" void kernel_launch(void* const* d_in, const int* in_sizes, int n_in,
                              void* d_out, int out_size){
    const float* images   = (const float*)d_in[0];
    const float* pe_ln1_w = (const float*)d_in[1];
    const float* pe_ln1_b = (const float*)d_in[2];
    const float* pe_w     = (const float*)d_in[3];
    const float* pe_b     = (const float*)d_in[4];
    const float* pe_ln2_w = (const float*)d_in[5];
    const float* pe_ln2_b = (const float*)d_in[6];
    const float* pos_h    = (const float*)d_in[7];
    const float* pos_w    = (const float*)d_in[8];
    const float* attn_ln  = (const float*)d_in[9];
    const float* wq       = (const float*)d_in[10];
    const float* wk       = (const float*)d_in[11];
    const float* wv       = (const float*)d_in[12];
    const float* qn       = (const float*)d_in[13];
    const float* kn       = (const float*)d_in[14];
    const float* wo       = (const float*)d_in[15];
    const float* ff_ln    = (const float*)d_in[16];
    const float* ff_w1    = (const float*)d_in[17];
    const float* ff_b1    = (const float*)d_in[18];
    const float* ff_w2    = (const float*)d_in[19];
    const float* ff_b2    = (const float*)d_in[20];
    const float* final_ln = (const float*)d_in[21];
    const float* pool_q   = (const float*)d_in[22];
    const float* pool_ln  = (const float*)d_in[23];
    const float* pool_wq  = (const float*)d_in[24];
    const float* pool_wk  = (const float*)d_in[25];
    const float* pool_wv  = (const float*)d_in[26];
    const float* pool_qn  = (const float*)d_in[27];
    const float* pool_kn  = (const float*)d_in[28];
    const float* pool_wo  = (const float*)d_in[29];
    const float* head_ln  = (const float*)d_in[30];
    const float* head_w   = (const float*)d_in[31];
    float* out = (float*)d_out;

    cudaFuncSetAttribute(bgemm_nt, cudaFuncAttributeMaxDynamicSharedMemorySize, B_SMEM);
    cudaFuncSetAttribute(flash_kernel, cudaFuncAttributeMaxDynamicSharedMemorySize, FSMEM);

    float *tok,*t,*qkv,*u,*qp,*po,*pooled,*hn;
    __nv_bfloat16 *wh,*wl,*lth,*ltl,*xnh,*xnl,*mlph,*mlpl,*oh,*ol;
    cudaGetSymbolAddress((void**)&tok, g_tok);
    cudaGetSymbolAddress((void**)&t,   g_t);
    cudaGetSymbolAddress((void**)&qkv, g_qkv);
    cudaGetSymbolAddress((void**)&u,   g_u);
    cudaGetSymbolAddress((void**)&qp,  g_qp);
    cudaGetSymbolAddress((void**)&po,  g_po);
    cudaGetSymbolAddress((void**)&pooled, g_pooled);
    cudaGetSymbolAddress((void**)&hn,  g_hn);
    cudaGetSymbolAddress((void**)&wh,  g_wh);
    cudaGetSymbolAddress((void**)&wl,  g_wl);
    cudaGetSymbolAddress((void**)&lth, g_lth);
    cudaGetSymbolAddress((void**)&ltl, g_ltl);
    cudaGetSymbolAddress((void**)&xnh, g_xnh);
    cudaGetSymbolAddress((void**)&xnl, g_xnl);
    cudaGetSymbolAddress((void**)&mlph, g_mlph);
    cudaGetSymbolAddress((void**)&mlpl, g_mlpl);
    cudaGetSymbolAddress((void**)&oh,  g_oh);
    cudaGetSymbolAddress((void**)&ol,  g_ol);

    float* q = qkv;
    float* k = qkv + (size_t)NTOK*DIM;
    float* v = qkv + (size_t)2*NTOK*DIM;

    // ---- weight split (once per launch) ----
    launch_split(wq, wh + OFF_QKV,             wl + OFF_QKV,             6L*DIM*DIM);
    launch_split(wk, wh + OFF_QKV + 1572864L,  wl + OFF_QKV + 1572864L,  6L*DIM*DIM);
    launch_split(wv, wh + OFF_QKV + 3145728L,  wl + OFF_QKV + 3145728L,  6L*DIM*DIM);
    launch_split(wo, wh + OFF_WO,  wl + OFF_WO,  6L*DIM*DIM);
    launch_split(ff_w1, wh + OFF_FF1, wl + OFF_FF1, 6L*MLPD*DIM);
    launch_split(ff_w2, wh + OFF_FF2, wl + OFF_FF2, 6L*DIM*MLPD);
    launch_split(pe_w, wh + OFF_PE, wl + OFF_PE, (long)DIM*PDIM);
    launch_split(pool_wk, wh + OFF_PK, wl + OFF_PK, (long)DIM*DIM);
    launch_split(pool_wv, wh + OFF_PV, wl + OFF_PV, (long)DIM*DIM);

    // ---- patch embed ----
    pack_kernel<<<((size_t)NTOK*PDIM + 255)/256, 256>>>(images, tok);
    ln_kernel<<<NTOK, 256>>>(tok, pe_ln1_w, pe_ln1_b, nullptr, lth, ltl, PDIM);
    launch_bg(lth, ltl, PDIM, wh + OFF_PE, wl + OFF_PE, PDIM, 0, pe_b,
              nullptr, 0, t, nullptr, nullptr, DIM, 0, DIM, PDIM, 0, 1, 1);
    ln_kernel<<<NTOK, 256>>>(t, pe_ln2_w, pe_ln2_b, t, nullptr, nullptr, DIM);
    posmask_kernel<<<NTOK, DIM>>>(t, pos_h, pos_w);

    // ---- transformer layers ----
    for (int l = 0; l < NDEPTH; l++){
        ln_kernel<<<NTOK, 256>>>(t, attn_ln + l*DIM, nullptr, nullptr, xnh, xnl, DIM);
        launch_bg(xnh, xnl, DIM, wh + OFF_QKV + (size_t)l*DIM*DIM, wl + OFF_QKV + (size_t)l*DIM*DIM,
                  DIM, 1572864L, nullptr, nullptr, 0,
                  qkv, nullptr, nullptr, DIM, (long)NTOK*DIM, DIM, DIM, 0, 3, 1);
        flash_kernel<<<dim3(8, BB*HEADS), 256, FSMEM>>>(q, k, v, qn + l*DH, kn + l*DH, oh, ol);
        launch_bg(oh, ol, DIM, wh + OFF_WO + (size_t)l*DIM*DIM, wl + OFF_WO + (size_t)l*DIM*DIM,
                  DIM, 0, nullptr, t, DIM, t, nullptr, nullptr, DIM, 0, DIM, DIM, 0, 1, 1);
        ln_kernel<<<NTOK, 256>>>(t, ff_ln + l*DIM, nullptr, nullptr, xnh, xnl, DIM);
        launch_bg(xnh, xnl, DIM, wh + OFF_FF1 + (size_t)l*MLPD*DIM, wl + OFF_FF1 + (size_t)l*MLPD*DIM,
                  DIM, 0, ff_b1 + l*MLPD, nullptr, 0,
                  nullptr, mlph, mlpl, MLPD, 0, MLPD, DIM, 1, 1, 1);
        launch_bg(mlph, mlpl, MLPD, wh + OFF_FF2 + (size_t)l*DIM*MLPD, wl + OFF_FF2 + (size_t)l*DIM*MLPD,
                  MLPD, 0, ff_b2 + l*DIM, t, DIM, t, nullptr, nullptr, DIM, 0, DIM, MLPD, 0, 1, 1);
    }

    // ---- final LN + pooling ----
    ln_kernel<<<NTOK, 256>>>(t, final_ln, nullptr, nullptr, xnh, xnl, DIM);
    ln_kernel<<<1, 256>>>(pool_q, pool_ln, nullptr, u, nullptr, nullptr, DIM);
    launch_small(u, DIM, pool_wq, DIM, nullptr, qp, DIM, 1, DIM, DIM);
    head_ln_kernel<<<1, 256>>>(qp, pool_qn, HEADS);
    launch_bg(xnh, xnl, DIM, wh + OFF_PK, wl + OFF_PK, DIM, 0, nullptr, nullptr, 0,
              k, nullptr, nullptr, DIM, 0, DIM, DIM, 0, 1, 1);
    head_ln_kernel<<<(NTOK*HEADS*32 + 255)/256, 256>>>(k, pool_kn, NTOK*HEADS);
    launch_bg(xnh, xnl, DIM, wh + OFF_PV, wl + OFF_PV, DIM, 0, nullptr, nullptr, 0,
              v, nullptr, nullptr, DIM, 0, DIM, DIM, 0, 1, 1);
    pool_attn_kernel<<<dim3(HEADS, BB), 256>>>(qp, k, v, po);
    launch_small(po, DIM, pool_wo, DIM, nullptr, pooled, DIM, BB, DIM, DIM);
    ln_kernel<<<BB, 256>>>(pooled, head_ln, nullptr, hn, nullptr, nullptr, DIM);
    launch_small(hn, DIM, head_w, DIM, nullptr, out, NC, BB, NC, DIM);
}

// round 6
// speedup vs baseline: 6.4113x; 1.0162x over previous
#include <cuda_runtime.h>
#include <cuda_bf16.h>
#include <math.h>
#include <stdint.h>

#define BB 8
#define LMAX 1024
#define DIM 512
#define HEADS 8
#define DH 64
#define NDEPTH 6
#define MLPD 2048
#define NC 1000
#define PDIM 768
#define NTOK (BB*LMAX)   // 8192

__constant__ int c_L[8]  = {1024, 768, 896, 576, 560, 512, 384, 640};
__constant__ int c_Wp[8] = {  32,  24,  32,  24,  28,  32,  16,  20};

// weight-split buffer offsets (elements)
#define OFF_QKV 0L
#define OFF_WO  4718592L
#define OFF_FF1 6291456L
#define OFF_FF2 12582912L
#define OFF_PE  18874368L
#define OFF_PK  19267584L
#define OFF_PV  19529728L
#define WTOT    19791872L

// ---------------- scratch ----------------
__device__ __align__(128) float g_tok[(size_t)NTOK*PDIM];
__device__ __align__(128) float g_t  [(size_t)NTOK*DIM];
__device__ __align__(128) float g_qkv[(size_t)3*NTOK*DIM];
__device__ __align__(128) float g_u  [DIM];
__device__ __align__(128) float g_qp [DIM];
__device__ __align__(128) float g_po [BB*DIM];
__device__ __align__(128) float g_pooled[BB*DIM];
__device__ __align__(128) float g_hn [BB*DIM];
__device__ __align__(128) __nv_bfloat16 g_wh[WTOT];
__device__ __align__(128) __nv_bfloat16 g_wl[WTOT];
__device__ __align__(128) __nv_bfloat16 g_lth[(size_t)NTOK*PDIM];
__device__ __align__(128) __nv_bfloat16 g_ltl[(size_t)NTOK*PDIM];
__device__ __align__(128) __nv_bfloat16 g_xnh[(size_t)NTOK*DIM];
__device__ __align__(128) __nv_bfloat16 g_xnl[(size_t)NTOK*DIM];
__device__ __align__(128) __nv_bfloat16 g_mlph[(size_t)NTOK*MLPD];
__device__ __align__(128) __nv_bfloat16 g_mlpl[(size_t)NTOK*MLPD];
__device__ __align__(128) __nv_bfloat16 g_oh[(size_t)NTOK*DIM];
__device__ __align__(128) __nv_bfloat16 g_ol[(size_t)NTOK*DIM];
__device__ __align__(128) __nv_bfloat16 g_qh2[(size_t)NTOK*DIM];
__device__ __align__(128) __nv_bfloat16 g_ql2[(size_t)NTOK*DIM];
__device__ __align__(128) __nv_bfloat16 g_kh2[(size_t)NTOK*DIM];
__device__ __align__(128) __nv_bfloat16 g_kl2[(size_t)NTOK*DIM];
__device__ __align__(128) __nv_bfloat16 g_vh2[(size_t)NTOK*DIM];
__device__ __align__(128) __nv_bfloat16 g_vl2[(size_t)NTOK*DIM];

// ================= helpers =================
__device__ __forceinline__ uint32_t smem_u32(const void* p){
    uint32_t a; asm("{ .reg .u64 t; cvta.to.shared.u64 t, %1; cvt.u32.u64 %0, t; }" : "=r"(a) : "l"(p));
    return a;
}
__device__ __forceinline__ void ldsm_x4(uint32_t* r, uint32_t addr){
    asm volatile("ldmatrix.sync.aligned.m8n8.x4.shared.b16 {%0,%1,%2,%3}, [%4];"
        : "=r"(r[0]),"=r"(r[1]),"=r"(r[2]),"=r"(r[3]) : "r"(addr));
}
__device__ __forceinline__ void ldsm_x2(uint32_t* r, uint32_t addr){
    asm volatile("ldmatrix.sync.aligned.m8n8.x2.shared.b16 {%0,%1}, [%2];"
        : "=r"(r[0]),"=r"(r[1]) : "r"(addr));
}
__device__ __forceinline__ void ldsm_x2t(uint32_t* r, uint32_t addr){
    asm volatile("ldmatrix.sync.aligned.m8n8.x2.trans.shared.b16 {%0,%1}, [%2];"
        : "=r"(r[0]),"=r"(r[1]) : "r"(addr));
}
__device__ __forceinline__ void mma16816(float* c, const uint32_t* a, const uint32_t* b){
    asm volatile("mma.sync.aligned.m16n8k16.row.col.f32.bf16.bf16.f32 "
        "{%0,%1,%2,%3}, {%4,%5,%6,%7}, {%8,%9}, {%0,%1,%2,%3};"
        : "+f"(c[0]),"+f"(c[1]),"+f"(c[2]),"+f"(c[3])
        : "r"(a[0]),"r"(a[1]),"r"(a[2]),"r"(a[3]), "r"(b[0]),"r"(b[1]));
}
__device__ __forceinline__ void cp_async16(uint32_t dst, const void* src){
    asm volatile("cp.async.cg.shared.global [%0], [%1], 16;" :: "r"(dst), "l"(src) : "memory");
}
__device__ __forceinline__ void cp_commit(){ asm volatile("cp.async.commit_group;" ::: "memory"); }
template<int N> __device__ __forceinline__ void cp_wait(){
    asm volatile("cp.async.wait_group %0;" :: "n"(N) : "memory");
}
__device__ __forceinline__ uint32_t bf2u(__nv_bfloat162 v){ return *reinterpret_cast<uint32_t*>(&v); }
__device__ __forceinline__ uint32_t packbf(float a, float b){
    return bf2u(__float22bfloat162_rn(make_float2(a, b)));
}
__device__ __forceinline__ void cvt8(float4 a, float4 b, uint4& hi, uint4& lo){
    __nv_bfloat162 h0 = __float22bfloat162_rn(make_float2(a.x, a.y));
    __nv_bfloat162 h1 = __float22bfloat162_rn(make_float2(a.z, a.w));
    __nv_bfloat162 h2 = __float22bfloat162_rn(make_float2(b.x, b.y));
    __nv_bfloat162 h3 = __float22bfloat162_rn(make_float2(b.z, b.w));
    float2 f0 = __bfloat1622float2(h0), f1 = __bfloat1622float2(h1);
    float2 f2 = __bfloat1622float2(h2), f3 = __bfloat1622float2(h3);
    __nv_bfloat162 l0 = __float22bfloat162_rn(make_float2(a.x - f0.x, a.y - f0.y));
    __nv_bfloat162 l1 = __float22bfloat162_rn(make_float2(a.z - f1.x, a.w - f1.y));
    __nv_bfloat162 l2 = __float22bfloat162_rn(make_float2(b.x - f2.x, b.y - f2.y));
    __nv_bfloat162 l3 = __float22bfloat162_rn(make_float2(b.z - f3.x, b.w - f3.y));
    hi = make_uint4(bf2u(h0), bf2u(h1), bf2u(h2), bf2u(h3));
    lo = make_uint4(bf2u(l0), bf2u(l1), bf2u(l2), bf2u(l3));
}

// ---------------- f32 -> hi/lo bf16 split ----------------
__global__ void split_kernel(const float* __restrict__ src, __nv_bfloat16* __restrict__ h,
                             __nv_bfloat16* __restrict__ l, int n){
    int i = blockIdx.x*blockDim.x + threadIdx.x;
    if (i >= n) return;
    float v = src[i];
    __nv_bfloat16 hv = __float2bfloat16(v);
    h[i] = hv;
    l[i] = __float2bfloat16(v - __bfloat162float(hv));
}

// ============== cp.async HMMA GEMM NT on pre-split bf16 ==============
#define BTILE (128*144)          // 18432
#define B_AH 0
#define B_AL BTILE
#define B_WH (2*BTILE)
#define B_WL (3*BTILE)
#define B_BUF (4*BTILE)          // 73728
#define B_SMEM (2*B_BUF)         // 147456

__global__ __launch_bounds__(256) void bgemm_nt(
    const __nv_bfloat16* __restrict__ Ah, const __nv_bfloat16* __restrict__ Al, int lda,
    const __nv_bfloat16* __restrict__ Wh, const __nv_bfloat16* __restrict__ Wl, int ldw, long wz,
    const float* __restrict__ bias,
    const float* __restrict__ R, int ldr,
    float* __restrict__ C, __nv_bfloat16* __restrict__ Ch, __nv_bfloat16* __restrict__ Cl,
    int ldc, long cz,
    int K, int act, int tokrows)
{
    extern __shared__ char smem[];
    uint32_t sb = smem_u32(smem);
    int tid = threadIdx.x, lane = tid & 31, wid = tid >> 5;
    int z = blockIdx.z;
    Wh += (size_t)z*wz; Wl += (size_t)z*wz;
    if (C)  C  += (size_t)z*cz;
    int bm = blockIdx.y*128, bn = blockIdx.x*128;
    if (tokrows && (bm & 1023) >= c_L[bm >> 10]) return;
    int wr = (wid & 1)*64;
    int wn = (wid >> 1)*32;

    float acc[4][4][4];
    #pragma unroll
    for (int i = 0; i < 4; i++)
        #pragma unroll
        for (int j = 0; j < 4; j++)
            #pragma unroll
            for (int p = 0; p < 4; p++) acc[i][j][p] = 0.f;

#define BSTAGE(KC, BUFB) do { \
    _Pragma("unroll") \
    for (int it = 0; it < 4; it++){ \
        int slot = it*256 + tid; int row = slot >> 3, seg = slot & 7; \
        uint32_t so = (uint32_t)(BUFB) + (uint32_t)(row*144 + seg*16); \
        cp_async16(sb + B_AH + so, Ah + (size_t)(bm + row)*lda + (KC)*64 + seg*8); \
        cp_async16(sb + B_AL + so, Al + (size_t)(bm + row)*lda + (KC)*64 + seg*8); \
        cp_async16(sb + B_WH + so, Wh + (size_t)(bn + row)*ldw + (KC)*64 + seg*8); \
        cp_async16(sb + B_WL + so, Wl + (size_t)(bn + row)*ldw + (KC)*64 + seg*8); \
    } } while(0)

    int nk = K >> 6;
    BSTAGE(0, 0);
    cp_commit();

    int grp = lane >> 3, wi = lane & 7;
    for (int kc = 0; kc < nk; kc++){
        if (kc + 1 < nk){
            BSTAGE(kc + 1, ((kc + 1) & 1)*B_BUF);
            cp_commit();
            cp_wait<1>();
        } else {
            cp_wait<0>();
        }
        __syncthreads();
        uint32_t cur = (uint32_t)((kc & 1)*B_BUF);
        #pragma unroll
        for (int ks = 0; ks < 4; ks++){
            uint32_t a_hi[4][4], a_lo[4][4];
            #pragma unroll
            for (int mi = 0; mi < 4; mi++){
                uint32_t off = (uint32_t)((wr + mi*16 + wi + (grp & 1)*8)*144
                                          + (ks*16 + (grp >> 1)*8)*2);
                ldsm_x4(a_hi[mi], sb + B_AH + cur + off);
                ldsm_x4(a_lo[mi], sb + B_AL + cur + off);
            }
            uint32_t b_hi[4][2], b_lo[4][2];
            #pragma unroll
            for (int ni = 0; ni < 4; ni++){
                uint32_t off = (uint32_t)((wn + ni*8 + (lane & 7))*144
                                          + (ks*16 + ((lane >> 3) & 1)*8)*2);
                ldsm_x2(b_hi[ni], sb + B_WH + cur + off);
                ldsm_x2(b_lo[ni], sb + B_WL + cur + off);
            }
            #pragma unroll
            for (int mi = 0; mi < 4; mi++)
                #pragma unroll
                for (int ni = 0; ni < 4; ni++){
                    mma16816(acc[mi][ni], a_hi[mi], b_hi[ni]);
                    mma16816(acc[mi][ni], a_hi[mi], b_lo[ni]);
                    mma16816(acc[mi][ni], a_lo[mi], b_hi[ni]);
                }
        }
        __syncthreads();
    }
#undef BSTAGE

    // ---- epilogue ----
    #pragma unroll
    for (int mi = 0; mi < 4; mi++){
        #pragma unroll
        for (int ni = 0; ni < 4; ni++){
            int gn = bn + wn + ni*8 + (lane & 3)*2;
            #pragma unroll
            for (int hh = 0; hh < 2; hh++){
                int m = bm + wr + mi*16 + (lane >> 2) + hh*8;
                float v0 = acc[mi][ni][hh*2 + 0];
                float v1 = acc[mi][ni][hh*2 + 1];
                if (bias){ v0 += bias[gn]; v1 += bias[gn + 1]; }
                if (act){
                    v0 = 0.5f*v0*(1.f + erff(v0*0.70710678118654752f));
                    v1 = 0.5f*v1*(1.f + erff(v1*0.70710678118654752f));
                }
                if (Ch){
                    uint32_t hp = packbf(v0, v1);
                    float2 hf = __bfloat1622float2(*reinterpret_cast<__nv_bfloat162*>(&hp));
                    uint32_t lp = packbf(v0 - hf.x, v1 - hf.y);
                    *(uint32_t*)(Ch + (size_t)m*ldc + gn) = hp;
                    *(uint32_t*)(Cl + (size_t)m*ldc + gn) = lp;
                } else {
                    if (R){
                        const float* rp = R + (size_t)m*ldr + gn;
                        v0 += rp[0]; v1 += rp[1];
                    }
                    *(float2*)(C + (size_t)m*ldc + gn) = make_float2(v0, v1);
                }
            }
        }
    }
}

// ============== kvprep: head-LN(Q x 1/8, K) + split QKV to bf16 hi/lo ==============
__global__ void kvprep_kernel(const float* __restrict__ qkv,
    const float* __restrict__ qn, const float* __restrict__ kn,
    __nv_bfloat16* __restrict__ qh, __nv_bfloat16* __restrict__ ql,
    __nv_bfloat16* __restrict__ kh, __nv_bfloat16* __restrict__ kl,
    __nv_bfloat16* __restrict__ vh, __nv_bfloat16* __restrict__ vl)
{
    int g = blockIdx.x*blockDim.x + threadIdx.x;   // NTOK*HEADS*8
    int seg = g & 7;
    int r = g >> 3;
    int tokn = r >> 3, h = r & 7;
    int b = tokn >> 10, l = tokn & 1023;
    if (l >= c_L[b]) return;
    size_t base = (size_t)tokn*DIM + h*64 + seg*8;

#define LN8(x, y, wvec, scale) do { \
    float sum = x.x + x.y + x.z + x.w + y.x + y.y + y.z + y.w; \
    sum += __shfl_xor_sync(0xffffffffu, sum, 1); \
    sum += __shfl_xor_sync(0xffffffffu, sum, 2); \
    sum += __shfl_xor_sync(0xffffffffu, sum, 4); \
    float mu = sum * (1.f/64.f); \
    x.x -= mu; x.y -= mu; x.z -= mu; x.w -= mu; \
    y.x -= mu; y.y -= mu; y.z -= mu; y.w -= mu; \
    float ss = x.x*x.x + x.y*x.y + x.z*x.z + x.w*x.w \
             + y.x*y.x + y.y*y.y + y.z*y.z + y.w*y.w; \
    ss += __shfl_xor_sync(0xffffffffu, ss, 1); \
    ss += __shfl_xor_sync(0xffffffffu, ss, 2); \
    ss += __shfl_xor_sync(0xffffffffu, ss, 4); \
    float rs = rsqrtf(ss * (1.f/64.f) + 1e-5f) * (scale); \
    float4 w0 = *(const float4*)((wvec) + seg*8); \
    float4 w1 = *(const float4*)((wvec) + seg*8 + 4); \
    x.x *= rs*w0.x; x.y *= rs*w0.y; x.z *= rs*w0.z; x.w *= rs*w0.w; \
    y.x *= rs*w1.x; y.y *= rs*w1.y; y.z *= rs*w1.z; y.w *= rs*w1.w; \
} while(0)

    uint4 hi, lo;
    {   // Q
        const float* p = qkv + base;
        float4 x = *(const float4*)p, y = *(const float4*)(p + 4);
        LN8(x, y, qn, 0.125f);
        cvt8(x, y, hi, lo);
        *(uint4*)(qh + base) = hi; *(uint4*)(ql + base) = lo;
    }
    {   // K
        const float* p = qkv + (size_t)NTOK*DIM + base;
        float4 x = *(const float4*)p, y = *(const float4*)(p + 4);
        LN8(x, y, kn, 1.f);
        cvt8(x, y, hi, lo);
        *(uint4*)(kh + base) = hi; *(uint4*)(kl + base) = lo;
    }
    {   // V (no LN)
        const float* p = qkv + (size_t)2*NTOK*DIM + base;
        cvt8(*(const float4*)p, *(const float4*)(p + 4), hi, lo);
        *(uint4*)(vh + base) = hi; *(uint4*)(vl + base) = lo;
    }
#undef LN8
}

// ============== flash attention v2: pre-split inputs, cp.async double-buffered K/V ==============
#define FQH 0
#define FQL 18432
#define FKV0 36864
#define FKVS 73728                       // per-stage: KH+0, KL+18432, VH+36864, VL+55296
#define FSMEM (36864 + 2*73728)          // 184320

__global__ __launch_bounds__(256) void flash_kernel(
    const __nv_bfloat16* __restrict__ Qh, const __nv_bfloat16* __restrict__ Ql,
    const __nv_bfloat16* __restrict__ Kh, const __nv_bfloat16* __restrict__ Kl,
    const __nv_bfloat16* __restrict__ Vh, const __nv_bfloat16* __restrict__ Vl,
    __nv_bfloat16* __restrict__ Oh, __nv_bfloat16* __restrict__ Ol)
{
    extern __shared__ char smem[];
    uint32_t sb = smem_u32(smem);
    int tid = threadIdx.x, lane = tid & 31, wid = tid >> 5;
    int qt = blockIdx.x;
    int bh = blockIdx.y;
    int b = bh >> 3, h = bh & 7;
    int L = c_L[b];
    if (qt*128 >= L) return;
    int ktiles = (L + 127) >> 7;

    // ---- stage Q (cp.async, group 1) ----
    #pragma unroll
    for (int it = 0; it < 4; it++){
        int slot = it*256 + tid; int row = slot >> 3, seg = slot & 7;
        size_t go = (size_t)(b*1024 + qt*128 + row)*DIM + h*64 + seg*8;
        uint32_t so = (uint32_t)(row*144 + seg*16);
        cp_async16(sb + FQH + so, Qh + go);
        cp_async16(sb + FQL + so, Ql + go);
    }
    cp_commit();

#define KVSTAGE(KT, SBASE) do { \
    _Pragma("unroll") \
    for (int it = 0; it < 4; it++){ \
        int slot = it*256 + tid; int row = slot >> 3, seg = slot & 7; \
        size_t go = (size_t)(b*1024 + (KT)*128 + row)*DIM + h*64 + seg*8; \
        uint32_t so = (uint32_t)(SBASE) + (uint32_t)(row*144 + seg*16); \
        cp_async16(sb + so,         Kh + go); \
        cp_async16(sb + so + 18432, Kl + go); \
        cp_async16(sb + so + 36864, Vh + go); \
        cp_async16(sb + so + 55296, Vl + go); \
    } } while(0)

    KVSTAGE(0, FKV0);
    cp_commit();

    cp_wait<1>();          // Q complete (KV0 may still be in flight)
    __syncthreads();

    int wr = wid*16;
    int grp = lane >> 3, wi = lane & 7;
    uint32_t aqh[4][4], aql[4][4];
    #pragma unroll
    for (int ks = 0; ks < 4; ks++){
        uint32_t off = (uint32_t)((wr + wi + (grp & 1)*8)*144 + (ks*16 + (grp >> 1)*8)*2);
        ldsm_x4(aqh[ks], sb + FQH + off);
        ldsm_x4(aql[ks], sb + FQL + off);
    }

    float m0 = -1e30f, m1 = -1e30f, l0 = 0.f, l1 = 0.f;
    float ao[8][4];
    #pragma unroll
    for (int i = 0; i < 8; i++)
        #pragma unroll
        for (int p = 0; p < 4; p++) ao[i][p] = 0.f;

    for (int kt = 0; kt < ktiles; kt++){
        if (kt + 1 < ktiles){
            KVSTAGE(kt + 1, FKV0 + ((kt + 1) & 1)*FKVS);
            cp_commit();
            cp_wait<1>();
        } else {
            cp_wait<0>();
        }
        __syncthreads();
        uint32_t kb = (uint32_t)(FKV0 + (kt & 1)*FKVS);

        // ---- S = Q K^T ----
        float s[16][4];
        #pragma unroll
        for (int i = 0; i < 16; i++)
            #pragma unroll
            for (int p = 0; p < 4; p++) s[i][p] = 0.f;
        #pragma unroll
        for (int ks = 0; ks < 4; ks++){
            #pragma unroll
            for (int ni = 0; ni < 16; ni++){
                uint32_t off = (uint32_t)((ni*8 + wi)*144 + (ks*16 + (grp & 1)*8)*2);
                uint32_t bh_[2], bl_[2];
                ldsm_x2(bh_, sb + kb + off);
                ldsm_x2(bl_, sb + kb + 18432 + off);
                mma16816(s[ni], aqh[ks], bh_);
                mma16816(s[ni], aqh[ks], bl_);
                mma16816(s[ni], aql[ks], bh_);
            }
        }

        // ---- mask (partial tile only) ----
        if (kt == ktiles - 1 && (L & 127)){
            int kbase = kt*128 + 2*(lane & 3);
            #pragma unroll
            for (int ni = 0; ni < 16; ni++){
                int kg = kbase + ni*8;
                if (kg     >= L){ s[ni][0] = -1e9f; s[ni][2] = -1e9f; }
                if (kg + 1 >= L){ s[ni][1] = -1e9f; s[ni][3] = -1e9f; }
            }
        }

        // ---- online softmax ----
        float tm0 = -1e30f, tm1 = -1e30f;
        #pragma unroll
        for (int ni = 0; ni < 16; ni++){
            tm0 = fmaxf(tm0, fmaxf(s[ni][0], s[ni][1]));
            tm1 = fmaxf(tm1, fmaxf(s[ni][2], s[ni][3]));
        }
        tm0 = fmaxf(tm0, __shfl_xor_sync(0xffffffffu, tm0, 1));
        tm0 = fmaxf(tm0, __shfl_xor_sync(0xffffffffu, tm0, 2));
        tm1 = fmaxf(tm1, __shfl_xor_sync(0xffffffffu, tm1, 1));
        tm1 = fmaxf(tm1, __shfl_xor_sync(0xffffffffu, tm1, 2));
        float mn0 = fmaxf(m0, tm0), mn1 = fmaxf(m1, tm1);
        float sc0 = __expf(m0 - mn0), sc1 = __expf(m1 - mn1);
        m0 = mn0; m1 = mn1;
        float ts0 = 0.f, ts1 = 0.f;
        #pragma unroll
        for (int ni = 0; ni < 16; ni++){
            s[ni][0] = __expf(s[ni][0] - m0);
            s[ni][1] = __expf(s[ni][1] - m0);
            s[ni][2] = __expf(s[ni][2] - m1);
            s[ni][3] = __expf(s[ni][3] - m1);
            ts0 += s[ni][0] + s[ni][1];
            ts1 += s[ni][2] + s[ni][3];
        }
        ts0 += __shfl_xor_sync(0xffffffffu, ts0, 1);
        ts0 += __shfl_xor_sync(0xffffffffu, ts0, 2);
        ts1 += __shfl_xor_sync(0xffffffffu, ts1, 1);
        ts1 += __shfl_xor_sync(0xffffffffu, ts1, 2);
        l0 = l0*sc0 + ts0;
        l1 = l1*sc1 + ts1;
        #pragma unroll
        for (int i = 0; i < 8; i++){
            ao[i][0] *= sc0; ao[i][1] *= sc0;
            ao[i][2] *= sc1; ao[i][3] *= sc1;
        }

        // ---- O += P V ----
        #pragma unroll
        for (int kk = 0; kk < 8; kk++){
            float p00 = s[2*kk][0],   p01 = s[2*kk][1],   p02 = s[2*kk][2],   p03 = s[2*kk][3];
            float p10 = s[2*kk+1][0], p11 = s[2*kk+1][1], p12 = s[2*kk+1][2], p13 = s[2*kk+1][3];
            uint32_t aph[4], apl[4];
            aph[0] = packbf(p00, p01); aph[1] = packbf(p02, p03);
            aph[2] = packbf(p10, p11); aph[3] = packbf(p12, p13);
            {
                float2 f0 = __bfloat1622float2(*reinterpret_cast<__nv_bfloat162*>(&aph[0]));
                float2 f1 = __bfloat1622float2(*reinterpret_cast<__nv_bfloat162*>(&aph[1]));
                float2 f2 = __bfloat1622float2(*reinterpret_cast<__nv_bfloat162*>(&aph[2]));
                float2 f3 = __bfloat1622float2(*reinterpret_cast<__nv_bfloat162*>(&aph[3]));
                apl[0] = packbf(p00 - f0.x, p01 - f0.y);
                apl[1] = packbf(p02 - f1.x, p03 - f1.y);
                apl[2] = packbf(p10 - f2.x, p11 - f2.y);
                apl[3] = packbf(p12 - f3.x, p13 - f3.y);
            }
            #pragma unroll
            for (int ni = 0; ni < 8; ni++){
                uint32_t off = (uint32_t)((kk*16 + (lane & 15))*144 + ni*16);
                uint32_t vh_[2], vl_[2];
                ldsm_x2t(vh_, sb + kb + 36864 + off);
                ldsm_x2t(vl_, sb + kb + 55296 + off);
                mma16816(ao[ni], aph, vh_);
                mma16816(ao[ni], apl, vh_);
                mma16816(ao[ni], aph, vl_);
            }
        }
        __syncthreads();
    }
#undef KVSTAGE

    // ---- epilogue: split-bf16 O ----
    float il0 = 1.f / l0, il1 = 1.f / l1;
    int mrow = qt*128 + wr + (lane >> 2);
    #pragma unroll
    for (int ni = 0; ni < 8; ni++){
        int col = h*64 + ni*8 + 2*(lane & 3);
        {
            float a0 = ao[ni][0]*il0, a1 = ao[ni][1]*il0;
            uint32_t hp = packbf(a0, a1);
            float2 hf = __bfloat1622float2(*reinterpret_cast<__nv_bfloat162*>(&hp));
            uint32_t lp = packbf(a0 - hf.x, a1 - hf.y);
            *(uint32_t*)(Oh + (size_t)(b*1024 + mrow)*DIM + col) = hp;
            *(uint32_t*)(Ol + (size_t)(b*1024 + mrow)*DIM + col) = lp;
        }
        {
            float a0 = ao[ni][2]*il1, a1 = ao[ni][3]*il1;
            uint32_t hp = packbf(a0, a1);
            float2 hf = __bfloat1622float2(*reinterpret_cast<__nv_bfloat162*>(&hp));
            uint32_t lp = packbf(a0 - hf.x, a1 - hf.y);
            *(uint32_t*)(Oh + (size_t)(b*1024 + mrow + 8)*DIM + col) = hp;
            *(uint32_t*)(Ol + (size_t)(b*1024 + mrow + 8)*DIM + col) = lp;
        }
    }
}

// ---------------- patch packing ----------------
__global__ void pack_kernel(const float* __restrict__ img, float* __restrict__ tok){
    size_t i = (size_t)blockIdx.x*blockDim.x + threadIdx.x;
    if (i >= (size_t)NTOK*PDIM) return;
    int pd = (int)(i % PDIM);
    size_t bl = i / PDIM;
    int l = (int)(bl % LMAX);
    int b = (int)(bl / LMAX);
    int L = c_L[b], w = c_Wp[b];
    float v = 0.f;
    if (l < L){
        int c  = pd >> 8;
        int r  = pd & 255;
        int py = r >> 4, px = r & 15;
        int ph = l / w, pw = l % w;
        v = img[((size_t)(b*3 + c)*512 + (size_t)(ph*16 + py))*512 + (size_t)(pw*16 + px)];
    }
    tok[i] = v;
}

// ---------------- row LayerNorm; tokskip skips padding rows ----------------
__global__ void ln_kernel(const float* __restrict__ x, const float* __restrict__ w,
                          const float* __restrict__ bb, float* __restrict__ y,
                          __nv_bfloat16* __restrict__ yh, __nv_bfloat16* __restrict__ yl,
                          int D, int tokskip){
    __shared__ float red[8];
    int row = blockIdx.x, tid = threadIdx.x, lane = tid & 31, wp = tid >> 5;
    if (tokskip && (row & 1023) >= c_L[row >> 10]) return;
    const float* xr = x + (size_t)row*D;
    float lv[3]; float s = 0.f;
    #pragma unroll
    for (int i = 0; i < 3; i++){
        int idx = tid + i*256;
        float vv = (idx < D) ? xr[idx] : 0.f;
        lv[i] = vv; s += vv;
    }
    #pragma unroll
    for (int off = 16; off; off >>= 1) s += __shfl_xor_sync(0xffffffffu, s, off);
    if (lane == 0) red[wp] = s;
    __syncthreads();
    float tot = 0.f;
    #pragma unroll
    for (int i = 0; i < 8; i++) tot += red[i];
    float mu = tot / (float)D;
    __syncthreads();
    float vs = 0.f;
    #pragma unroll
    for (int i = 0; i < 3; i++){
        int idx = tid + i*256;
        if (idx < D){ float d = lv[i] - mu; vs += d*d; }
    }
    #pragma unroll
    for (int off = 16; off; off >>= 1) vs += __shfl_xor_sync(0xffffffffu, vs, off);
    if (lane == 0) red[wp] = vs;
    __syncthreads();
    float tv = 0.f;
    #pragma unroll
    for (int i = 0; i < 8; i++) tv += red[i];
    float rs = rsqrtf(tv / (float)D + 1e-5f);
    #pragma unroll
    for (int i = 0; i < 3; i++){
        int idx = tid + i*256;
        if (idx < D){
            float val = (lv[i] - mu)*rs*w[idx];
            if (bb) val += bb[idx];
            if (y) y[(size_t)row*D + idx] = val;
            else {
                __nv_bfloat16 hv = __float2bfloat16(val);
                yh[(size_t)row*D + idx] = hv;
                yl[(size_t)row*D + idx] = __float2bfloat16(val - __bfloat162float(hv));
            }
        }
    }
}

// ---------------- per-head LayerNorm over 64 dims ----------------
__global__ void head_ln_kernel(float* __restrict__ x, const float* __restrict__ w, int rows){
    int gw = (int)(((size_t)blockIdx.x*blockDim.x + threadIdx.x) >> 5);
    int lane = threadIdx.x & 31;
    if (gw >= rows) return;
    float* p = x + (size_t)gw*64;
    float a = p[lane], b = p[lane + 32];
    float s = a + b;
    #pragma unroll
    for (int off = 16; off; off >>= 1) s += __shfl_xor_sync(0xffffffffu, s, off);
    float mu = s * (1.f/64.f);
    float da = a - mu, db = b - mu;
    float vs = da*da + db*db;
    #pragma unroll
    for (int off = 16; off; off >>= 1) vs += __shfl_xor_sync(0xffffffffu, vs, off);
    float rs = rsqrtf(vs * (1.f/64.f) + 1e-5f);
    p[lane]      = da * rs * w[lane];
    p[lane + 32] = db * rs * w[lane + 32];
}

// ---------------- pos embed + mask ----------------
__global__ void posmask_kernel(float* __restrict__ t, const float* __restrict__ ph,
                               const float* __restrict__ pw){
    int bl = blockIdx.x;
    int b = bl >> 10, l = bl & 1023;
    int L = c_L[b], w = c_Wp[b];
    float* r = t + (size_t)bl*DIM;
    int d = threadIdx.x;
    if (l < L) r[d] = r[d] + ph[(size_t)(l / w)*DIM + d] + pw[(size_t)(l % w)*DIM + d];
    else       r[d] = 0.f;
}

// ---------------- f32 SIMT GEMM NT (small M only) ----------------
__global__ __launch_bounds__(256) void gemm_nt_kernel(
    const float* __restrict__ A, int lda,
    const float* __restrict__ W, int ldw,
    const float* __restrict__ bias,
    float* __restrict__ C, int ldc,
    int M, int N, int K)
{
    __shared__ __align__(16) float As[8][128];
    __shared__ __align__(16) float Bs[8][128];
    int bm = blockIdx.y*128, bn = blockIdx.x*128;
    int tid = threadIdx.x;
    int tx = tid & 15, ty = tid >> 4;
    float acc[8][8];
    #pragma unroll
    for (int i = 0; i < 8; i++)
        #pragma unroll
        for (int j = 0; j < 8; j++) acc[i][j] = 0.f;
    int lr = tid >> 1;
    int lk = (tid & 1)*4;
    for (int k0 = 0; k0 < K; k0 += 8){
        float4 av = make_float4(0,0,0,0), bv = make_float4(0,0,0,0);
        if (bm + lr < M) av = *(const float4*)(A + (size_t)(bm + lr)*lda + k0 + lk);
        if (bn + lr < N) bv = *(const float4*)(W + (size_t)(bn + lr)*ldw + k0 + lk);
        As[lk+0][lr] = av.x; As[lk+1][lr] = av.y; As[lk+2][lr] = av.z; As[lk+3][lr] = av.w;
        Bs[lk+0][lr] = bv.x; Bs[lk+1][lr] = bv.y; Bs[lk+2][lr] = bv.z; Bs[lk+3][lr] = bv.w;
        __syncthreads();
        #pragma unroll
        for (int kk = 0; kk < 8; kk++){
            float a[8], b[8];
            #pragma unroll
            for (int i = 0; i < 8; i++) a[i] = As[kk][ty*8 + i];
            #pragma unroll
            for (int j = 0; j < 8; j++) b[j] = Bs[kk][tx*8 + j];
            #pragma unroll
            for (int i = 0; i < 8; i++)
                #pragma unroll
                for (int j = 0; j < 8; j++) acc[i][j] = fmaf(a[i], b[j], acc[i][j]);
        }
        __syncthreads();
    }
    #pragma unroll
    for (int i = 0; i < 8; i++){
        int m = bm + ty*8 + i;
        if (m >= M) continue;
        #pragma unroll
        for (int j = 0; j < 8; j++){
            int n = bn + tx*8 + j;
            if (n >= N) continue;
            float v = acc[i][j];
            if (bias) v += bias[n];
            C[(size_t)m*ldc + n] = v;
        }
    }
}

// ---------------- pooling attention (Lq=1) ----------------
__global__ void pool_attn_kernel(const float* __restrict__ qhat, const float* __restrict__ K,
                                 const float* __restrict__ V, float* __restrict__ O){
    int h = blockIdx.x, b = blockIdx.y;
    __shared__ float sq[64];
    __shared__ float sa[1024];
    __shared__ float red[8], red2[8];
    __shared__ float racc[4][64];
    int tid = threadIdx.x, lane = tid & 31, wp = tid >> 5;
    if (tid < 64) sq[tid] = qhat[h*64 + tid];
    __syncthreads();
    int L = c_L[b];
    for (int kk = tid; kk < 1024; kk += 256){
        float dot = -1e9f;
        if (kk < L){
            const float* kr = K + ((size_t)(b*1024 + kk))*DIM + h*64;
            float ss = 0.f;
            #pragma unroll
            for (int d = 0; d < 64; d++) ss += sq[d]*kr[d];
            dot = ss*0.125f;
        }
        sa[kk] = dot;
    }
    __syncthreads();
    float m = -1e30f;
    for (int kk = tid; kk < 1024; kk += 256) m = fmaxf(m, sa[kk]);
    #pragma unroll
    for (int off = 16; off; off >>= 1) m = fmaxf(m, __shfl_xor_sync(0xffffffffu, m, off));
    if (lane == 0) red[wp] = m;
    __syncthreads();
    float bm = -1e30f;
    #pragma unroll
    for (int i = 0; i < 8; i++) bm = fmaxf(bm, red[i]);
    float sum = 0.f;
    for (int kk = tid; kk < 1024; kk += 256){
        float e = __expf(sa[kk] - bm);
        sa[kk] = e; sum += e;
    }
    #pragma unroll
    for (int off = 16; off; off >>= 1) sum += __shfl_xor_sync(0xffffffffu, sum, off);
    if (lane == 0) red2[wp] = sum;
    __syncthreads();
    float bs = 0.f;
    #pragma unroll
    for (int i = 0; i < 8; i++) bs += red2[i];
    float inv = 1.f / bs;
    int dd = tid & 63, part = tid >> 6;
    float acc = 0.f;
    for (int kk = part; kk < 1024; kk += 4)
        acc += sa[kk] * V[((size_t)(b*1024 + kk))*DIM + h*64 + dd];
    racc[part][dd] = acc;
    __syncthreads();
    if (part == 0)
        O[b*DIM + h*64 + dd] = (racc[0][dd] + racc[1][dd] + racc[2][dd] + racc[3][dd]) * inv;
}

// ---------------- host helpers ----------------
static void launch_split(const float* src, __nv_bfloat16* h, __nv_bfloat16* l, long n){
    split_kernel<<<(int)((n + 255)/256), 256>>>(src, h, l, (int)n);
}
static void launch_bg(const __nv_bfloat16* Ah, const __nv_bfloat16* Al, int lda,
                      const __nv_bfloat16* Wh, const __nv_bfloat16* Wl, int ldw, long wz,
                      const float* bias, const float* R, int ldr,
                      float* C, __nv_bfloat16* Ch, __nv_bfloat16* Cl, int ldc, long cz,
                      int N, int K, int act, int nz, int tokrows){
    dim3 g(N/128, NTOK/128, nz);
    bgemm_nt<<<g, 256, B_SMEM>>>(Ah, Al, lda, Wh, Wl, ldw, wz, bias, R, ldr,
                                 C, Ch, Cl, ldc, cz, K, act, tokrows);
}
static void launch_small(const float* A, int lda, const float* W, int ldw,
                         const float* bias, float* C, int ldc, int M, int N, int K){
    dim3 g((N + 127)/128, (M + 127)/128, 1);
    gemm_nt_kernel<<<g, 256>>>(A, lda, W, ldw, bias, C, ldc, M, N, K);
}

extern "C" void kernel_launch(void* const* d_in, const int* in_sizes, int n_in,
                              void* d_out, int out_size){
    const float* images   = (const float*)d_in[0];
    const float* pe_ln1_w = (const float*)d_in[1];
    const float* pe_ln1_b = (const float*)d_in[2];
    const float* pe_w     = (const float*)d_in[3];
    const float* pe_b     = (const float*)d_in[4];
    const float* pe_ln2_w = (const float*)d_in[5];
    const float* pe_ln2_b = (const float*)d_in[6];
    const float* pos_h    = (const float*)d_in[7];
    const float* pos_w    = (const float*)d_in[8];
    const float* attn_ln  = (const float*)d_in[9];
    const float* wq       = (const float*)d_in[10];
    const float* wk       = (const float*)d_in[11];
    const float* wv       = (const float*)d_in[12];
    const float* qn       = (const float*)d_in[13];
    const float* kn       = (const float*)d_in[14];
    const float* wo       = (const float*)d_in[15];
    const float* ff_ln    = (const float*)d_in[16];
    const float* ff_w1    = (const float*)d_in[17];
    const float* ff_b1    = (const float*)d_in[18];
    const float* ff_w2    = (const float*)d_in[19];
    const float* ff_b2    = (const float*)d_in[20];
    const float* final_ln = (const float*)d_in[21];
    const float* pool_q   = (const float*)d_in[22];
    const float* pool_ln  = (const float*)d_in[23];
    const float* pool_wq  = (const float*)d_in[24];
    const float* pool_wk  = (const float*)d_in[25];
    const float* pool_wv  = (const float*)d_in[26];
    const float* pool_qn  = (const float*)d_in[27];
    const float* pool_kn  = (const float*)d_in[28];
    const float* pool_wo  = (const float*)d_in[29];
    const float* head_ln  = (const float*)d_in[30];
    const float* head_w   = (const float*)d_in[31];
    float* out = (float*)d_out;

    cudaFuncSetAttribute(bgemm_nt, cudaFuncAttributeMaxDynamicSharedMemorySize, B_SMEM);
    cudaFuncSetAttribute(flash_kernel, cudaFuncAttributeMaxDynamicSharedMemorySize, FSMEM);

    float *tok,*t,*qkv,*u,*qp,*po,*pooled,*hn;
    __nv_bfloat16 *wh,*wl,*lth,*ltl,*xnh,*xnl,*mlph,*mlpl,*oh,*ol;
    __nv_bfloat16 *qh,*ql,*kh,*kl,*vh,*vl;
    cudaGetSymbolAddress((void**)&tok, g_tok);
    cudaGetSymbolAddress((void**)&t,   g_t);
    cudaGetSymbolAddress((void**)&qkv, g_qkv);
    cudaGetSymbolAddress((void**)&u,   g_u);
    cudaGetSymbolAddress((void**)&qp,  g_qp);
    cudaGetSymbolAddress((void**)&po,  g_po);
    cudaGetSymbolAddress((void**)&pooled, g_pooled);
    cudaGetSymbolAddress((void**)&hn,  g_hn);
    cudaGetSymbolAddress((void**)&wh,  g_wh);
    cudaGetSymbolAddress((void**)&wl,  g_wl);
    cudaGetSymbolAddress((void**)&lth, g_lth);
    cudaGetSymbolAddress((void**)&ltl, g_ltl);
    cudaGetSymbolAddress((void**)&xnh, g_xnh);
    cudaGetSymbolAddress((void**)&xnl, g_xnl);
    cudaGetSymbolAddress((void**)&mlph, g_mlph);
    cudaGetSymbolAddress((void**)&mlpl, g_mlpl);
    cudaGetSymbolAddress((void**)&oh,  g_oh);
    cudaGetSymbolAddress((void**)&ol,  g_ol);
    cudaGetSymbolAddress((void**)&qh,  g_qh2);
    cudaGetSymbolAddress((void**)&ql,  g_ql2);
    cudaGetSymbolAddress((void**)&kh,  g_kh2);
    cudaGetSymbolAddress((void**)&kl,  g_kl2);
    cudaGetSymbolAddress((void**)&vh,  g_vh2);
    cudaGetSymbolAddress((void**)&vl,  g_vl2);

    float* kf = qkv + (size_t)NTOK*DIM;
    float* vf = qkv + (size_t)2*NTOK*DIM;

    // ---- weight split (once per launch) ----
    launch_split(wq, wh + OFF_QKV,             wl + OFF_QKV,             6L*DIM*DIM);
    launch_split(wk, wh + OFF_QKV + 1572864L,  wl + OFF_QKV + 1572864L,  6L*DIM*DIM);
    launch_split(wv, wh + OFF_QKV + 3145728L,  wl + OFF_QKV + 3145728L,  6L*DIM*DIM);
    launch_split(wo, wh + OFF_WO,  wl + OFF_WO,  6L*DIM*DIM);
    launch_split(ff_w1, wh + OFF_FF1, wl + OFF_FF1, 6L*MLPD*DIM);
    launch_split(ff_w2, wh + OFF_FF2, wl + OFF_FF2, 6L*DIM*MLPD);
    launch_split(pe_w, wh + OFF_PE, wl + OFF_PE, (long)DIM*PDIM);
    launch_split(pool_wk, wh + OFF_PK, wl + OFF_PK, (long)DIM*DIM);
    launch_split(pool_wv, wh + OFF_PV, wl + OFF_PV, (long)DIM*DIM);

    // ---- patch embed ----
    pack_kernel<<<((size_t)NTOK*PDIM + 255)/256, 256>>>(images, tok);
    ln_kernel<<<NTOK, 256>>>(tok, pe_ln1_w, pe_ln1_b, nullptr, lth, ltl, PDIM, 1);
    launch_bg(lth, ltl, PDIM, wh + OFF_PE, wl + OFF_PE, PDIM, 0, pe_b,
              nullptr, 0, t, nullptr, nullptr, DIM, 0, DIM, PDIM, 0, 1, 1);
    ln_kernel<<<NTOK, 256>>>(t, pe_ln2_w, pe_ln2_b, t, nullptr, nullptr, DIM, 1);
    posmask_kernel<<<NTOK, DIM>>>(t, pos_h, pos_w);

    // ---- transformer layers ----
    for (int l = 0; l < NDEPTH; l++){
        ln_kernel<<<NTOK, 256>>>(t, attn_ln + l*DIM, nullptr, nullptr, xnh, xnl, DIM, 1);
        launch_bg(xnh, xnl, DIM, wh + OFF_QKV + (size_t)l*DIM*DIM, wl + OFF_QKV + (size_t)l*DIM*DIM,
                  DIM, 1572864L, nullptr, nullptr, 0,
                  qkv, nullptr, nullptr, DIM, (long)NTOK*DIM, DIM, DIM, 0, 3, 1);
        kvprep_kernel<<<NTOK*HEADS*8/256, 256>>>(qkv, qn + l*DH, kn + l*DH, qh, ql, kh, kl, vh, vl);
        flash_kernel<<<dim3(8, BB*HEADS), 256, FSMEM>>>(qh, ql, kh, kl, vh, vl, oh, ol);
        launch_bg(oh, ol, DIM, wh + OFF_WO + (size_t)l*DIM*DIM, wl + OFF_WO + (size_t)l*DIM*DIM,
                  DIM, 0, nullptr, t, DIM, t, nullptr, nullptr, DIM, 0, DIM, DIM, 0, 1, 1);
        ln_kernel<<<NTOK, 256>>>(t, ff_ln + l*DIM, nullptr, nullptr, xnh, xnl, DIM, 1);
        launch_bg(xnh, xnl, DIM, wh + OFF_FF1 + (size_t)l*MLPD*DIM, wl + OFF_FF1 + (size_t)l*MLPD*DIM,
                  DIM, 0, ff_b1 + l*MLPD, nullptr, 0,
                  nullptr, mlph, mlpl, MLPD, 0, MLPD, DIM, 1, 1, 1);
        launch_bg(mlph, mlpl, MLPD, wh + OFF_FF2 + (size_t)l*DIM*MLPD, wl + OFF_FF2 + (size_t)l*DIM*MLPD,
                  MLPD, 0, ff_b2 + l*DIM, t, DIM, t, nullptr, nullptr, DIM, 0, DIM, MLPD, 0, 1, 1);
    }

    // ---- final LN + pooling ----
    ln_kernel<<<NTOK, 256>>>(t, final_ln, nullptr, nullptr, xnh, xnl, DIM, 1);
    ln_kernel<<<1, 256>>>(pool_q, pool_ln, nullptr, u, nullptr, nullptr, DIM, 0);
    launch_small(u, DIM, pool_wq, DIM, nullptr, qp, DIM, 1, DIM, DIM);
    head_ln_kernel<<<1, 256>>>(qp, pool_qn, HEADS);
    launch_bg(xnh, xnl, DIM, wh + OFF_PK, wl + OFF_PK, DIM, 0, nullptr, nullptr, 0,
              kf, nullptr, nullptr, DIM, 0, DIM, DIM, 0, 1, 1);
    head_ln_kernel<<<(NTOK*HEADS*32 + 255)/256, 256>>>(kf, pool_kn, NTOK*HEADS);
    launch_bg(xnh, xnl, DIM, wh + OFF_PV, wl + OFF_PV, DIM, 0, nullptr, nullptr, 0,
              vf, nullptr, nullptr, DIM, 0, DIM, DIM, 0, 1, 1);
    pool_attn_kernel<<<dim3(HEADS, BB), 256>>>(qp, kf, vf, po);
    launch_small(po, DIM, pool_wo, DIM, nullptr, pooled, DIM, BB, DIM, DIM);
    ln_kernel<<<BB, 256>>>(pooled, head_ln, nullptr, hn, nullptr, nullptr, DIM, 0);
    launch_small(hn, DIM, head_w, DIM, nullptr, out, NC, BB, NC, DIM);
}

// round 7
// speedup vs baseline: 9.0273x; 1.4080x over previous
#include <cuda_runtime.h>
#include <cuda_fp16.h>
#include <math.h>
#include <stdint.h>

#define BB 8
#define LMAX 1024
#define DIM 512
#define HEADS 8
#define DH 64
#define NDEPTH 6
#define MLPD 2048
#define NC 1000
#define PDIM 768
#define NTOK (BB*LMAX)   // 8192

__constant__ int c_L[8]  = {1024, 768, 896, 576, 560, 512, 384, 640};
__constant__ int c_Wp[8] = {  32,  24,  32,  24,  28,  32,  16,  20};

// weight-split buffer offsets (elements)
#define OFF_QKV 0L
#define OFF_WO  4718592L
#define OFF_FF1 6291456L
#define OFF_FF2 12582912L
#define OFF_PE  18874368L
#define OFF_PK  19267584L
#define OFF_PV  19529728L
#define WTOT    19791872L

// ---------------- scratch ----------------
__device__ __align__(128) float g_tok[(size_t)NTOK*PDIM];
__device__ __align__(128) float g_t  [(size_t)NTOK*DIM];
__device__ __align__(128) float g_qkv[(size_t)3*NTOK*DIM];
__device__ __align__(128) float g_u  [DIM];
__device__ __align__(128) float g_qp [DIM];
__device__ __align__(128) float g_po [BB*DIM];
__device__ __align__(128) float g_pooled[BB*DIM];
__device__ __align__(128) float g_hn [BB*DIM];
__device__ __align__(128) __half g_wh[WTOT];
__device__ __align__(128) __half g_wl[WTOT];
__device__ __align__(128) __half g_lt [(size_t)NTOK*PDIM];
__device__ __align__(128) __half g_xn [(size_t)NTOK*DIM];
__device__ __align__(128) __half g_mlp[(size_t)NTOK*MLPD];
__device__ __align__(128) __half g_o  [(size_t)NTOK*DIM];
__device__ __align__(128) __half g_qh2[(size_t)NTOK*DIM];
__device__ __align__(128) __half g_kh2[(size_t)NTOK*DIM];
__device__ __align__(128) __half g_kl2[(size_t)NTOK*DIM];
__device__ __align__(128) __half g_vh2[(size_t)NTOK*DIM];

// ================= helpers =================
__device__ __forceinline__ uint32_t smem_u32(const void* p){
    uint32_t a; asm("{ .reg .u64 t; cvta.to.shared.u64 t, %1; cvt.u32.u64 %0, t; }" : "=r"(a) : "l"(p));
    return a;
}
__device__ __forceinline__ void ldsm_x4(uint32_t* r, uint32_t addr){
    asm volatile("ldmatrix.sync.aligned.m8n8.x4.shared.b16 {%0,%1,%2,%3}, [%4];"
        : "=r"(r[0]),"=r"(r[1]),"=r"(r[2]),"=r"(r[3]) : "r"(addr));
}
__device__ __forceinline__ void ldsm_x2(uint32_t* r, uint32_t addr){
    asm volatile("ldmatrix.sync.aligned.m8n8.x2.shared.b16 {%0,%1}, [%2];"
        : "=r"(r[0]),"=r"(r[1]) : "r"(addr));
}
__device__ __forceinline__ void ldsm_x2t(uint32_t* r, uint32_t addr){
    asm volatile("ldmatrix.sync.aligned.m8n8.x2.trans.shared.b16 {%0,%1}, [%2];"
        : "=r"(r[0]),"=r"(r[1]) : "r"(addr));
}
__device__ __forceinline__ void mma16816(float* c, const uint32_t* a, const uint32_t* b){
    asm volatile("mma.sync.aligned.m16n8k16.row.col.f32.f16.f16.f32 "
        "{%0,%1,%2,%3}, {%4,%5,%6,%7}, {%8,%9}, {%0,%1,%2,%3};"
        : "+f"(c[0]),"+f"(c[1]),"+f"(c[2]),"+f"(c[3])
        : "r"(a[0]),"r"(a[1]),"r"(a[2]),"r"(a[3]), "r"(b[0]),"r"(b[1]));
}
__device__ __forceinline__ void cp_async16(uint32_t dst, const void* src){
    asm volatile("cp.async.cg.shared.global [%0], [%1], 16;" :: "r"(dst), "l"(src) : "memory");
}
__device__ __forceinline__ void cp_commit(){ asm volatile("cp.async.commit_group;" ::: "memory"); }
template<int N> __device__ __forceinline__ void cp_wait(){
    asm volatile("cp.async.wait_group %0;" :: "n"(N) : "memory");
}
__device__ __forceinline__ uint32_t h2u(__half2 v){ return *reinterpret_cast<uint32_t*>(&v); }
__device__ __forceinline__ uint32_t packh(float a, float b){
    return h2u(__float22half2_rn(make_float2(a, b)));
}
// 8 floats -> 8 fp16 (single)
__device__ __forceinline__ uint4 cvt8s(float4 a, float4 b){
    return make_uint4(packh(a.x, a.y), packh(a.z, a.w), packh(b.x, b.y), packh(b.z, b.w));
}

// ---------------- weight f32 -> hi/lo fp16 split ----------------
__global__ void wsplit_kernel(const float* __restrict__ src, __half* __restrict__ h,
                              __half* __restrict__ l, int n){
    int i = blockIdx.x*blockDim.x + threadIdx.x;
    if (i >= n) return;
    float v = src[i];
    __half hv = __float2half_rn(v);
    h[i] = hv;
    l[i] = __float2half_rn(v - __half2float(hv));
}

// ============== cp.async HMMA GEMM NT: C = A @ (Wh+Wl)^T  (A single fp16) ==============
#define BTILE (128*144)          // 18432
#define B_A  0
#define B_WH BTILE
#define B_WL (2*BTILE)
#define B_BUF (3*BTILE)          // 55296
#define B_SMEM (2*B_BUF)         // 110592

__global__ __launch_bounds__(256, 2) void bgemm_nt(
    const __half* __restrict__ A, int lda,
    const __half* __restrict__ Wh, const __half* __restrict__ Wl, int ldw, long wz,
    const float* __restrict__ bias,
    const float* __restrict__ R, int ldr,
    float* __restrict__ C, __half* __restrict__ Ch,
    int ldc, long cz,
    int K, int act, int tokrows)
{
    extern __shared__ char smem[];
    uint32_t sb = smem_u32(smem);
    int tid = threadIdx.x, lane = tid & 31, wid = tid >> 5;
    int z = blockIdx.z;
    Wh += (size_t)z*wz; Wl += (size_t)z*wz;
    if (C)  C  += (size_t)z*cz;
    int bm = blockIdx.y*128, bn = blockIdx.x*128;
    if (tokrows && (bm & 1023) >= c_L[bm >> 10]) return;
    int wr = (wid & 1)*64;
    int wn = (wid >> 1)*32;

    float acc[4][4][4];
    #pragma unroll
    for (int i = 0; i < 4; i++)
        #pragma unroll
        for (int j = 0; j < 4; j++)
            #pragma unroll
            for (int p = 0; p < 4; p++) acc[i][j][p] = 0.f;

#define BSTAGE(KC, BUFB) do { \
    _Pragma("unroll") \
    for (int it = 0; it < 4; it++){ \
        int slot = it*256 + tid; int row = slot >> 3, seg = slot & 7; \
        uint32_t so = (uint32_t)(BUFB) + (uint32_t)(row*144 + seg*16); \
        cp_async16(sb + B_A  + so, A  + (size_t)(bm + row)*lda + (KC)*64 + seg*8); \
        cp_async16(sb + B_WH + so, Wh + (size_t)(bn + row)*ldw + (KC)*64 + seg*8); \
        cp_async16(sb + B_WL + so, Wl + (size_t)(bn + row)*ldw + (KC)*64 + seg*8); \
    } } while(0)

    int nk = K >> 6;
    BSTAGE(0, 0);
    cp_commit();

    int grp = lane >> 3, wi = lane & 7;
    for (int kc = 0; kc < nk; kc++){
        if (kc + 1 < nk){
            BSTAGE(kc + 1, ((kc + 1) & 1)*B_BUF);
            cp_commit();
            cp_wait<1>();
        } else {
            cp_wait<0>();
        }
        __syncthreads();
        uint32_t cur = (uint32_t)((kc & 1)*B_BUF);
        #pragma unroll
        for (int ks = 0; ks < 4; ks++){
            uint32_t a_f[4][4];
            #pragma unroll
            for (int mi = 0; mi < 4; mi++){
                uint32_t off = (uint32_t)((wr + mi*16 + wi + (grp & 1)*8)*144
                                          + (ks*16 + (grp >> 1)*8)*2);
                ldsm_x4(a_f[mi], sb + B_A + cur + off);
            }
            uint32_t b_hi[4][2], b_lo[4][2];
            #pragma unroll
            for (int ni = 0; ni < 4; ni++){
                uint32_t off = (uint32_t)((wn + ni*8 + (lane & 7))*144
                                          + (ks*16 + ((lane >> 3) & 1)*8)*2);
                ldsm_x2(b_hi[ni], sb + B_WH + cur + off);
                ldsm_x2(b_lo[ni], sb + B_WL + cur + off);
            }
            #pragma unroll
            for (int mi = 0; mi < 4; mi++)
                #pragma unroll
                for (int ni = 0; ni < 4; ni++){
                    mma16816(acc[mi][ni], a_f[mi], b_hi[ni]);
                    mma16816(acc[mi][ni], a_f[mi], b_lo[ni]);
                }
        }
        __syncthreads();
    }
#undef BSTAGE

    // ---- epilogue ----
    #pragma unroll
    for (int mi = 0; mi < 4; mi++){
        #pragma unroll
        for (int ni = 0; ni < 4; ni++){
            int gn = bn + wn + ni*8 + (lane & 3)*2;
            #pragma unroll
            for (int hh = 0; hh < 2; hh++){
                int m = bm + wr + mi*16 + (lane >> 2) + hh*8;
                float v0 = acc[mi][ni][hh*2 + 0];
                float v1 = acc[mi][ni][hh*2 + 1];
                if (bias){ v0 += bias[gn]; v1 += bias[gn + 1]; }
                if (act){
                    v0 = 0.5f*v0*(1.f + erff(v0*0.70710678118654752f));
                    v1 = 0.5f*v1*(1.f + erff(v1*0.70710678118654752f));
                }
                if (Ch){
                    *(uint32_t*)(Ch + (size_t)m*ldc + gn) = packh(v0, v1);
                } else {
                    if (R){
                        const float* rp = R + (size_t)m*ldr + gn;
                        v0 += rp[0]; v1 += rp[1];
                    }
                    *(float2*)(C + (size_t)m*ldc + gn) = make_float2(v0, v1);
                }
            }
        }
    }
}

// ============== kvprep: head-LN(Q x 1/8 single, K split) + V single fp16 ==============
__global__ void kvprep_kernel(const float* __restrict__ qkv,
    const float* __restrict__ qn, const float* __restrict__ kn,
    __half* __restrict__ qh,
    __half* __restrict__ kh, __half* __restrict__ kl,
    __half* __restrict__ vh)
{
    int g = blockIdx.x*blockDim.x + threadIdx.x;   // NTOK*HEADS*8
    int seg = g & 7;
    int r = g >> 3;
    int tokn = r >> 3, h = r & 7;
    int b = tokn >> 10, l = tokn & 1023;
    if (l >= c_L[b]) return;
    size_t base = (size_t)tokn*DIM + h*64 + seg*8;

#define LN8(x, y, wvec, scale) do { \
    float sum = x.x + x.y + x.z + x.w + y.x + y.y + y.z + y.w; \
    sum += __shfl_xor_sync(0xffffffffu, sum, 1); \
    sum += __shfl_xor_sync(0xffffffffu, sum, 2); \
    sum += __shfl_xor_sync(0xffffffffu, sum, 4); \
    float mu = sum * (1.f/64.f); \
    x.x -= mu; x.y -= mu; x.z -= mu; x.w -= mu; \
    y.x -= mu; y.y -= mu; y.z -= mu; y.w -= mu; \
    float ss = x.x*x.x + x.y*x.y + x.z*x.z + x.w*x.w \
             + y.x*y.x + y.y*y.y + y.z*y.z + y.w*y.w; \
    ss += __shfl_xor_sync(0xffffffffu, ss, 1); \
    ss += __shfl_xor_sync(0xffffffffu, ss, 2); \
    ss += __shfl_xor_sync(0xffffffffu, ss, 4); \
    float rs = rsqrtf(ss * (1.f/64.f) + 1e-5f) * (scale); \
    float4 w0 = *(const float4*)((wvec) + seg*8); \
    float4 w1 = *(const float4*)((wvec) + seg*8 + 4); \
    x.x *= rs*w0.x; x.y *= rs*w0.y; x.z *= rs*w0.z; x.w *= rs*w0.w; \
    y.x *= rs*w1.x; y.y *= rs*w1.y; y.z *= rs*w1.z; y.w *= rs*w1.w; \
} while(0)

    {   // Q single fp16
        const float* p = qkv + base;
        float4 x = *(const float4*)p, y = *(const float4*)(p + 4);
        LN8(x, y, qn, 0.125f);
        *(uint4*)(qh + base) = cvt8s(x, y);
    }
    {   // K split fp16
        const float* p = qkv + (size_t)NTOK*DIM + base;
        float4 x = *(const float4*)p, y = *(const float4*)(p + 4);
        LN8(x, y, kn, 1.f);
        uint4 hi = cvt8s(x, y);
        __half2 h0 = *reinterpret_cast<__half2*>(&hi.x);
        __half2 h1 = *reinterpret_cast<__half2*>(&hi.y);
        __half2 h2 = *reinterpret_cast<__half2*>(&hi.z);
        __half2 h3 = *reinterpret_cast<__half2*>(&hi.w);
        float2 f0 = __half22float2(h0), f1 = __half22float2(h1);
        float2 f2 = __half22float2(h2), f3 = __half22float2(h3);
        uint4 lo = make_uint4(packh(x.x - f0.x, x.y - f0.y), packh(x.z - f1.x, x.w - f1.y),
                              packh(y.x - f2.x, y.y - f2.y), packh(y.z - f3.x, y.w - f3.y));
        *(uint4*)(kh + base) = hi;
        *(uint4*)(kl + base) = lo;
    }
    {   // V single fp16
        const float* p = qkv + (size_t)2*NTOK*DIM + base;
        float4 x = *(const float4*)p, y = *(const float4*)(p + 4);
        *(uint4*)(vh + base) = cvt8s(x, y);
    }
#undef LN8
}

// ============== flash attention: Q single, K split, V single; cp.async double-buffered ==============
#define FQ 0
#define FKV0 18432
#define FKVS 55296                       // per-stage: KH+0, KL+18432, VH+36864
#define FSMEM (18432 + 2*55296)          // 129024

__global__ __launch_bounds__(256) void flash_kernel(
    const __half* __restrict__ Qh,
    const __half* __restrict__ Kh, const __half* __restrict__ Kl,
    const __half* __restrict__ Vh,
    __half* __restrict__ O)
{
    extern __shared__ char smem[];
    uint32_t sb = smem_u32(smem);
    int tid = threadIdx.x, lane = tid & 31, wid = tid >> 5;
    int qt = blockIdx.x;
    int bh = blockIdx.y;
    int b = bh >> 3, h = bh & 7;
    int L = c_L[b];
    if (qt*128 >= L) return;
    int ktiles = (L + 127) >> 7;

    // ---- stage Q ----
    #pragma unroll
    for (int it = 0; it < 4; it++){
        int slot = it*256 + tid; int row = slot >> 3, seg = slot & 7;
        size_t go = (size_t)(b*1024 + qt*128 + row)*DIM + h*64 + seg*8;
        cp_async16(sb + FQ + (uint32_t)(row*144 + seg*16), Qh + go);
    }
    cp_commit();

#define KVSTAGE(KT, SBASE) do { \
    _Pragma("unroll") \
    for (int it = 0; it < 4; it++){ \
        int slot = it*256 + tid; int row = slot >> 3, seg = slot & 7; \
        size_t go = (size_t)(b*1024 + (KT)*128 + row)*DIM + h*64 + seg*8; \
        uint32_t so = (uint32_t)(SBASE) + (uint32_t)(row*144 + seg*16); \
        cp_async16(sb + so,         Kh + go); \
        cp_async16(sb + so + 18432, Kl + go); \
        cp_async16(sb + so + 36864, Vh + go); \
    } } while(0)

    KVSTAGE(0, FKV0);
    cp_commit();

    cp_wait<1>();
    __syncthreads();

    int wr = wid*16;
    int grp = lane >> 3, wi = lane & 7;
    uint32_t aq[4][4];
    #pragma unroll
    for (int ks = 0; ks < 4; ks++){
        uint32_t off = (uint32_t)((wr + wi + (grp & 1)*8)*144 + (ks*16 + (grp >> 1)*8)*2);
        ldsm_x4(aq[ks], sb + FQ + off);
    }

    float m0 = -1e30f, m1 = -1e30f, l0 = 0.f, l1 = 0.f;
    float ao[8][4];
    #pragma unroll
    for (int i = 0; i < 8; i++)
        #pragma unroll
        for (int p = 0; p < 4; p++) ao[i][p] = 0.f;

    for (int kt = 0; kt < ktiles; kt++){
        if (kt + 1 < ktiles){
            KVSTAGE(kt + 1, FKV0 + ((kt + 1) & 1)*FKVS);
            cp_commit();
            cp_wait<1>();
        } else {
            cp_wait<0>();
        }
        __syncthreads();
        uint32_t kb = (uint32_t)(FKV0 + (kt & 1)*FKVS);

        // ---- S = Q K^T  (2 terms) ----
        float s[16][4];
        #pragma unroll
        for (int i = 0; i < 16; i++)
            #pragma unroll
            for (int p = 0; p < 4; p++) s[i][p] = 0.f;
        #pragma unroll
        for (int ks = 0; ks < 4; ks++){
            #pragma unroll
            for (int ni = 0; ni < 16; ni++){
                uint32_t off = (uint32_t)((ni*8 + wi)*144 + (ks*16 + (grp & 1)*8)*2);
                uint32_t bh_[2], bl_[2];
                ldsm_x2(bh_, sb + kb + off);
                ldsm_x2(bl_, sb + kb + 18432 + off);
                mma16816(s[ni], aq[ks], bh_);
                mma16816(s[ni], aq[ks], bl_);
            }
        }

        // ---- mask (partial tile only) ----
        if (kt == ktiles - 1 && (L & 127)){
            int kbase = kt*128 + 2*(lane & 3);
            #pragma unroll
            for (int ni = 0; ni < 16; ni++){
                int kg = kbase + ni*8;
                if (kg     >= L){ s[ni][0] = -1e9f; s[ni][2] = -1e9f; }
                if (kg + 1 >= L){ s[ni][1] = -1e9f; s[ni][3] = -1e9f; }
            }
        }

        // ---- online softmax ----
        float tm0 = -1e30f, tm1 = -1e30f;
        #pragma unroll
        for (int ni = 0; ni < 16; ni++){
            tm0 = fmaxf(tm0, fmaxf(s[ni][0], s[ni][1]));
            tm1 = fmaxf(tm1, fmaxf(s[ni][2], s[ni][3]));
        }
        tm0 = fmaxf(tm0, __shfl_xor_sync(0xffffffffu, tm0, 1));
        tm0 = fmaxf(tm0, __shfl_xor_sync(0xffffffffu, tm0, 2));
        tm1 = fmaxf(tm1, __shfl_xor_sync(0xffffffffu, tm1, 1));
        tm1 = fmaxf(tm1, __shfl_xor_sync(0xffffffffu, tm1, 2));
        float mn0 = fmaxf(m0, tm0), mn1 = fmaxf(m1, tm1);
        float sc0 = __expf(m0 - mn0), sc1 = __expf(m1 - mn1);
        m0 = mn0; m1 = mn1;
        float ts0 = 0.f, ts1 = 0.f;
        #pragma unroll
        for (int ni = 0; ni < 16; ni++){
            s[ni][0] = __expf(s[ni][0] - m0);
            s[ni][1] = __expf(s[ni][1] - m0);
            s[ni][2] = __expf(s[ni][2] - m1);
            s[ni][3] = __expf(s[ni][3] - m1);
            ts0 += s[ni][0] + s[ni][1];
            ts1 += s[ni][2] + s[ni][3];
        }
        ts0 += __shfl_xor_sync(0xffffffffu, ts0, 1);
        ts0 += __shfl_xor_sync(0xffffffffu, ts0, 2);
        ts1 += __shfl_xor_sync(0xffffffffu, ts1, 1);
        ts1 += __shfl_xor_sync(0xffffffffu, ts1, 2);
        l0 = l0*sc0 + ts0;
        l1 = l1*sc1 + ts1;
        #pragma unroll
        for (int i = 0; i < 8; i++){
            ao[i][0] *= sc0; ao[i][1] *= sc0;
            ao[i][2] *= sc1; ao[i][3] *= sc1;
        }

        // ---- O += P V  (1 term) ----
        #pragma unroll
        for (int kk = 0; kk < 8; kk++){
            uint32_t ap[4];
            ap[0] = packh(s[2*kk][0],   s[2*kk][1]);
            ap[1] = packh(s[2*kk][2],   s[2*kk][3]);
            ap[2] = packh(s[2*kk+1][0], s[2*kk+1][1]);
            ap[3] = packh(s[2*kk+1][2], s[2*kk+1][3]);
            #pragma unroll
            for (int ni = 0; ni < 8; ni++){
                uint32_t off = (uint32_t)((kk*16 + (lane & 15))*144 + ni*16);
                uint32_t v_[2];
                ldsm_x2t(v_, sb + kb + 36864 + off);
                mma16816(ao[ni], ap, v_);
            }
        }
        __syncthreads();
    }
#undef KVSTAGE

    // ---- epilogue: single fp16 O ----
    float il0 = 1.f / l0, il1 = 1.f / l1;
    int mrow = qt*128 + wr + (lane >> 2);
    #pragma unroll
    for (int ni = 0; ni < 8; ni++){
        int col = h*64 + ni*8 + 2*(lane & 3);
        *(uint32_t*)(O + (size_t)(b*1024 + mrow)*DIM + col)     = packh(ao[ni][0]*il0, ao[ni][1]*il0);
        *(uint32_t*)(O + (size_t)(b*1024 + mrow + 8)*DIM + col) = packh(ao[ni][2]*il1, ao[ni][3]*il1);
    }
}

// ---------------- patch packing ----------------
__global__ void pack_kernel(const float* __restrict__ img, float* __restrict__ tok){
    size_t i = (size_t)blockIdx.x*blockDim.x + threadIdx.x;
    if (i >= (size_t)NTOK*PDIM) return;
    int pd = (int)(i % PDIM);
    size_t bl = i / PDIM;
    int l = (int)(bl % LMAX);
    int b = (int)(bl / LMAX);
    int L = c_L[b], w = c_Wp[b];
    float v = 0.f;
    if (l < L){
        int c  = pd >> 8;
        int r  = pd & 255;
        int py = r >> 4, px = r & 15;
        int ph = l / w, pw = l % w;
        v = img[((size_t)(b*3 + c)*512 + (size_t)(ph*16 + py))*512 + (size_t)(pw*16 + px)];
    }
    tok[i] = v;
}

// ---------------- row LayerNorm; writes f32 (y) or single fp16 (yh) ----------------
__global__ void ln_kernel(const float* __restrict__ x, const float* __restrict__ w,
                          const float* __restrict__ bb, float* __restrict__ y,
                          __half* __restrict__ yh, int D, int tokskip){
    __shared__ float red[8];
    int row = blockIdx.x, tid = threadIdx.x, lane = tid & 31, wp = tid >> 5;
    if (tokskip && (row & 1023) >= c_L[row >> 10]) return;
    const float* xr = x + (size_t)row*D;
    float lv[3]; float s = 0.f;
    #pragma unroll
    for (int i = 0; i < 3; i++){
        int idx = tid + i*256;
        float vv = (idx < D) ? xr[idx] : 0.f;
        lv[i] = vv; s += vv;
    }
    #pragma unroll
    for (int off = 16; off; off >>= 1) s += __shfl_xor_sync(0xffffffffu, s, off);
    if (lane == 0) red[wp] = s;
    __syncthreads();
    float tot = 0.f;
    #pragma unroll
    for (int i = 0; i < 8; i++) tot += red[i];
    float mu = tot / (float)D;
    __syncthreads();
    float vs = 0.f;
    #pragma unroll
    for (int i = 0; i < 3; i++){
        int idx = tid + i*256;
        if (idx < D){ float d = lv[i] - mu; vs += d*d; }
    }
    #pragma unroll
    for (int off = 16; off; off >>= 1) vs += __shfl_xor_sync(0xffffffffu, vs, off);
    if (lane == 0) red[wp] = vs;
    __syncthreads();
    float tv = 0.f;
    #pragma unroll
    for (int i = 0; i < 8; i++) tv += red[i];
    float rs = rsqrtf(tv / (float)D + 1e-5f);
    #pragma unroll
    for (int i = 0; i < 3; i++){
        int idx = tid + i*256;
        if (idx < D){
            float val = (lv[i] - mu)*rs*w[idx];
            if (bb) val += bb[idx];
            if (y) y[(size_t)row*D + idx] = val;
            else   yh[(size_t)row*D + idx] = __float2half_rn(val);
        }
    }
}

// ---------------- per-head LayerNorm over 64 dims (pool path) ----------------
__global__ void head_ln_kernel(float* __restrict__ x, const float* __restrict__ w, int rows){
    int gw = (int)(((size_t)blockIdx.x*blockDim.x + threadIdx.x) >> 5);
    int lane = threadIdx.x & 31;
    if (gw >= rows) return;
    float* p = x + (size_t)gw*64;
    float a = p[lane], b = p[lane + 32];
    float s = a + b;
    #pragma unroll
    for (int off = 16; off; off >>= 1) s += __shfl_xor_sync(0xffffffffu, s, off);
    float mu = s * (1.f/64.f);
    float da = a - mu, db = b - mu;
    float vs = da*da + db*db;
    #pragma unroll
    for (int off = 16; off; off >>= 1) vs += __shfl_xor_sync(0xffffffffu, vs, off);
    float rs = rsqrtf(vs * (1.f/64.f) + 1e-5f);
    p[lane]      = da * rs * w[lane];
    p[lane + 32] = db * rs * w[lane + 32];
}

// ---------------- pos embed + mask ----------------
__global__ void posmask_kernel(float* __restrict__ t, const float* __restrict__ ph,
                               const float* __restrict__ pw){
    int bl = blockIdx.x;
    int b = bl >> 10, l = bl & 1023;
    int L = c_L[b], w = c_Wp[b];
    float* r = t + (size_t)bl*DIM;
    int d = threadIdx.x;
    if (l < L) r[d] = r[d] + ph[(size_t)(l / w)*DIM + d] + pw[(size_t)(l % w)*DIM + d];
    else       r[d] = 0.f;
}

// ---------------- f32 SIMT GEMM NT (small M only) ----------------
__global__ __launch_bounds__(256) void gemm_nt_kernel(
    const float* __restrict__ A, int lda,
    const float* __restrict__ W, int ldw,
    const float* __restrict__ bias,
    float* __restrict__ C, int ldc,
    int M, int N, int K)
{
    __shared__ __align__(16) float As[8][128];
    __shared__ __align__(16) float Bs[8][128];
    int bm = blockIdx.y*128, bn = blockIdx.x*128;
    int tid = threadIdx.x;
    int tx = tid & 15, ty = tid >> 4;
    float acc[8][8];
    #pragma unroll
    for (int i = 0; i < 8; i++)
        #pragma unroll
        for (int j = 0; j < 8; j++) acc[i][j] = 0.f;
    int lr = tid >> 1;
    int lk = (tid & 1)*4;
    for (int k0 = 0; k0 < K; k0 += 8){
        float4 av = make_float4(0,0,0,0), bv = make_float4(0,0,0,0);
        if (bm + lr < M) av = *(const float4*)(A + (size_t)(bm + lr)*lda + k0 + lk);
        if (bn + lr < N) bv = *(const float4*)(W + (size_t)(bn + lr)*ldw + k0 + lk);
        As[lk+0][lr] = av.x; As[lk+1][lr] = av.y; As[lk+2][lr] = av.z; As[lk+3][lr] = av.w;
        Bs[lk+0][lr] = bv.x; Bs[lk+1][lr] = bv.y; Bs[lk+2][lr] = bv.z; Bs[lk+3][lr] = bv.w;
        __syncthreads();
        #pragma unroll
        for (int kk = 0; kk < 8; kk++){
            float a[8], b[8];
            #pragma unroll
            for (int i = 0; i < 8; i++) a[i] = As[kk][ty*8 + i];
            #pragma unroll
            for (int j = 0; j < 8; j++) b[j] = Bs[kk][tx*8 + j];
            #pragma unroll
            for (int i = 0; i < 8; i++)
                #pragma unroll
                for (int j = 0; j < 8; j++) acc[i][j] = fmaf(a[i], b[j], acc[i][j]);
        }
        __syncthreads();
    }
    #pragma unroll
    for (int i = 0; i < 8; i++){
        int m = bm + ty*8 + i;
        if (m >= M) continue;
        #pragma unroll
        for (int j = 0; j < 8; j++){
            int n = bn + tx*8 + j;
            if (n >= N) continue;
            float v = acc[i][j];
            if (bias) v += bias[n];
            C[(size_t)m*ldc + n] = v;
        }
    }
}

// ---------------- pooling attention (Lq=1) ----------------
__global__ void pool_attn_kernel(const float* __restrict__ qhat, const float* __restrict__ K,
                                 const float* __restrict__ V, float* __restrict__ O){
    int h = blockIdx.x, b = blockIdx.y;
    __shared__ float sq[64];
    __shared__ float sa[1024];
    __shared__ float red[8], red2[8];
    __shared__ float racc[4][64];
    int tid = threadIdx.x, lane = tid & 31, wp = tid >> 5;
    if (tid < 64) sq[tid] = qhat[h*64 + tid];
    __syncthreads();
    int L = c_L[b];
    for (int kk = tid; kk < 1024; kk += 256){
        float dot = -1e9f;
        if (kk < L){
            const float* kr = K + ((size_t)(b*1024 + kk))*DIM + h*64;
            float ss = 0.f;
            #pragma unroll
            for (int d = 0; d < 64; d++) ss += sq[d]*kr[d];
            dot = ss*0.125f;
        }
        sa[kk] = dot;
    }
    __syncthreads();
    float m = -1e30f;
    for (int kk = tid; kk < 1024; kk += 256) m = fmaxf(m, sa[kk]);
    #pragma unroll
    for (int off = 16; off; off >>= 1) m = fmaxf(m, __shfl_xor_sync(0xffffffffu, m, off));
    if (lane == 0) red[wp] = m;
    __syncthreads();
    float bm = -1e30f;
    #pragma unroll
    for (int i = 0; i < 8; i++) bm = fmaxf(bm, red[i]);
    float sum = 0.f;
    for (int kk = tid; kk < 1024; kk += 256){
        float e = __expf(sa[kk] - bm);
        sa[kk] = e; sum += e;
    }
    #pragma unroll
    for (int off = 16; off; off >>= 1) sum += __shfl_xor_sync(0xffffffffu, sum, off);
    if (lane == 0) red2[wp] = sum;
    __syncthreads();
    float bs = 0.f;
    #pragma unroll
    for (int i = 0; i < 8; i++) bs += red2[i];
    float inv = 1.f / bs;
    int dd = tid & 63, part = tid >> 6;
    float acc = 0.f;
    for (int kk = part; kk < 1024; kk += 4)
        acc += sa[kk] * V[((size_t)(b*1024 + kk))*DIM + h*64 + dd];
    racc[part][dd] = acc;
    __syncthreads();
    if (part == 0)
        O[b*DIM + h*64 + dd] = (racc[0][dd] + racc[1][dd] + racc[2][dd] + racc[3][dd]) * inv;
}

// ---------------- host helpers ----------------
static void launch_wsplit(const float* src, __half* h, __half* l, long n){
    wsplit_kernel<<<(int)((n + 255)/256), 256>>>(src, h, l, (int)n);
}
static void launch_bg(const __half* A, int lda,
                      const __half* Wh, const __half* Wl, int ldw, long wz,
                      const float* bias, const float* R, int ldr,
                      float* C, __half* Ch, int ldc, long cz,
                      int N, int K, int act, int nz, int tokrows){
    dim3 g(N/128, NTOK/128, nz);
    bgemm_nt<<<g, 256, B_SMEM>>>(A, lda, Wh, Wl, ldw, wz, bias, R, ldr,
                                 C, Ch, ldc, cz, K, act, tokrows);
}
static void launch_small(const float* A, int lda, const float* W, int ldw,
                         const float* bias, float* C, int ldc, int M, int N, int K){
    dim3 g((N + 127)/128, (M + 127)/128, 1);
    gemm_nt_kernel<<<g, 256>>>(A, lda, W, ldw, bias, C, ldc, M, N, K);
}

extern "C" void kernel_launch(void* const* d_in, const int* in_sizes, int n_in,
                              void* d_out, int out_size){
    const float* images   = (const float*)d_in[0];
    const float* pe_ln1_w = (const float*)d_in[1];
    const float* pe_ln1_b = (const float*)d_in[2];
    const float* pe_w     = (const float*)d_in[3];
    const float* pe_b     = (const float*)d_in[4];
    const float* pe_ln2_w = (const float*)d_in[5];
    const float* pe_ln2_b = (const float*)d_in[6];
    const float* pos_h    = (const float*)d_in[7];
    const float* pos_w    = (const float*)d_in[8];
    const float* attn_ln  = (const float*)d_in[9];
    const float* wq       = (const float*)d_in[10];
    const float* wk       = (const float*)d_in[11];
    const float* wv       = (const float*)d_in[12];
    const float* qn       = (const float*)d_in[13];
    const float* kn       = (const float*)d_in[14];
    const float* wo       = (const float*)d_in[15];
    const float* ff_ln    = (const float*)d_in[16];
    const float* ff_w1    = (const float*)d_in[17];
    const float* ff_b1    = (const float*)d_in[18];
    const float* ff_w2    = (const float*)d_in[19];
    const float* ff_b2    = (const float*)d_in[20];
    const float* final_ln = (const float*)d_in[21];
    const float* pool_q   = (const float*)d_in[22];
    const float* pool_ln  = (const float*)d_in[23];
    const float* pool_wq  = (const float*)d_in[24];
    const float* pool_wk  = (const float*)d_in[25];
    const float* pool_wv  = (const float*)d_in[26];
    const float* pool_qn  = (const float*)d_in[27];
    const float* pool_kn  = (const float*)d_in[28];
    const float* pool_wo  = (const float*)d_in[29];
    const float* head_ln  = (const float*)d_in[30];
    const float* head_w   = (const float*)d_in[31];
    float* out = (float*)d_out;

    cudaFuncSetAttribute(bgemm_nt, cudaFuncAttributeMaxDynamicSharedMemorySize, B_SMEM);
    cudaFuncSetAttribute(flash_kernel, cudaFuncAttributeMaxDynamicSharedMemorySize, FSMEM);

    float *tok,*t,*qkv,*u,*qp,*po,*pooled,*hn;
    __half *wh,*wl,*lt,*xn,*mlp,*o,*qh,*kh,*kl,*vh;
    cudaGetSymbolAddress((void**)&tok, g_tok);
    cudaGetSymbolAddress((void**)&t,   g_t);
    cudaGetSymbolAddress((void**)&qkv, g_qkv);
    cudaGetSymbolAddress((void**)&u,   g_u);
    cudaGetSymbolAddress((void**)&qp,  g_qp);
    cudaGetSymbolAddress((void**)&po,  g_po);
    cudaGetSymbolAddress((void**)&pooled, g_pooled);
    cudaGetSymbolAddress((void**)&hn,  g_hn);
    cudaGetSymbolAddress((void**)&wh,  g_wh);
    cudaGetSymbolAddress((void**)&wl,  g_wl);
    cudaGetSymbolAddress((void**)&lt,  g_lt);
    cudaGetSymbolAddress((void**)&xn,  g_xn);
    cudaGetSymbolAddress((void**)&mlp, g_mlp);
    cudaGetSymbolAddress((void**)&o,   g_o);
    cudaGetSymbolAddress((void**)&qh,  g_qh2);
    cudaGetSymbolAddress((void**)&kh,  g_kh2);
    cudaGetSymbolAddress((void**)&kl,  g_kl2);
    cudaGetSymbolAddress((void**)&vh,  g_vh2);

    float* kf = qkv + (size_t)NTOK*DIM;
    float* vf = qkv + (size_t)2*NTOK*DIM;

    // ---- weight split (once per launch) ----
    launch_wsplit(wq, wh + OFF_QKV,             wl + OFF_QKV,             6L*DIM*DIM);
    launch_wsplit(wk, wh + OFF_QKV + 1572864L,  wl + OFF_QKV + 1572864L,  6L*DIM*DIM);
    launch_wsplit(wv, wh + OFF_QKV + 3145728L,  wl + OFF_QKV + 3145728L,  6L*DIM*DIM);
    launch_wsplit(wo, wh + OFF_WO,  wl + OFF_WO,  6L*DIM*DIM);
    launch_wsplit(ff_w1, wh + OFF_FF1, wl + OFF_FF1, 6L*MLPD*DIM);
    launch_wsplit(ff_w2, wh + OFF_FF2, wl + OFF_FF2, 6L*DIM*MLPD);
    launch_wsplit(pe_w, wh + OFF_PE, wl + OFF_PE, (long)DIM*PDIM);
    launch_wsplit(pool_wk, wh + OFF_PK, wl + OFF_PK, (long)DIM*DIM);
    launch_wsplit(pool_wv, wh + OFF_PV, wl + OFF_PV, (long)DIM*DIM);

    // ---- patch embed ----
    pack_kernel<<<((size_t)NTOK*PDIM + 255)/256, 256>>>(images, tok);
    ln_kernel<<<NTOK, 256>>>(tok, pe_ln1_w, pe_ln1_b, nullptr, lt, PDIM, 1);
    launch_bg(lt, PDIM, wh + OFF_PE, wl + OFF_PE, PDIM, 0, pe_b,
              nullptr, 0, t, nullptr, DIM, 0, DIM, PDIM, 0, 1, 1);
    ln_kernel<<<NTOK, 256>>>(t, pe_ln2_w, pe_ln2_b, t, nullptr, DIM, 1);
    posmask_kernel<<<NTOK, DIM>>>(t, pos_h, pos_w);

    // ---- transformer layers ----
    for (int l = 0; l < NDEPTH; l++){
        ln_kernel<<<NTOK, 256>>>(t, attn_ln + l*DIM, nullptr, nullptr, xn, DIM, 1);
        launch_bg(xn, DIM, wh + OFF_QKV + (size_t)l*DIM*DIM, wl + OFF_QKV + (size_t)l*DIM*DIM,
                  DIM, 1572864L, nullptr, nullptr, 0,
                  qkv, nullptr, DIM, (long)NTOK*DIM, DIM, DIM, 0, 3, 1);
        kvprep_kernel<<<NTOK*HEADS*8/256, 256>>>(qkv, qn + l*DH, kn + l*DH, qh, kh, kl, vh);
        flash_kernel<<<dim3(8, BB*HEADS), 256, FSMEM>>>(qh, kh, kl, vh, o);
        launch_bg(o, DIM, wh + OFF_WO + (size_t)l*DIM*DIM, wl + OFF_WO + (size_t)l*DIM*DIM,
                  DIM, 0, nullptr, t, DIM, t, nullptr, DIM, 0, DIM, DIM, 0, 1, 1);
        ln_kernel<<<NTOK, 256>>>(t, ff_ln + l*DIM, nullptr, nullptr, xn, DIM, 1);
        launch_bg(xn, DIM, wh + OFF_FF1 + (size_t)l*MLPD*DIM, wl + OFF_FF1 + (size_t)l*MLPD*DIM,
                  DIM, 0, ff_b1 + l*MLPD, nullptr, 0,
                  nullptr, mlp, MLPD, 0, MLPD, DIM, 1, 1, 1);
        launch_bg(mlp, MLPD, wh + OFF_FF2 + (size_t)l*DIM*MLPD, wl + OFF_FF2 + (size_t)l*DIM*MLPD,
                  MLPD, 0, ff_b2 + l*DIM, t, DIM, t, nullptr, DIM, 0, DIM, MLPD, 0, 1, 1);
    }

    // ---- final LN + pooling ----
    ln_kernel<<<NTOK, 256>>>(t, final_ln, nullptr, nullptr, xn, DIM, 1);
    ln_kernel<<<1, 256>>>(pool_q, pool_ln, nullptr, u, nullptr, DIM, 0);
    launch_small(u, DIM, pool_wq, DIM, nullptr, qp, DIM, 1, DIM, DIM);
    head_ln_kernel<<<1, 256>>>(qp, pool_qn, HEADS);
    launch_bg(xn, DIM, wh + OFF_PK, wl + OFF_PK, DIM, 0, nullptr, nullptr, 0,
              kf, nullptr, DIM, 0, DIM, DIM, 0, 1, 1);
    head_ln_kernel<<<(NTOK*HEADS*32 + 255)/256, 256>>>(kf, pool_kn, NTOK*HEADS);
    launch_bg(xn, DIM, wh + OFF_PV, wl + OFF_PV, DIM, 0, nullptr, nullptr, 0,
              vf, nullptr, DIM, 0, DIM, DIM, 0, 1, 1);
    pool_attn_kernel<<<dim3(HEADS, BB), 256>>>(qp, kf, vf, po);
    launch_small(po, DIM, pool_wo, DIM, nullptr, pooled, DIM, BB, DIM, DIM);
    ln_kernel<<<BB, 256>>>(pooled, head_ln, nullptr, hn, nullptr, DIM, 0);
    launch_small(hn, DIM, head_w, DIM, nullptr, out, NC, BB, NC, DIM);
}

// round 8
// speedup vs baseline: 12.8060x; 1.4186x over previous
#include <cuda_runtime.h>
#include <cuda_fp16.h>
#include <math.h>
#include <stdint.h>

#define BB 8
#define LMAX 1024
#define DIM 512
#define HEADS 8
#define DH 64
#define NDEPTH 6
#define MLPD 2048
#define NC 1000
#define PDIM 768
#define NTOK (BB*LMAX)   // 8192

__constant__ int c_L[8]  = {1024, 768, 896, 576, 560, 512, 384, 640};
__constant__ int c_Wp[8] = {  32,  24,  32,  24,  28,  32,  16,  20};

// weight buffer offsets (elements)
#define OFF_QKV 0L
#define OFF_WO  4718592L
#define OFF_FF1 6291456L
#define OFF_FF2 12582912L
#define OFF_PE  18874368L
#define OFF_PK  19267584L
#define OFF_PV  19529728L
#define WTOT    19791872L

// ---------------- scratch ----------------
__device__ __align__(128) float g_tok[(size_t)NTOK*PDIM];
__device__ __align__(128) float g_t  [(size_t)NTOK*DIM];
__device__ __align__(128) float g_qkv[(size_t)3*NTOK*DIM];
__device__ __align__(128) float g_u  [DIM];
__device__ __align__(128) float g_qp [DIM];
__device__ __align__(128) float g_po [BB*DIM];
__device__ __align__(128) float g_pooled[BB*DIM];
__device__ __align__(128) float g_hn [BB*DIM];
__device__ __align__(128) __half g_wh[WTOT];
__device__ __align__(128) __half g_lt [(size_t)NTOK*PDIM];
__device__ __align__(128) __half g_xn [(size_t)NTOK*DIM];
__device__ __align__(128) __half g_mlp[(size_t)NTOK*MLPD];
__device__ __align__(128) __half g_o  [(size_t)NTOK*DIM];
__device__ __align__(128) __half g_qh2[(size_t)NTOK*DIM];
__device__ __align__(128) __half g_kh2[(size_t)NTOK*DIM];
__device__ __align__(128) __half g_vh2[(size_t)NTOK*DIM];

// ================= helpers =================
__device__ __forceinline__ uint32_t smem_u32(const void* p){
    uint32_t a; asm("{ .reg .u64 t; cvta.to.shared.u64 t, %1; cvt.u32.u64 %0, t; }" : "=r"(a) : "l"(p));
    return a;
}
__device__ __forceinline__ void ldsm_x4(uint32_t* r, uint32_t addr){
    asm volatile("ldmatrix.sync.aligned.m8n8.x4.shared.b16 {%0,%1,%2,%3}, [%4];"
        : "=r"(r[0]),"=r"(r[1]),"=r"(r[2]),"=r"(r[3]) : "r"(addr));
}
__device__ __forceinline__ void ldsm_x2(uint32_t* r, uint32_t addr){
    asm volatile("ldmatrix.sync.aligned.m8n8.x2.shared.b16 {%0,%1}, [%2];"
        : "=r"(r[0]),"=r"(r[1]) : "r"(addr));
}
__device__ __forceinline__ void ldsm_x2t(uint32_t* r, uint32_t addr){
    asm volatile("ldmatrix.sync.aligned.m8n8.x2.trans.shared.b16 {%0,%1}, [%2];"
        : "=r"(r[0]),"=r"(r[1]) : "r"(addr));
}
__device__ __forceinline__ void mma16816(float* c, const uint32_t* a, const uint32_t* b){
    asm volatile("mma.sync.aligned.m16n8k16.row.col.f32.f16.f16.f32 "
        "{%0,%1,%2,%3}, {%4,%5,%6,%7}, {%8,%9}, {%0,%1,%2,%3};"
        : "+f"(c[0]),"+f"(c[1]),"+f"(c[2]),"+f"(c[3])
        : "r"(a[0]),"r"(a[1]),"r"(a[2]),"r"(a[3]), "r"(b[0]),"r"(b[1]));
}
__device__ __forceinline__ void cp_async16(uint32_t dst, const void* src){
    asm volatile("cp.async.cg.shared.global [%0], [%1], 16;" :: "r"(dst), "l"(src) : "memory");
}
__device__ __forceinline__ void cp_commit(){ asm volatile("cp.async.commit_group;" ::: "memory"); }
template<int N> __device__ __forceinline__ void cp_wait(){
    asm volatile("cp.async.wait_group %0;" :: "n"(N) : "memory");
}
__device__ __forceinline__ uint32_t h2u(__half2 v){ return *reinterpret_cast<uint32_t*>(&v); }
__device__ __forceinline__ uint32_t packh(float a, float b){
    return h2u(__float22half2_rn(make_float2(a, b)));
}
__device__ __forceinline__ uint4 cvt8s(float4 a, float4 b){
    return make_uint4(packh(a.x, a.y), packh(a.z, a.w), packh(b.x, b.y), packh(b.z, b.w));
}

// ---------------- weight f32 -> fp16 convert ----------------
__global__ void wcvt_kernel(const float* __restrict__ src, __half* __restrict__ h, int n){
    int i = blockIdx.x*blockDim.x + threadIdx.x;
    if (i >= n) return;
    h[i] = __float2half_rn(src[i]);
}

// ============== cp.async HMMA GEMM NT: C = A @ W^T  (pure fp16, f32 accum) ==============
#define BTILE (128*144)          // 18432
#define B_A  0
#define B_W  BTILE
#define B_BUF (2*BTILE)          // 36864
#define B_SMEM (2*B_BUF)         // 73728

__global__ __launch_bounds__(256, 2) void bgemm_nt(
    const __half* __restrict__ A, int lda,
    const __half* __restrict__ W, int ldw, long wz,
    const float* __restrict__ bias,
    const float* __restrict__ R, int ldr,
    float* __restrict__ C, __half* __restrict__ Ch,
    int ldc, long cz,
    int K, int act, int tokrows)
{
    extern __shared__ char smem[];
    uint32_t sb = smem_u32(smem);
    int tid = threadIdx.x, lane = tid & 31, wid = tid >> 5;
    int z = blockIdx.z;
    W += (size_t)z*wz;
    if (C)  C  += (size_t)z*cz;
    int bm = blockIdx.y*128, bn = blockIdx.x*128;
    if (tokrows && (bm & 1023) >= c_L[bm >> 10]) return;
    int wr = (wid & 1)*64;
    int wn = (wid >> 1)*32;

    float acc[4][4][4];
    #pragma unroll
    for (int i = 0; i < 4; i++)
        #pragma unroll
        for (int j = 0; j < 4; j++)
            #pragma unroll
            for (int p = 0; p < 4; p++) acc[i][j][p] = 0.f;

#define BSTAGE(KC, BUFB) do { \
    _Pragma("unroll") \
    for (int it = 0; it < 4; it++){ \
        int slot = it*256 + tid; int row = slot >> 3, seg = slot & 7; \
        uint32_t so = (uint32_t)(BUFB) + (uint32_t)(row*144 + seg*16); \
        cp_async16(sb + B_A + so, A + (size_t)(bm + row)*lda + (KC)*64 + seg*8); \
        cp_async16(sb + B_W + so, W + (size_t)(bn + row)*ldw + (KC)*64 + seg*8); \
    } } while(0)

    int nk = K >> 6;
    BSTAGE(0, 0);
    cp_commit();

    int grp = lane >> 3, wi = lane & 7;
    for (int kc = 0; kc < nk; kc++){
        if (kc + 1 < nk){
            BSTAGE(kc + 1, ((kc + 1) & 1)*B_BUF);
            cp_commit();
            cp_wait<1>();
        } else {
            cp_wait<0>();
        }
        __syncthreads();
        uint32_t cur = (uint32_t)((kc & 1)*B_BUF);
        #pragma unroll
        for (int ks = 0; ks < 4; ks++){
            uint32_t a_f[4][4];
            #pragma unroll
            for (int mi = 0; mi < 4; mi++){
                uint32_t off = (uint32_t)((wr + mi*16 + wi + (grp & 1)*8)*144
                                          + (ks*16 + (grp >> 1)*8)*2);
                ldsm_x4(a_f[mi], sb + B_A + cur + off);
            }
            uint32_t b_f[4][2];
            #pragma unroll
            for (int ni = 0; ni < 4; ni++){
                uint32_t off = (uint32_t)((wn + ni*8 + (lane & 7))*144
                                          + (ks*16 + ((lane >> 3) & 1)*8)*2);
                ldsm_x2(b_f[ni], sb + B_W + cur + off);
            }
            #pragma unroll
            for (int mi = 0; mi < 4; mi++)
                #pragma unroll
                for (int ni = 0; ni < 4; ni++)
                    mma16816(acc[mi][ni], a_f[mi], b_f[ni]);
        }
        __syncthreads();
    }
#undef BSTAGE

    // ---- epilogue ----
    #pragma unroll
    for (int mi = 0; mi < 4; mi++){
        #pragma unroll
        for (int ni = 0; ni < 4; ni++){
            int gn = bn + wn + ni*8 + (lane & 3)*2;
            #pragma unroll
            for (int hh = 0; hh < 2; hh++){
                int m = bm + wr + mi*16 + (lane >> 2) + hh*8;
                float v0 = acc[mi][ni][hh*2 + 0];
                float v1 = acc[mi][ni][hh*2 + 1];
                if (bias){ v0 += bias[gn]; v1 += bias[gn + 1]; }
                if (act){
                    v0 = 0.5f*v0*(1.f + erff(v0*0.70710678118654752f));
                    v1 = 0.5f*v1*(1.f + erff(v1*0.70710678118654752f));
                }
                if (Ch){
                    *(uint32_t*)(Ch + (size_t)m*ldc + gn) = packh(v0, v1);
                } else {
                    if (R){
                        const float* rp = R + (size_t)m*ldr + gn;
                        v0 += rp[0]; v1 += rp[1];
                    }
                    *(float2*)(C + (size_t)m*ldc + gn) = make_float2(v0, v1);
                }
            }
        }
    }
}

// ============== kvprep: head-LN(Q x 1/8, K) + QKV -> single fp16 ==============
__global__ void kvprep_kernel(const float* __restrict__ qkv,
    const float* __restrict__ qn, const float* __restrict__ kn,
    __half* __restrict__ qh, __half* __restrict__ kh, __half* __restrict__ vh)
{
    int g = blockIdx.x*blockDim.x + threadIdx.x;   // NTOK*HEADS*8
    int seg = g & 7;
    int r = g >> 3;
    int tokn = r >> 3, h = r & 7;
    int b = tokn >> 10, l = tokn & 1023;
    if (l >= c_L[b]) return;
    size_t base = (size_t)tokn*DIM + h*64 + seg*8;

#define LN8(x, y, wvec, scale) do { \
    float sum = x.x + x.y + x.z + x.w + y.x + y.y + y.z + y.w; \
    sum += __shfl_xor_sync(0xffffffffu, sum, 1); \
    sum += __shfl_xor_sync(0xffffffffu, sum, 2); \
    sum += __shfl_xor_sync(0xffffffffu, sum, 4); \
    float mu = sum * (1.f/64.f); \
    x.x -= mu; x.y -= mu; x.z -= mu; x.w -= mu; \
    y.x -= mu; y.y -= mu; y.z -= mu; y.w -= mu; \
    float ss = x.x*x.x + x.y*x.y + x.z*x.z + x.w*x.w \
             + y.x*y.x + y.y*y.y + y.z*y.z + y.w*y.w; \
    ss += __shfl_xor_sync(0xffffffffu, ss, 1); \
    ss += __shfl_xor_sync(0xffffffffu, ss, 2); \
    ss += __shfl_xor_sync(0xffffffffu, ss, 4); \
    float rs = rsqrtf(ss * (1.f/64.f) + 1e-5f) * (scale); \
    float4 w0 = *(const float4*)((wvec) + seg*8); \
    float4 w1 = *(const float4*)((wvec) + seg*8 + 4); \
    x.x *= rs*w0.x; x.y *= rs*w0.y; x.z *= rs*w0.z; x.w *= rs*w0.w; \
    y.x *= rs*w1.x; y.y *= rs*w1.y; y.z *= rs*w1.z; y.w *= rs*w1.w; \
} while(0)

    {   // Q
        const float* p = qkv + base;
        float4 x = *(const float4*)p, y = *(const float4*)(p + 4);
        LN8(x, y, qn, 0.125f);
        *(uint4*)(qh + base) = cvt8s(x, y);
    }
    {   // K
        const float* p = qkv + (size_t)NTOK*DIM + base;
        float4 x = *(const float4*)p, y = *(const float4*)(p + 4);
        LN8(x, y, kn, 1.f);
        *(uint4*)(kh + base) = cvt8s(x, y);
    }
    {   // V
        const float* p = qkv + (size_t)2*NTOK*DIM + base;
        float4 x = *(const float4*)p, y = *(const float4*)(p + 4);
        *(uint4*)(vh + base) = cvt8s(x, y);
    }
#undef LN8
}

// ============== flash attention: pure fp16, cp.async double-buffered K/V ==============
#define FQ 0
#define FKV0 18432
#define FKVS 36864                       // per-stage: KH+0, VH+18432
#define FSMEM (18432 + 2*36864)          // 92160

__global__ __launch_bounds__(256, 2) void flash_kernel(
    const __half* __restrict__ Qh,
    const __half* __restrict__ Kh,
    const __half* __restrict__ Vh,
    __half* __restrict__ O)
{
    extern __shared__ char smem[];
    uint32_t sb = smem_u32(smem);
    int tid = threadIdx.x, lane = tid & 31, wid = tid >> 5;
    int qt = blockIdx.x;
    int bh = blockIdx.y;
    int b = bh >> 3, h = bh & 7;
    int L = c_L[b];
    if (qt*128 >= L) return;
    int ktiles = (L + 127) >> 7;

    // ---- stage Q ----
    #pragma unroll
    for (int it = 0; it < 4; it++){
        int slot = it*256 + tid; int row = slot >> 3, seg = slot & 7;
        size_t go = (size_t)(b*1024 + qt*128 + row)*DIM + h*64 + seg*8;
        cp_async16(sb + FQ + (uint32_t)(row*144 + seg*16), Qh + go);
    }
    cp_commit();

#define KVSTAGE(KT, SBASE) do { \
    _Pragma("unroll") \
    for (int it = 0; it < 4; it++){ \
        int slot = it*256 + tid; int row = slot >> 3, seg = slot & 7; \
        size_t go = (size_t)(b*1024 + (KT)*128 + row)*DIM + h*64 + seg*8; \
        uint32_t so = (uint32_t)(SBASE) + (uint32_t)(row*144 + seg*16); \
        cp_async16(sb + so,         Kh + go); \
        cp_async16(sb + so + 18432, Vh + go); \
    } } while(0)

    KVSTAGE(0, FKV0);
    cp_commit();

    cp_wait<1>();
    __syncthreads();

    int wr = wid*16;
    int grp = lane >> 3, wi = lane & 7;
    uint32_t aq[4][4];
    #pragma unroll
    for (int ks = 0; ks < 4; ks++){
        uint32_t off = (uint32_t)((wr + wi + (grp & 1)*8)*144 + (ks*16 + (grp >> 1)*8)*2);
        ldsm_x4(aq[ks], sb + FQ + off);
    }

    float m0 = -1e30f, m1 = -1e30f, l0 = 0.f, l1 = 0.f;
    float ao[8][4];
    #pragma unroll
    for (int i = 0; i < 8; i++)
        #pragma unroll
        for (int p = 0; p < 4; p++) ao[i][p] = 0.f;

    for (int kt = 0; kt < ktiles; kt++){
        if (kt + 1 < ktiles){
            KVSTAGE(kt + 1, FKV0 + ((kt + 1) & 1)*FKVS);
            cp_commit();
            cp_wait<1>();
        } else {
            cp_wait<0>();
        }
        __syncthreads();
        uint32_t kb = (uint32_t)(FKV0 + (kt & 1)*FKVS);

        // ---- S = Q K^T ----
        float s[16][4];
        #pragma unroll
        for (int i = 0; i < 16; i++)
            #pragma unroll
            for (int p = 0; p < 4; p++) s[i][p] = 0.f;
        #pragma unroll
        for (int ks = 0; ks < 4; ks++){
            #pragma unroll
            for (int ni = 0; ni < 16; ni++){
                uint32_t off = (uint32_t)((ni*8 + wi)*144 + (ks*16 + (grp & 1)*8)*2);
                uint32_t b_[2];
                ldsm_x2(b_, sb + kb + off);
                mma16816(s[ni], aq[ks], b_);
            }
        }

        // ---- mask (partial tile only) ----
        if (kt == ktiles - 1 && (L & 127)){
            int kbase = kt*128 + 2*(lane & 3);
            #pragma unroll
            for (int ni = 0; ni < 16; ni++){
                int kg = kbase + ni*8;
                if (kg     >= L){ s[ni][0] = -1e9f; s[ni][2] = -1e9f; }
                if (kg + 1 >= L){ s[ni][1] = -1e9f; s[ni][3] = -1e9f; }
            }
        }

        // ---- online softmax ----
        float tm0 = -1e30f, tm1 = -1e30f;
        #pragma unroll
        for (int ni = 0; ni < 16; ni++){
            tm0 = fmaxf(tm0, fmaxf(s[ni][0], s[ni][1]));
            tm1 = fmaxf(tm1, fmaxf(s[ni][2], s[ni][3]));
        }
        tm0 = fmaxf(tm0, __shfl_xor_sync(0xffffffffu, tm0, 1));
        tm0 = fmaxf(tm0, __shfl_xor_sync(0xffffffffu, tm0, 2));
        tm1 = fmaxf(tm1, __shfl_xor_sync(0xffffffffu, tm1, 1));
        tm1 = fmaxf(tm1, __shfl_xor_sync(0xffffffffu, tm1, 2));
        float mn0 = fmaxf(m0, tm0), mn1 = fmaxf(m1, tm1);
        float sc0 = __expf(m0 - mn0), sc1 = __expf(m1 - mn1);
        m0 = mn0; m1 = mn1;
        float ts0 = 0.f, ts1 = 0.f;
        #pragma unroll
        for (int ni = 0; ni < 16; ni++){
            s[ni][0] = __expf(s[ni][0] - m0);
            s[ni][1] = __expf(s[ni][1] - m0);
            s[ni][2] = __expf(s[ni][2] - m1);
            s[ni][3] = __expf(s[ni][3] - m1);
            ts0 += s[ni][0] + s[ni][1];
            ts1 += s[ni][2] + s[ni][3];
        }
        ts0 += __shfl_xor_sync(0xffffffffu, ts0, 1);
        ts0 += __shfl_xor_sync(0xffffffffu, ts0, 2);
        ts1 += __shfl_xor_sync(0xffffffffu, ts1, 1);
        ts1 += __shfl_xor_sync(0xffffffffu, ts1, 2);
        l0 = l0*sc0 + ts0;
        l1 = l1*sc1 + ts1;
        #pragma unroll
        for (int i = 0; i < 8; i++){
            ao[i][0] *= sc0; ao[i][1] *= sc0;
            ao[i][2] *= sc1; ao[i][3] *= sc1;
        }

        // ---- O += P V ----
        #pragma unroll
        for (int kk = 0; kk < 8; kk++){
            uint32_t ap[4];
            ap[0] = packh(s[2*kk][0],   s[2*kk][1]);
            ap[1] = packh(s[2*kk][2],   s[2*kk][3]);
            ap[2] = packh(s[2*kk+1][0], s[2*kk+1][1]);
            ap[3] = packh(s[2*kk+1][2], s[2*kk+1][3]);
            #pragma unroll
            for (int ni = 0; ni < 8; ni++){
                uint32_t off = (uint32_t)((kk*16 + (lane & 15))*144 + ni*16);
                uint32_t v_[2];
                ldsm_x2t(v_, sb + kb + 18432 + off);
                mma16816(ao[ni], ap, v_);
            }
        }
        __syncthreads();
    }
#undef KVSTAGE

    // ---- epilogue: fp16 O ----
    float il0 = 1.f / l0, il1 = 1.f / l1;
    int mrow = qt*128 + wr + (lane >> 2);
    #pragma unroll
    for (int ni = 0; ni < 8; ni++){
        int col = h*64 + ni*8 + 2*(lane & 3);
        *(uint32_t*)(O + (size_t)(b*1024 + mrow)*DIM + col)     = packh(ao[ni][0]*il0, ao[ni][1]*il0);
        *(uint32_t*)(O + (size_t)(b*1024 + mrow + 8)*DIM + col) = packh(ao[ni][2]*il1, ao[ni][3]*il1);
    }
}

// ---------------- patch packing ----------------
__global__ void pack_kernel(const float* __restrict__ img, float* __restrict__ tok){
    size_t i = (size_t)blockIdx.x*blockDim.x + threadIdx.x;
    if (i >= (size_t)NTOK*PDIM) return;
    int pd = (int)(i % PDIM);
    size_t bl = i / PDIM;
    int l = (int)(bl % LMAX);
    int b = (int)(bl / LMAX);
    int L = c_L[b], w = c_Wp[b];
    float v = 0.f;
    if (l < L){
        int c  = pd >> 8;
        int r  = pd & 255;
        int py = r >> 4, px = r & 15;
        int ph = l / w, pw = l % w;
        v = img[((size_t)(b*3 + c)*512 + (size_t)(ph*16 + py))*512 + (size_t)(pw*16 + px)];
    }
    tok[i] = v;
}

// ---------------- row LayerNorm; writes f32 (y) or fp16 (yh) ----------------
__global__ void ln_kernel(const float* __restrict__ x, const float* __restrict__ w,
                          const float* __restrict__ bb, float* __restrict__ y,
                          __half* __restrict__ yh, int D, int tokskip){
    __shared__ float red[8];
    int row = blockIdx.x, tid = threadIdx.x, lane = tid & 31, wp = tid >> 5;
    if (tokskip && (row & 1023) >= c_L[row >> 10]) return;
    const float* xr = x + (size_t)row*D;
    float lv[3]; float s = 0.f;
    #pragma unroll
    for (int i = 0; i < 3; i++){
        int idx = tid + i*256;
        float vv = (idx < D) ? xr[idx] : 0.f;
        lv[i] = vv; s += vv;
    }
    #pragma unroll
    for (int off = 16; off; off >>= 1) s += __shfl_xor_sync(0xffffffffu, s, off);
    if (lane == 0) red[wp] = s;
    __syncthreads();
    float tot = 0.f;
    #pragma unroll
    for (int i = 0; i < 8; i++) tot += red[i];
    float mu = tot / (float)D;
    __syncthreads();
    float vs = 0.f;
    #pragma unroll
    for (int i = 0; i < 3; i++){
        int idx = tid + i*256;
        if (idx < D){ float d = lv[i] - mu; vs += d*d; }
    }
    #pragma unroll
    for (int off = 16; off; off >>= 1) vs += __shfl_xor_sync(0xffffffffu, vs, off);
    if (lane == 0) red[wp] = vs;
    __syncthreads();
    float tv = 0.f;
    #pragma unroll
    for (int i = 0; i < 8; i++) tv += red[i];
    float rs = rsqrtf(tv / (float)D + 1e-5f);
    #pragma unroll
    for (int i = 0; i < 3; i++){
        int idx = tid + i*256;
        if (idx < D){
            float val = (lv[i] - mu)*rs*w[idx];
            if (bb) val += bb[idx];
            if (y) y[(size_t)row*D + idx] = val;
            else   yh[(size_t)row*D + idx] = __float2half_rn(val);
        }
    }
}

// ---------------- per-head LayerNorm over 64 dims (pool path) ----------------
__global__ void head_ln_kernel(float* __restrict__ x, const float* __restrict__ w, int rows){
    int gw = (int)(((size_t)blockIdx.x*blockDim.x + threadIdx.x) >> 5);
    int lane = threadIdx.x & 31;
    if (gw >= rows) return;
    float* p = x + (size_t)gw*64;
    float a = p[lane], b = p[lane + 32];
    float s = a + b;
    #pragma unroll
    for (int off = 16; off; off >>= 1) s += __shfl_xor_sync(0xffffffffu, s, off);
    float mu = s * (1.f/64.f);
    float da = a - mu, db = b - mu;
    float vs = da*da + db*db;
    #pragma unroll
    for (int off = 16; off; off >>= 1) vs += __shfl_xor_sync(0xffffffffu, vs, off);
    float rs = rsqrtf(vs * (1.f/64.f) + 1e-5f);
    p[lane]      = da * rs * w[lane];
    p[lane + 32] = db * rs * w[lane + 32];
}

// ---------------- pos embed + mask ----------------
__global__ void posmask_kernel(float* __restrict__ t, const float* __restrict__ ph,
                               const float* __restrict__ pw){
    int bl = blockIdx.x;
    int b = bl >> 10, l = bl & 1023;
    int L = c_L[b], w = c_Wp[b];
    float* r = t + (size_t)bl*DIM;
    int d = threadIdx.x;
    if (l < L) r[d] = r[d] + ph[(size_t)(l / w)*DIM + d] + pw[(size_t)(l % w)*DIM + d];
    else       r[d] = 0.f;
}

// ---------------- f32 SIMT GEMM NT (small M only) ----------------
__global__ __launch_bounds__(256) void gemm_nt_kernel(
    const float* __restrict__ A, int lda,
    const float* __restrict__ W, int ldw,
    const float* __restrict__ bias,
    float* __restrict__ C, int ldc,
    int M, int N, int K)
{
    __shared__ __align__(16) float As[8][128];
    __shared__ __align__(16) float Bs[8][128];
    int bm = blockIdx.y*128, bn = blockIdx.x*128;
    int tid = threadIdx.x;
    int tx = tid & 15, ty = tid >> 4;
    float acc[8][8];
    #pragma unroll
    for (int i = 0; i < 8; i++)
        #pragma unroll
        for (int j = 0; j < 8; j++) acc[i][j] = 0.f;
    int lr = tid >> 1;
    int lk = (tid & 1)*4;
    for (int k0 = 0; k0 < K; k0 += 8){
        float4 av = make_float4(0,0,0,0), bv = make_float4(0,0,0,0);
        if (bm + lr < M) av = *(const float4*)(A + (size_t)(bm + lr)*lda + k0 + lk);
        if (bn + lr < N) bv = *(const float4*)(W + (size_t)(bn + lr)*ldw + k0 + lk);
        As[lk+0][lr] = av.x; As[lk+1][lr] = av.y; As[lk+2][lr] = av.z; As[lk+3][lr] = av.w;
        Bs[lk+0][lr] = bv.x; Bs[lk+1][lr] = bv.y; Bs[lk+2][lr] = bv.z; Bs[lk+3][lr] = bv.w;
        __syncthreads();
        #pragma unroll
        for (int kk = 0; kk < 8; kk++){
            float a[8], b[8];
            #pragma unroll
            for (int i = 0; i < 8; i++) a[i] = As[kk][ty*8 + i];
            #pragma unroll
            for (int j = 0; j < 8; j++) b[j] = Bs[kk][tx*8 + j];
            #pragma unroll
            for (int i = 0; i < 8; i++)
                #pragma unroll
                for (int j = 0; j < 8; j++) acc[i][j] = fmaf(a[i], b[j], acc[i][j]);
        }
        __syncthreads();
    }
    #pragma unroll
    for (int i = 0; i < 8; i++){
        int m = bm + ty*8 + i;
        if (m >= M) continue;
        #pragma unroll
        for (int j = 0; j < 8; j++){
            int n = bn + tx*8 + j;
            if (n >= N) continue;
            float v = acc[i][j];
            if (bias) v += bias[n];
            C[(size_t)m*ldc + n] = v;
        }
    }
}

// ---------------- pooling attention (Lq=1) ----------------
__global__ void pool_attn_kernel(const float* __restrict__ qhat, const float* __restrict__ K,
                                 const float* __restrict__ V, float* __restrict__ O){
    int h = blockIdx.x, b = blockIdx.y;
    __shared__ float sq[64];
    __shared__ float sa[1024];
    __shared__ float red[8], red2[8];
    __shared__ float racc[4][64];
    int tid = threadIdx.x, lane = tid & 31, wp = tid >> 5;
    if (tid < 64) sq[tid] = qhat[h*64 + tid];
    __syncthreads();
    int L = c_L[b];
    for (int kk = tid; kk < 1024; kk += 256){
        float dot = -1e9f;
        if (kk < L){
            const float* kr = K + ((size_t)(b*1024 + kk))*DIM + h*64;
            float ss = 0.f;
            #pragma unroll
            for (int d = 0; d < 64; d++) ss += sq[d]*kr[d];
            dot = ss*0.125f;
        }
        sa[kk] = dot;
    }
    __syncthreads();
    float m = -1e30f;
    for (int kk = tid; kk < 1024; kk += 256) m = fmaxf(m, sa[kk]);
    #pragma unroll
    for (int off = 16; off; off >>= 1) m = fmaxf(m, __shfl_xor_sync(0xffffffffu, m, off));
    if (lane == 0) red[wp] = m;
    __syncthreads();
    float bm = -1e30f;
    #pragma unroll
    for (int i = 0; i < 8; i++) bm = fmaxf(bm, red[i]);
    float sum = 0.f;
    for (int kk = tid; kk < 1024; kk += 256){
        float e = __expf(sa[kk] - bm);
        sa[kk] = e; sum += e;
    }
    #pragma unroll
    for (int off = 16; off; off >>= 1) sum += __shfl_xor_sync(0xffffffffu, sum, off);
    if (lane == 0) red2[wp] = sum;
    __syncthreads();
    float bs = 0.f;
    #pragma unroll
    for (int i = 0; i < 8; i++) bs += red2[i];
    float inv = 1.f / bs;
    int dd = tid & 63, part = tid >> 6;
    float acc = 0.f;
    for (int kk = part; kk < 1024; kk += 4)
        acc += sa[kk] * V[((size_t)(b*1024 + kk))*DIM + h*64 + dd];
    racc[part][dd] = acc;
    __syncthreads();
    if (part == 0)
        O[b*DIM + h*64 + dd] = (racc[0][dd] + racc[1][dd] + racc[2][dd] + racc[3][dd]) * inv;
}

// ---------------- host helpers ----------------
static void launch_wcvt(const float* src, __half* h, long n){
    wcvt_kernel<<<(int)((n + 255)/256), 256>>>(src, h, (int)n);
}
static void launch_bg(const __half* A, int lda,
                      const __half* W, int ldw, long wz,
                      const float* bias, const float* R, int ldr,
                      float* C, __half* Ch, int ldc, long cz,
                      int N, int K, int act, int nz, int tokrows){
    dim3 g(N/128, NTOK/128, nz);
    bgemm_nt<<<g, 256, B_SMEM>>>(A, lda, W, ldw, wz, bias, R, ldr,
                                 C, Ch, ldc, cz, K, act, tokrows);
}
static void launch_small(const float* A, int lda, const float* W, int ldw,
                         const float* bias, float* C, int ldc, int M, int N, int K){
    dim3 g((N + 127)/128, (M + 127)/128, 1);
    gemm_nt_kernel<<<g, 256>>>(A, lda, W, ldw, bias, C, ldc, M, N, K);
}

extern "C" void kernel_launch(void* const* d_in, const int* in_sizes, int n_in,
                              void* d_out, int out_size){
    const float* images   = (const float*)d_in[0];
    const float* pe_ln1_w = (const float*)d_in[1];
    const float* pe_ln1_b = (const float*)d_in[2];
    const float* pe_w     = (const float*)d_in[3];
    const float* pe_b     = (const float*)d_in[4];
    const float* pe_ln2_w = (const float*)d_in[5];
    const float* pe_ln2_b = (const float*)d_in[6];
    const float* pos_h    = (const float*)d_in[7];
    const float* pos_w    = (const float*)d_in[8];
    const float* attn_ln  = (const float*)d_in[9];
    const float* wq       = (const float*)d_in[10];
    const float* wk       = (const float*)d_in[11];
    const float* wv       = (const float*)d_in[12];
    const float* qn       = (const float*)d_in[13];
    const float* kn       = (const float*)d_in[14];
    const float* wo       = (const float*)d_in[15];
    const float* ff_ln    = (const float*)d_in[16];
    const float* ff_w1    = (const float*)d_in[17];
    const float* ff_b1    = (const float*)d_in[18];
    const float* ff_w2    = (const float*)d_in[19];
    const float* ff_b2    = (const float*)d_in[20];
    const float* final_ln = (const float*)d_in[21];
    const float* pool_q   = (const float*)d_in[22];
    const float* pool_ln  = (const float*)d_in[23];
    const float* pool_wq  = (const float*)d_in[24];
    const float* pool_wk  = (const float*)d_in[25];
    const float* pool_wv  = (const float*)d_in[26];
    const float* pool_qn  = (const float*)d_in[27];
    const float* pool_kn  = (const float*)d_in[28];
    const float* pool_wo  = (const float*)d_in[29];
    const float* head_ln  = (const float*)d_in[30];
    const float* head_w   = (const float*)d_in[31];
    float* out = (float*)d_out;

    cudaFuncSetAttribute(bgemm_nt, cudaFuncAttributeMaxDynamicSharedMemorySize, B_SMEM);
    cudaFuncSetAttribute(flash_kernel, cudaFuncAttributeMaxDynamicSharedMemorySize, FSMEM);

    float *tok,*t,*qkv,*u,*qp,*po,*pooled,*hn;
    __half *wh,*lt,*xn,*mlp,*o,*qh,*kh,*vh;
    cudaGetSymbolAddress((void**)&tok, g_tok);
    cudaGetSymbolAddress((void**)&t,   g_t);
    cudaGetSymbolAddress((void**)&qkv, g_qkv);
    cudaGetSymbolAddress((void**)&u,   g_u);
    cudaGetSymbolAddress((void**)&qp,  g_qp);
    cudaGetSymbolAddress((void**)&po,  g_po);
    cudaGetSymbolAddress((void**)&pooled, g_pooled);
    cudaGetSymbolAddress((void**)&hn,  g_hn);
    cudaGetSymbolAddress((void**)&wh,  g_wh);
    cudaGetSymbolAddress((void**)&lt,  g_lt);
    cudaGetSymbolAddress((void**)&xn,  g_xn);
    cudaGetSymbolAddress((void**)&mlp, g_mlp);
    cudaGetSymbolAddress((void**)&o,   g_o);
    cudaGetSymbolAddress((void**)&qh,  g_qh2);
    cudaGetSymbolAddress((void**)&kh,  g_kh2);
    cudaGetSymbolAddress((void**)&vh,  g_vh2);

    float* kf = qkv + (size_t)NTOK*DIM;
    float* vf = qkv + (size_t)2*NTOK*DIM;

    // ---- weight convert (once per launch) ----
    launch_wcvt(wq, wh + OFF_QKV,            6L*DIM*DIM);
    launch_wcvt(wk, wh + OFF_QKV + 1572864L, 6L*DIM*DIM);
    launch_wcvt(wv, wh + OFF_QKV + 3145728L, 6L*DIM*DIM);
    launch_wcvt(wo, wh + OFF_WO,  6L*DIM*DIM);
    launch_wcvt(ff_w1, wh + OFF_FF1, 6L*MLPD*DIM);
    launch_wcvt(ff_w2, wh + OFF_FF2, 6L*DIM*MLPD);
    launch_wcvt(pe_w, wh + OFF_PE, (long)DIM*PDIM);
    launch_wcvt(pool_wk, wh + OFF_PK, (long)DIM*DIM);
    launch_wcvt(pool_wv, wh + OFF_PV, (long)DIM*DIM);

    // ---- patch embed ----
    pack_kernel<<<((size_t)NTOK*PDIM + 255)/256, 256>>>(images, tok);
    ln_kernel<<<NTOK, 256>>>(tok, pe_ln1_w, pe_ln1_b, nullptr, lt, PDIM, 1);
    launch_bg(lt, PDIM, wh + OFF_PE, PDIM, 0, pe_b,
              nullptr, 0, t, nullptr, DIM, 0, DIM, PDIM, 0, 1, 1);
    ln_kernel<<<NTOK, 256>>>(t, pe_ln2_w, pe_ln2_b, t, nullptr, DIM, 1);
    posmask_kernel<<<NTOK, DIM>>>(t, pos_h, pos_w);

    // ---- transformer layers ----
    for (int l = 0; l < NDEPTH; l++){
        ln_kernel<<<NTOK, 256>>>(t, attn_ln + l*DIM, nullptr, nullptr, xn, DIM, 1);
        launch_bg(xn, DIM, wh + OFF_QKV + (size_t)l*DIM*DIM, DIM, 1572864L,
                  nullptr, nullptr, 0,
                  qkv, nullptr, DIM, (long)NTOK*DIM, DIM, DIM, 0, 3, 1);
        kvprep_kernel<<<NTOK*HEADS*8/256, 256>>>(qkv, qn + l*DH, kn + l*DH, qh, kh, vh);
        flash_kernel<<<dim3(8, BB*HEADS), 256, FSMEM>>>(qh, kh, vh, o);
        launch_bg(o, DIM, wh + OFF_WO + (size_t)l*DIM*DIM, DIM, 0,
                  nullptr, t, DIM, t, nullptr, DIM, 0, DIM, DIM, 0, 1, 1);
        ln_kernel<<<NTOK, 256>>>(t, ff_ln + l*DIM, nullptr, nullptr, xn, DIM, 1);
        launch_bg(xn, DIM, wh + OFF_FF1 + (size_t)l*MLPD*DIM, DIM, 0,
                  ff_b1 + l*MLPD, nullptr, 0,
                  nullptr, mlp, MLPD, 0, MLPD, DIM, 1, 1, 1);
        launch_bg(mlp, MLPD, wh + OFF_FF2 + (size_t)l*DIM*MLPD, MLPD, 0,
                  ff_b2 + l*DIM, t, DIM, t, nullptr, DIM, 0, DIM, MLPD, 0, 1, 1);
    }

    // ---- final LN + pooling ----
    ln_kernel<<<NTOK, 256>>>(t, final_ln, nullptr, nullptr, xn, DIM, 1);
    ln_kernel<<<1, 256>>>(pool_q, pool_ln, nullptr, u, nullptr, DIM, 0);
    launch_small(u, DIM, pool_wq, DIM, nullptr, qp, DIM, 1, DIM, DIM);
    head_ln_kernel<<<1, 256>>>(qp, pool_qn, HEADS);
    launch_bg(xn, DIM, wh + OFF_PK, DIM, 0, nullptr, nullptr, 0,
              kf, nullptr, DIM, 0, DIM, DIM, 0, 1, 1);
    head_ln_kernel<<<(NTOK*HEADS*32 + 255)/256, 256>>>(kf, pool_kn, NTOK*HEADS);
    launch_bg(xn, DIM, wh + OFF_PV, DIM, 0, nullptr, nullptr, 0,
              vf, nullptr, DIM, 0, DIM, DIM, 0, 1, 1);
    pool_attn_kernel<<<dim3(HEADS, BB), 256>>>(qp, kf, vf, po);
    launch_small(po, DIM, pool_wo, DIM, nullptr, pooled, DIM, BB, DIM, DIM);
    ln_kernel<<<BB, 256>>>(pooled, head_ln, nullptr, hn, nullptr, DIM, 0);
    launch_small(hn, DIM, head_w, DIM, nullptr, out, NC, BB, NC, DIM);
}

// round 10
// speedup vs baseline: 15.4194x; 1.2041x over previous
#include <cuda_runtime.h>
#include <cuda_fp16.h>
#include <math.h>
#include <stdint.h>

#define BB 8
#define LMAX 1024
#define DIM 512
#define HEADS 8
#define DH 64
#define NDEPTH 6
#define MLPD 2048
#define NC 1000
#define PDIM 768
#define NTOK (BB*LMAX)   // 8192

__constant__ int c_L[8]  = {1024, 768, 896, 576, 560, 512, 384, 640};
__constant__ int c_Wp[8] = {  32,  24,  32,  24,  28,  32,  16,  20};

// weight buffer offsets (elements)
#define OFF_QKV 0L
#define OFF_WO  4718592L
#define OFF_FF1 6291456L
#define OFF_FF2 12582912L
#define OFF_PE  18874368L
#define OFF_PK  19267584L
#define OFF_PV  19529728L
#define WTOT    19791872L

// ---------------- scratch ----------------
__device__ __align__(128) float g_tok[(size_t)NTOK*PDIM];
__device__ __align__(128) float g_t  [(size_t)NTOK*DIM];
__device__ __align__(128) float g_qkv[(size_t)3*NTOK*DIM];
__device__ __align__(128) float g_u  [DIM];
__device__ __align__(128) float g_qp [DIM];
__device__ __align__(128) float g_po [BB*DIM];
__device__ __align__(128) float g_pooled[BB*DIM];
__device__ __align__(128) float g_hn [BB*DIM];
__device__ __align__(128) __half g_wh[WTOT];
__device__ __align__(128) __half g_lt [(size_t)NTOK*PDIM];
__device__ __align__(128) __half g_xn [(size_t)NTOK*DIM];
__device__ __align__(128) __half g_mlp[(size_t)NTOK*MLPD];
__device__ __align__(128) __half g_o  [(size_t)NTOK*DIM];
__device__ __align__(128) __half g_qkv16[(size_t)3*NTOK*DIM];
__device__ __align__(128) __half g_qh2[(size_t)NTOK*DIM];
__device__ __align__(128) __half g_kh2[(size_t)NTOK*DIM];
__device__ __align__(128) __half g_vh2[(size_t)NTOK*DIM];

// ================= helpers =================
__device__ __forceinline__ uint32_t smem_u32(const void* p){
    uint32_t a; asm("{ .reg .u64 t; cvta.to.shared.u64 t, %1; cvt.u32.u64 %0, t; }" : "=r"(a) : "l"(p));
    return a;
}
__device__ __forceinline__ void ldsm_x4(uint32_t* r, uint32_t addr){
    asm volatile("ldmatrix.sync.aligned.m8n8.x4.shared.b16 {%0,%1,%2,%3}, [%4];"
        : "=r"(r[0]),"=r"(r[1]),"=r"(r[2]),"=r"(r[3]) : "r"(addr));
}
__device__ __forceinline__ void ldsm_x2(uint32_t* r, uint32_t addr){
    asm volatile("ldmatrix.sync.aligned.m8n8.x2.shared.b16 {%0,%1}, [%2];"
        : "=r"(r[0]),"=r"(r[1]) : "r"(addr));
}
__device__ __forceinline__ void ldsm_x2t(uint32_t* r, uint32_t addr){
    asm volatile("ldmatrix.sync.aligned.m8n8.x2.trans.shared.b16 {%0,%1}, [%2];"
        : "=r"(r[0]),"=r"(r[1]) : "r"(addr));
}
__device__ __forceinline__ void mma16816(float* c, const uint32_t* a, const uint32_t* b){
    asm volatile("mma.sync.aligned.m16n8k16.row.col.f32.f16.f16.f32 "
        "{%0,%1,%2,%3}, {%4,%5,%6,%7}, {%8,%9}, {%0,%1,%2,%3};"
        : "+f"(c[0]),"+f"(c[1]),"+f"(c[2]),"+f"(c[3])
        : "r"(a[0]),"r"(a[1]),"r"(a[2]),"r"(a[3]), "r"(b[0]),"r"(b[1]));
}
__device__ __forceinline__ void cp_async16(uint32_t dst, const void* src){
    asm volatile("cp.async.cg.shared.global [%0], [%1], 16;" :: "r"(dst), "l"(src) : "memory");
}
__device__ __forceinline__ void cp_commit(){ asm volatile("cp.async.commit_group;" ::: "memory"); }
template<int N> __device__ __forceinline__ void cp_wait(){
    asm volatile("cp.async.wait_group %0;" :: "n"(N) : "memory");
}
__device__ __forceinline__ uint32_t h2u(__half2 v){ return *reinterpret_cast<uint32_t*>(&v); }
__device__ __forceinline__ uint32_t packh(float a, float b){
    return h2u(__float22half2_rn(make_float2(a, b)));
}
__device__ __forceinline__ uint4 cvt8s(float4 a, float4 b){
    return make_uint4(packh(a.x, a.y), packh(a.z, a.w), packh(b.x, b.y), packh(b.z, b.w));
}

// ---------------- weight f32 -> fp16 convert (vectorized, n % 4 == 0) ----------------
__global__ void wcvt_kernel(const float* __restrict__ src, __half* __restrict__ h, int n4){
    int i = blockIdx.x*blockDim.x + threadIdx.x;
    if (i >= n4) return;
    float4 v = ((const float4*)src)[i];
    ((uint2*)h)[i] = make_uint2(packh(v.x, v.y), packh(v.z, v.w));
}

// ============== cp.async HMMA GEMM NT: C = A @ W^T  (pure fp16, f32 accum) ==============
#define BTILE (128*144)          // 18432
#define B_A  0
#define B_W  BTILE
#define B_BUF (2*BTILE)          // 36864
#define B_SMEM (2*B_BUF)         // 73728

__global__ __launch_bounds__(256, 2) void bgemm_nt(
    const __half* __restrict__ A, int lda,
    const __half* __restrict__ W, int ldw, long wz,
    const float* __restrict__ bias,
    const float* __restrict__ R, int ldr,
    float* __restrict__ C, __half* __restrict__ Ch,
    int ldc, long cz,
    int K, int act, int tokrows)
{
    extern __shared__ char smem[];
    uint32_t sb = smem_u32(smem);
    int tid = threadIdx.x, lane = tid & 31, wid = tid >> 5;
    int z = blockIdx.z;
    W += (size_t)z*wz;
    if (C)  C  += (size_t)z*cz;
    if (Ch) Ch += (size_t)z*cz;
    int bm = blockIdx.y*128, bn = blockIdx.x*128;
    if (tokrows && (bm & 1023) >= c_L[bm >> 10]) return;
    int wr = (wid & 1)*64;
    int wn = (wid >> 1)*32;

    float acc[4][4][4];
    #pragma unroll
    for (int i = 0; i < 4; i++)
        #pragma unroll
        for (int j = 0; j < 4; j++)
            #pragma unroll
            for (int p = 0; p < 4; p++) acc[i][j][p] = 0.f;

#define BSTAGE(KC, BUFB) do { \
    _Pragma("unroll") \
    for (int it = 0; it < 4; it++){ \
        int slot = it*256 + tid; int row = slot >> 3, seg = slot & 7; \
        uint32_t so = (uint32_t)(BUFB) + (uint32_t)(row*144 + seg*16); \
        cp_async16(sb + B_A + so, A + (size_t)(bm + row)*lda + (KC)*64 + seg*8); \
        cp_async16(sb + B_W + so, W + (size_t)(bn + row)*ldw + (KC)*64 + seg*8); \
    } } while(0)

    int nk = K >> 6;
    BSTAGE(0, 0);
    cp_commit();

    int grp = lane >> 3, wi = lane & 7;
    for (int kc = 0; kc < nk; kc++){
        if (kc + 1 < nk){
            BSTAGE(kc + 1, ((kc + 1) & 1)*B_BUF);
            cp_commit();
            cp_wait<1>();
        } else {
            cp_wait<0>();
        }
        __syncthreads();
        uint32_t cur = (uint32_t)((kc & 1)*B_BUF);
        #pragma unroll
        for (int ks = 0; ks < 4; ks++){
            uint32_t a_f[4][4];
            #pragma unroll
            for (int mi = 0; mi < 4; mi++){
                uint32_t off = (uint32_t)((wr + mi*16 + wi + (grp & 1)*8)*144
                                          + (ks*16 + (grp >> 1)*8)*2);
                ldsm_x4(a_f[mi], sb + B_A + cur + off);
            }
            uint32_t b_f[4][2];
            #pragma unroll
            for (int ni = 0; ni < 4; ni++){
                uint32_t off = (uint32_t)((wn + ni*8 + (lane & 7))*144
                                          + (ks*16 + ((lane >> 3) & 1)*8)*2);
                ldsm_x2(b_f[ni], sb + B_W + cur + off);
            }
            #pragma unroll
            for (int mi = 0; mi < 4; mi++)
                #pragma unroll
                for (int ni = 0; ni < 4; ni++)
                    mma16816(acc[mi][ni], a_f[mi], b_f[ni]);
        }
        __syncthreads();
    }
#undef BSTAGE

    // ---- epilogue ----
    #pragma unroll
    for (int mi = 0; mi < 4; mi++){
        #pragma unroll
        for (int ni = 0; ni < 4; ni++){
            int gn = bn + wn + ni*8 + (lane & 3)*2;
            #pragma unroll
            for (int hh = 0; hh < 2; hh++){
                int m = bm + wr + mi*16 + (lane >> 2) + hh*8;
                float v0 = acc[mi][ni][hh*2 + 0];
                float v1 = acc[mi][ni][hh*2 + 1];
                if (bias){ v0 += bias[gn]; v1 += bias[gn + 1]; }
                if (act){
                    v0 = 0.5f*v0*(1.f + erff(v0*0.70710678118654752f));
                    v1 = 0.5f*v1*(1.f + erff(v1*0.70710678118654752f));
                }
                if (Ch){
                    *(uint32_t*)(Ch + (size_t)m*ldc + gn) = packh(v0, v1);
                } else {
                    if (R){
                        const float* rp = R + (size_t)m*ldr + gn;
                        v0 += rp[0]; v1 += rp[1];
                    }
                    *(float2*)(C + (size_t)m*ldc + gn) = make_float2(v0, v1);
                }
            }
        }
    }
}

// ============== kvprep: reads fp16 qkv; head-LN(Q x 1/8, K); writes fp16 ==============
__global__ void kvprep_kernel(const __half* __restrict__ qkv,
    const float* __restrict__ qn, const float* __restrict__ kn,
    __half* __restrict__ qh, __half* __restrict__ kh, __half* __restrict__ vh)
{
    int g = blockIdx.x*blockDim.x + threadIdx.x;   // NTOK*HEADS*8
    int seg = g & 7;
    int r = g >> 3;
    int tokn = r >> 3, h = r & 7;
    int b = tokn >> 10, l = tokn & 1023;
    if (l >= c_L[b]) return;
    size_t base = (size_t)tokn*DIM + h*64 + seg*8;

#define LD8H(P, X, Y) do { \
    uint4 raw = *(const uint4*)(P); \
    float2 f0 = __half22float2(*reinterpret_cast<__half2*>(&raw.x)); \
    float2 f1 = __half22float2(*reinterpret_cast<__half2*>(&raw.y)); \
    float2 f2 = __half22float2(*reinterpret_cast<__half2*>(&raw.z)); \
    float2 f3 = __half22float2(*reinterpret_cast<__half2*>(&raw.w)); \
    X = make_float4(f0.x, f0.y, f1.x, f1.y); \
    Y = make_float4(f2.x, f2.y, f3.x, f3.y); \
} while(0)

#define LN8(x, y, wvec, scale) do { \
    float sum = x.x + x.y + x.z + x.w + y.x + y.y + y.z + y.w; \
    sum += __shfl_xor_sync(0xffffffffu, sum, 1); \
    sum += __shfl_xor_sync(0xffffffffu, sum, 2); \
    sum += __shfl_xor_sync(0xffffffffu, sum, 4); \
    float mu = sum * (1.f/64.f); \
    x.x -= mu; x.y -= mu; x.z -= mu; x.w -= mu; \
    y.x -= mu; y.y -= mu; y.z -= mu; y.w -= mu; \
    float ss = x.x*x.x + x.y*x.y + x.z*x.z + x.w*x.w \
             + y.x*y.x + y.y*y.y + y.z*y.z + y.w*y.w; \
    ss += __shfl_xor_sync(0xffffffffu, ss, 1); \
    ss += __shfl_xor_sync(0xffffffffu, ss, 2); \
    ss += __shfl_xor_sync(0xffffffffu, ss, 4); \
    float rs = rsqrtf(ss * (1.f/64.f) + 1e-5f) * (scale); \
    float4 w0 = *(const float4*)((wvec) + seg*8); \
    float4 w1 = *(const float4*)((wvec) + seg*8 + 4); \
    x.x *= rs*w0.x; x.y *= rs*w0.y; x.z *= rs*w0.z; x.w *= rs*w0.w; \
    y.x *= rs*w1.x; y.y *= rs*w1.y; y.z *= rs*w1.z; y.w *= rs*w1.w; \
} while(0)

    {   // Q
        float4 x, y; LD8H(qkv + base, x, y);
        LN8(x, y, qn, 0.125f);
        *(uint4*)(qh + base) = cvt8s(x, y);
    }
    {   // K
        float4 x, y; LD8H(qkv + (size_t)NTOK*DIM + base, x, y);
        LN8(x, y, kn, 1.f);
        *(uint4*)(kh + base) = cvt8s(x, y);
    }
    {   // V (straight copy, already fp16)
        *(uint4*)(vh + base) = *(const uint4*)(qkv + (size_t)2*NTOK*DIM + base);
    }
#undef LN8
#undef LD8H
}

// ============== flash attention: pure fp16, cp.async double-buffered K/V ==============
#define FQ 0
#define FKV0 18432
#define FKVS 36864
#define FSMEM (18432 + 2*36864)          // 92160

__global__ __launch_bounds__(256, 2) void flash_kernel(
    const __half* __restrict__ Qh,
    const __half* __restrict__ Kh,
    const __half* __restrict__ Vh,
    __half* __restrict__ O)
{
    extern __shared__ char smem[];
    uint32_t sb = smem_u32(smem);
    int tid = threadIdx.x, lane = tid & 31, wid = tid >> 5;
    int qt = blockIdx.x;
    int bh = blockIdx.y;
    int b = bh >> 3, h = bh & 7;
    int L = c_L[b];
    if (qt*128 >= L) return;
    int ktiles = (L + 127) >> 7;

    // ---- stage Q ----
    #pragma unroll
    for (int it = 0; it < 4; it++){
        int slot = it*256 + tid; int row = slot >> 3, seg = slot & 7;
        size_t go = (size_t)(b*1024 + qt*128 + row)*DIM + h*64 + seg*8;
        cp_async16(sb + FQ + (uint32_t)(row*144 + seg*16), Qh + go);
    }
    cp_commit();

#define KVSTAGE(KT, SBASE) do { \
    _Pragma("unroll") \
    for (int it = 0; it < 4; it++){ \
        int slot = it*256 + tid; int row = slot >> 3, seg = slot & 7; \
        size_t go = (size_t)(b*1024 + (KT)*128 + row)*DIM + h*64 + seg*8; \
        uint32_t so = (uint32_t)(SBASE) + (uint32_t)(row*144 + seg*16); \
        cp_async16(sb + so,         Kh + go); \
        cp_async16(sb + so + 18432, Vh + go); \
    } } while(0)

    KVSTAGE(0, FKV0);
    cp_commit();

    cp_wait<1>();
    __syncthreads();

    int wr = wid*16;
    int grp = lane >> 3, wi = lane & 7;
    uint32_t aq[4][4];
    #pragma unroll
    for (int ks = 0; ks < 4; ks++){
        uint32_t off = (uint32_t)((wr + wi + (grp & 1)*8)*144 + (ks*16 + (grp >> 1)*8)*2);
        ldsm_x4(aq[ks], sb + FQ + off);
    }

    float m0 = -1e30f, m1 = -1e30f, l0 = 0.f, l1 = 0.f;
    float ao[8][4];
    #pragma unroll
    for (int i = 0; i < 8; i++)
        #pragma unroll
        for (int p = 0; p < 4; p++) ao[i][p] = 0.f;

    for (int kt = 0; kt < ktiles; kt++){
        if (kt + 1 < ktiles){
            KVSTAGE(kt + 1, FKV0 + ((kt + 1) & 1)*FKVS);
            cp_commit();
            cp_wait<1>();
        } else {
            cp_wait<0>();
        }
        __syncthreads();
        uint32_t kb = (uint32_t)(FKV0 + (kt & 1)*FKVS);

        // ---- S = Q K^T ----
        float s[16][4];
        #pragma unroll
        for (int i = 0; i < 16; i++)
            #pragma unroll
            for (int p = 0; p < 4; p++) s[i][p] = 0.f;
        #pragma unroll
        for (int ks = 0; ks < 4; ks++){
            #pragma unroll
            for (int ni = 0; ni < 16; ni++){
                uint32_t off = (uint32_t)((ni*8 + wi)*144 + (ks*16 + (grp & 1)*8)*2);
                uint32_t b_[2];
                ldsm_x2(b_, sb + kb + off);
                mma16816(s[ni], aq[ks], b_);
            }
        }

        // ---- mask (partial tile only) ----
        if (kt == ktiles - 1 && (L & 127)){
            int kbase = kt*128 + 2*(lane & 3);
            #pragma unroll
            for (int ni = 0; ni < 16; ni++){
                int kg = kbase + ni*8;
                if (kg     >= L){ s[ni][0] = -1e9f; s[ni][2] = -1e9f; }
                if (kg + 1 >= L){ s[ni][1] = -1e9f; s[ni][3] = -1e9f; }
            }
        }

        // ---- online softmax ----
        float tm0 = -1e30f, tm1 = -1e30f;
        #pragma unroll
        for (int ni = 0; ni < 16; ni++){
            tm0 = fmaxf(tm0, fmaxf(s[ni][0], s[ni][1]));
            tm1 = fmaxf(tm1, fmaxf(s[ni][2], s[ni][3]));
        }
        tm0 = fmaxf(tm0, __shfl_xor_sync(0xffffffffu, tm0, 1));
        tm0 = fmaxf(tm0, __shfl_xor_sync(0xffffffffu, tm0, 2));
        tm1 = fmaxf(tm1, __shfl_xor_sync(0xffffffffu, tm1, 1));
        tm1 = fmaxf(tm1, __shfl_xor_sync(0xffffffffu, tm1, 2));
        float mn0 = fmaxf(m0, tm0), mn1 = fmaxf(m1, tm1);
        float sc0 = __expf(m0 - mn0), sc1 = __expf(m1 - mn1);
        m0 = mn0; m1 = mn1;
        float ts0 = 0.f, ts1 = 0.f;
        #pragma unroll
        for (int ni = 0; ni < 16; ni++){
            s[ni][0] = __expf(s[ni][0] - m0);
            s[ni][1] = __expf(s[ni][1] - m0);
            s[ni][2] = __expf(s[ni][2] - m1);
            s[ni][3] = __expf(s[ni][3] - m1);
            ts0 += s[ni][0] + s[ni][1];
            ts1 += s[ni][2] + s[ni][3];
        }
        ts0 += __shfl_xor_sync(0xffffffffu, ts0, 1);
        ts0 += __shfl_xor_sync(0xffffffffu, ts0, 2);
        ts1 += __shfl_xor_sync(0xffffffffu, ts1, 1);
        ts1 += __shfl_xor_sync(0xffffffffu, ts1, 2);
        l0 = l0*sc0 + ts0;
        l1 = l1*sc1 + ts1;
        #pragma unroll
        for (int i = 0; i < 8; i++){
            ao[i][0] *= sc0; ao[i][1] *= sc0;
            ao[i][2] *= sc1; ao[i][3] *= sc1;
        }

        // ---- O += P V ----
        #pragma unroll
        for (int kk = 0; kk < 8; kk++){
            uint32_t ap[4];
            ap[0] = packh(s[2*kk][0],   s[2*kk][1]);
            ap[1] = packh(s[2*kk][2],   s[2*kk][3]);
            ap[2] = packh(s[2*kk+1][0], s[2*kk+1][1]);
            ap[3] = packh(s[2*kk+1][2], s[2*kk+1][3]);
            #pragma unroll
            for (int ni = 0; ni < 8; ni++){
                uint32_t off = (uint32_t)((kk*16 + (lane & 15))*144 + ni*16);
                uint32_t v_[2];
                ldsm_x2t(v_, sb + kb + 18432 + off);
                mma16816(ao[ni], ap, v_);
            }
        }
        __syncthreads();
    }
#undef KVSTAGE

    // ---- epilogue: fp16 O ----
    float il0 = 1.f / l0, il1 = 1.f / l1;
    int mrow = qt*128 + wr + (lane >> 2);
    #pragma unroll
    for (int ni = 0; ni < 8; ni++){
        int col = h*64 + ni*8 + 2*(lane & 3);
        *(uint32_t*)(O + (size_t)(b*1024 + mrow)*DIM + col)     = packh(ao[ni][0]*il0, ao[ni][1]*il0);
        *(uint32_t*)(O + (size_t)(b*1024 + mrow + 8)*DIM + col) = packh(ao[ni][2]*il1, ao[ni][3]*il1);
    }
}

// ---------------- patch packing ----------------
__global__ void pack_kernel(const float* __restrict__ img, float* __restrict__ tok){
    size_t i = (size_t)blockIdx.x*blockDim.x + threadIdx.x;
    if (i >= (size_t)NTOK*PDIM) return;
    int pd = (int)(i % PDIM);
    size_t bl = i / PDIM;
    int l = (int)(bl % LMAX);
    int b = (int)(bl / LMAX);
    int L = c_L[b], w = c_Wp[b];
    float v = 0.f;
    if (l < L){
        int c  = pd >> 8;
        int r  = pd & 255;
        int py = r >> 4, px = r & 15;
        int ph = l / w, pw = l % w;
        v = img[((size_t)(b*3 + c)*512 + (size_t)(ph*16 + py))*512 + (size_t)(pw*16 + px)];
    }
    tok[i] = v;
}

// ---------------- row LayerNorm, vectorized; writes f32 (y) or fp16 (yh) ----------------
__global__ void ln_kernel(const float* __restrict__ x, const float* __restrict__ w,
                          const float* __restrict__ bb, float* __restrict__ y,
                          __half* __restrict__ yh, int D, int tokskip){
    __shared__ float red[8];
    int row = blockIdx.x, tid = threadIdx.x, lane = tid & 31, wp = tid >> 5;
    int nw = blockDim.x >> 5;
    if (tokskip && (row & 1023) >= c_L[row >> 10]) return;
    int idx = tid*4;
    float4 v = make_float4(0,0,0,0);
    if (idx < D) v = *(const float4*)(x + (size_t)row*D + idx);
    float s = v.x + v.y + v.z + v.w;
    #pragma unroll
    for (int off = 16; off; off >>= 1) s += __shfl_xor_sync(0xffffffffu, s, off);
    if (lane == 0) red[wp] = s;
    __syncthreads();
    float tot = 0.f;
    for (int i = 0; i < nw; i++) tot += red[i];
    float mu = tot / (float)D;
    __syncthreads();
    float vs = 0.f;
    if (idx < D){
        float a = v.x - mu, b2 = v.y - mu, c = v.z - mu, d = v.w - mu;
        vs = a*a + b2*b2 + c*c + d*d;
    }
    #pragma unroll
    for (int off = 16; off; off >>= 1) vs += __shfl_xor_sync(0xffffffffu, vs, off);
    if (lane == 0) red[wp] = vs;
    __syncthreads();
    float tv = 0.f;
    for (int i = 0; i < nw; i++) tv += red[i];
    float rs = rsqrtf(tv / (float)D + 1e-5f);
    if (idx < D){
        float4 w4 = *(const float4*)(w + idx);
        float4 o;
        o.x = (v.x - mu)*rs*w4.x;
        o.y = (v.y - mu)*rs*w4.y;
        o.z = (v.z - mu)*rs*w4.z;
        o.w = (v.w - mu)*rs*w4.w;
        if (bb){
            float4 b4 = *(const float4*)(bb + idx);
            o.x += b4.x; o.y += b4.y; o.z += b4.z; o.w += b4.w;
        }
        if (y) *(float4*)(y + (size_t)row*D + idx) = o;
        else   *(uint2*)(yh + (size_t)row*D + idx) = make_uint2(packh(o.x, o.y), packh(o.z, o.w));
    }
}

// ---------------- fused LN + pos-embed + mask (D=512, in-place on t) ----------------
__global__ void ln_pos_kernel(float* __restrict__ t, const float* __restrict__ w,
                              const float* __restrict__ bb,
                              const float* __restrict__ ph, const float* __restrict__ pw){
    __shared__ float red[8];
    int row = blockIdx.x, tid = threadIdx.x, lane = tid & 31, wpi = tid >> 5;
    int nw = blockDim.x >> 5;
    int b = row >> 10, l = row & 1023;
    int L = c_L[b], wgrid = c_Wp[b];
    int idx = tid*4;
    if (l >= L){
        if (idx < DIM) *(float4*)(t + (size_t)row*DIM + idx) = make_float4(0,0,0,0);
        return;
    }
    float4 v = make_float4(0,0,0,0);
    if (idx < DIM) v = *(const float4*)(t + (size_t)row*DIM + idx);
    float s = v.x + v.y + v.z + v.w;
    #pragma unroll
    for (int off = 16; off; off >>= 1) s += __shfl_xor_sync(0xffffffffu, s, off);
    if (lane == 0) red[wpi] = s;
    __syncthreads();
    float tot = 0.f;
    for (int i = 0; i < nw; i++) tot += red[i];
    float mu = tot / (float)DIM;
    __syncthreads();
    float vs = 0.f;
    if (idx < DIM){
        float a = v.x - mu, b2 = v.y - mu, c = v.z - mu, d = v.w - mu;
        vs = a*a + b2*b2 + c*c + d*d;
    }
    #pragma unroll
    for (int off = 16; off; off >>= 1) vs += __shfl_xor_sync(0xffffffffu, vs, off);
    if (lane == 0) red[wpi] = vs;
    __syncthreads();
    float tv = 0.f;
    for (int i = 0; i < nw; i++) tv += red[i];
    float rs = rsqrtf(tv / (float)DIM + 1e-5f);
    if (idx < DIM){
        float4 w4 = *(const float4*)(w + idx);
        float4 b4 = *(const float4*)(bb + idx);
        float4 p0 = *(const float4*)(ph + (size_t)(l / wgrid)*DIM + idx);
        float4 p1 = *(const float4*)(pw + (size_t)(l % wgrid)*DIM + idx);
        float4 o;
        o.x = (v.x - mu)*rs*w4.x + b4.x + p0.x + p1.x;
        o.y = (v.y - mu)*rs*w4.y + b4.y + p0.y + p1.y;
        o.z = (v.z - mu)*rs*w4.z + b4.z + p0.z + p1.z;
        o.w = (v.w - mu)*rs*w4.w + b4.w + p0.w + p1.w;
        *(float4*)(t + (size_t)row*DIM + idx) = o;
    }
}

// ---------------- per-head LayerNorm over 64 dims (pool path) ----------------
__global__ void head_ln_kernel(float* __restrict__ x, const float* __restrict__ w, int rows){
    int gw = (int)(((size_t)blockIdx.x*blockDim.x + threadIdx.x) >> 5);
    int lane = threadIdx.x & 31;
    if (gw >= rows) return;
    float* p = x + (size_t)gw*64;
    float a = p[lane], b = p[lane + 32];
    float s = a + b;
    #pragma unroll
    for (int off = 16; off; off >>= 1) s += __shfl_xor_sync(0xffffffffu, s, off);
    float mu = s * (1.f/64.f);
    float da = a - mu, db = b - mu;
    float vs = da*da + db*db;
    #pragma unroll
    for (int off = 16; off; off >>= 1) vs += __shfl_xor_sync(0xffffffffu, vs, off);
    float rs = rsqrtf(vs * (1.f/64.f) + 1e-5f);
    p[lane]      = da * rs * w[lane];
    p[lane + 32] = db * rs * w[lane + 32];
}

// ---------------- tiny GEMM NT: warp per output element (small M) ----------------
__global__ void tiny_nt_kernel(const float* __restrict__ A, int lda,
                               const float* __restrict__ W, int ldw,
                               const float* __restrict__ bias,
                               float* __restrict__ C, int ldc,
                               int M, int N, int K){
    int gw = (int)(((size_t)blockIdx.x*blockDim.x + threadIdx.x) >> 5);
    int lane = threadIdx.x & 31;
    if (gw >= M*N) return;
    int m = gw / N, n = gw % N;
    const float* a = A + (size_t)m*lda;
    const float* wv = W + (size_t)n*ldw;
    float s = 0.f;
    for (int k = lane*4; k < K; k += 128){
        float4 av = *(const float4*)(a + k);
        float4 bv = *(const float4*)(wv + k);
        s += av.x*bv.x + av.y*bv.y + av.z*bv.z + av.w*bv.w;
    }
    #pragma unroll
    for (int off = 16; off; off >>= 1) s += __shfl_xor_sync(0xffffffffu, s, off);
    if (lane == 0){
        if (bias) s += bias[n];
        C[(size_t)m*ldc + n] = s;
    }
}

// ---------------- pooling attention (Lq=1) ----------------
__global__ void pool_attn_kernel(const float* __restrict__ qhat, const float* __restrict__ K,
                                 const float* __restrict__ V, float* __restrict__ O){
    int h = blockIdx.x, b = blockIdx.y;
    __shared__ float sq[64];
    __shared__ float sa[1024];
    __shared__ float red[8], red2[8];
    __shared__ float racc[4][64];
    int tid = threadIdx.x, lane = tid & 31, wp = tid >> 5;
    if (tid < 64) sq[tid] = qhat[h*64 + tid];
    __syncthreads();
    int L = c_L[b];
    for (int kk = tid; kk < 1024; kk += 256){
        float dot = -1e9f;
        if (kk < L){
            const float* kr = K + ((size_t)(b*1024 + kk))*DIM + h*64;
            float ss = 0.f;
            #pragma unroll
            for (int d = 0; d < 64; d++) ss += sq[d]*kr[d];
            dot = ss*0.125f;
        }
        sa[kk] = dot;
    }
    __syncthreads();
    float m = -1e30f;
    for (int kk = tid; kk < 1024; kk += 256) m = fmaxf(m, sa[kk]);
    #pragma unroll
    for (int off = 16; off; off >>= 1) m = fmaxf(m, __shfl_xor_sync(0xffffffffu, m, off));
    if (lane == 0) red[wp] = m;
    __syncthreads();
    float bm = -1e30f;
    #pragma unroll
    for (int i = 0; i < 8; i++) bm = fmaxf(bm, red[i]);
    float sum = 0.f;
    for (int kk = tid; kk < 1024; kk += 256){
        float e = __expf(sa[kk] - bm);
        sa[kk] = e; sum += e;
    }
    #pragma unroll
    for (int off = 16; off; off >>= 1) sum += __shfl_xor_sync(0xffffffffu, sum, off);
    if (lane == 0) red2[wp] = sum;
    __syncthreads();
    float bs = 0.f;
    #pragma unroll
    for (int i = 0; i < 8; i++) bs += red2[i];
    float inv = 1.f / bs;
    int dd = tid & 63, part = tid >> 6;
    float acc = 0.f;
    for (int kk = part; kk < 1024; kk += 4)
        acc += sa[kk] * V[((size_t)(b*1024 + kk))*DIM + h*64 + dd];
    racc[part][dd] = acc;
    __syncthreads();
    if (part == 0)
        O[b*DIM + h*64 + dd] = (racc[0][dd] + racc[1][dd] + racc[2][dd] + racc[3][dd]) * inv;
}

// ---------------- host helpers ----------------
static void launch_wcvt(const float* src, __half* h, long n){
    long n4 = n >> 2;
    wcvt_kernel<<<(int)((n4 + 255)/256), 256>>>(src, h, (int)n4);
}
static void launch_bg(const __half* A, int lda,
                      const __half* W, int ldw, long wz,
                      const float* bias, const float* R, int ldr,
                      float* C, __half* Ch, int ldc, long cz,
                      int N, int K, int act, int nz, int tokrows){
    dim3 g(N/128, NTOK/128, nz);
    bgemm_nt<<<g, 256, B_SMEM>>>(A, lda, W, ldw, wz, bias, R, ldr,
                                 C, Ch, ldc, cz, K, act, tokrows);
}
static void launch_tiny(const float* A, int lda, const float* W, int ldw,
                        const float* bias, float* C, int ldc, int M, int N, int K){
    int warps = M*N;
    tiny_nt_kernel<<<(warps*32 + 255)/256, 256>>>(A, lda, W, ldw, bias, C, ldc, M, N, K);
}

extern "C" void kernel_launch(void* const* d_in, const int* in_sizes, int n_in,
                              void* d_out, int out_size){
    const float* images   = (const float*)d_in[0];
    const float* pe_ln1_w = (const float*)d_in[1];
    const float* pe_ln1_b = (const float*)d_in[2];
    const float* pe_w     = (const float*)d_in[3];
    const float* pe_b     = (const float*)d_in[4];
    const float* pe_ln2_w = (const float*)d_in[5];
    const float* pe_ln2_b = (const float*)d_in[6];
    const float* pos_h    = (const float*)d_in[7];
    const float* pos_w    = (const float*)d_in[8];
    const float* attn_ln  = (const float*)d_in[9];
    const float* wq       = (const float*)d_in[10];
    const float* wk       = (const float*)d_in[11];
    const float* wv       = (const float*)d_in[12];
    const float* qn       = (const float*)d_in[13];
    const float* kn       = (const float*)d_in[14];
    const float* wo       = (const float*)d_in[15];
    const float* ff_ln    = (const float*)d_in[16];
    const float* ff_w1    = (const float*)d_in[17];
    const float* ff_b1    = (const float*)d_in[18];
    const float* ff_w2    = (const float*)d_in[19];
    const float* ff_b2    = (const float*)d_in[20];
    const float* final_ln = (const float*)d_in[21];
    const float* pool_q   = (const float*)d_in[22];
    const float* pool_ln  = (const float*)d_in[23];
    const float* pool_wq  = (const float*)d_in[24];
    const float* pool_wk  = (const float*)d_in[25];
    const float* pool_wv  = (const float*)d_in[26];
    const float* pool_qn  = (const float*)d_in[27];
    const float* pool_kn  = (const float*)d_in[28];
    const float* pool_wo  = (const float*)d_in[29];
    const float* head_ln  = (const float*)d_in[30];
    const float* head_w   = (const float*)d_in[31];
    float* out = (float*)d_out;

    cudaFuncSetAttribute(bgemm_nt, cudaFuncAttributeMaxDynamicSharedMemorySize, B_SMEM);
    cudaFuncSetAttribute(flash_kernel, cudaFuncAttributeMaxDynamicSharedMemorySize, FSMEM);

    float *tok,*t,*qkv,*u,*qp,*po,*pooled,*hn;
    __half *wh,*lt,*xn,*mlp,*o,*qkv16,*qh,*kh,*vh;
    cudaGetSymbolAddress((void**)&tok, g_tok);
    cudaGetSymbolAddress((void**)&t,   g_t);
    cudaGetSymbolAddress((void**)&qkv, g_qkv);
    cudaGetSymbolAddress((void**)&u,   g_u);
    cudaGetSymbolAddress((void**)&qp,  g_qp);
    cudaGetSymbolAddress((void**)&po,  g_po);
    cudaGetSymbolAddress((void**)&pooled, g_pooled);
    cudaGetSymbolAddress((void**)&hn,  g_hn);
    cudaGetSymbolAddress((void**)&wh,  g_wh);
    cudaGetSymbolAddress((void**)&lt,  g_lt);
    cudaGetSymbolAddress((void**)&xn,  g_xn);
    cudaGetSymbolAddress((void**)&mlp, g_mlp);
    cudaGetSymbolAddress((void**)&o,   g_o);
    cudaGetSymbolAddress((void**)&qkv16, g_qkv16);
    cudaGetSymbolAddress((void**)&qh,  g_qh2);
    cudaGetSymbolAddress((void**)&kh,  g_kh2);
    cudaGetSymbolAddress((void**)&vh,  g_vh2);

    float* kf = qkv + (size_t)NTOK*DIM;
    float* vf = qkv + (size_t)2*NTOK*DIM;

    // ---- weight convert (once per launch) ----
    launch_wcvt(wq, wh + OFF_QKV,            6L*DIM*DIM);
    launch_wcvt(wk, wh + OFF_QKV + 1572864L, 6L*DIM*DIM);
    launch_wcvt(wv, wh + OFF_QKV + 3145728L, 6L*DIM*DIM);
    launch_wcvt(wo, wh + OFF_WO,  6L*DIM*DIM);
    launch_wcvt(ff_w1, wh + OFF_FF1, 6L*MLPD*DIM);
    launch_wcvt(ff_w2, wh + OFF_FF2, 6L*DIM*MLPD);
    launch_wcvt(pe_w, wh + OFF_PE, (long)DIM*PDIM);
    launch_wcvt(pool_wk, wh + OFF_PK, (long)DIM*DIM);
    launch_wcvt(pool_wv, wh + OFF_PV, (long)DIM*DIM);

    // ---- patch embed ----
    pack_kernel<<<((size_t)NTOK*PDIM + 255)/256, 256>>>(images, tok);
    ln_kernel<<<NTOK, 256>>>(tok, pe_ln1_w, pe_ln1_b, nullptr, lt, PDIM, 1);
    launch_bg(lt, PDIM, wh + OFF_PE, PDIM, 0, pe_b,
              nullptr, 0, t, nullptr, DIM, 0, DIM, PDIM, 0, 1, 1);
    ln_pos_kernel<<<NTOK, 128>>>(t, pe_ln2_w, pe_ln2_b, pos_h, pos_w);

    // ---- transformer layers ----
    for (int l = 0; l < NDEPTH; l++){
        ln_kernel<<<NTOK, 128>>>(t, attn_ln + l*DIM, nullptr, nullptr, xn, DIM, 1);
        launch_bg(xn, DIM, wh + OFF_QKV + (size_t)l*DIM*DIM, DIM, 1572864L,
                  nullptr, nullptr, 0,
                  nullptr, qkv16, DIM, (long)NTOK*DIM, DIM, DIM, 0, 3, 1);
        kvprep_kernel<<<NTOK*HEADS*8/256, 256>>>(qkv16, qn + l*DH, kn + l*DH, qh, kh, vh);
        flash_kernel<<<dim3(8, BB*HEADS), 256, FSMEM>>>(qh, kh, vh, o);
        launch_bg(o, DIM, wh + OFF_WO + (size_t)l*DIM*DIM, DIM, 0,
                  nullptr, t, DIM, t, nullptr, DIM, 0, DIM, DIM, 0, 1, 1);
        ln_kernel<<<NTOK, 128>>>(t, ff_ln + l*DIM, nullptr, nullptr, xn, DIM, 1);
        launch_bg(xn, DIM, wh + OFF_FF1 + (size_t)l*MLPD*DIM, DIM, 0,
                  ff_b1 + l*MLPD, nullptr, 0,
                  nullptr, mlp, MLPD, 0, MLPD, DIM, 1, 1, 1);
        launch_bg(mlp, MLPD, wh + OFF_FF2 + (size_t)l*DIM*MLPD, MLPD, 0,
                  ff_b2 + l*DIM, t, DIM, t, nullptr, DIM, 0, DIM, MLPD, 0, 1, 1);
    }

    // ---- final LN + pooling ----
    ln_kernel<<<NTOK, 128>>>(t, final_ln, nullptr, nullptr, xn, DIM, 1);
    ln_kernel<<<1, 128>>>(pool_q, pool_ln, nullptr, u, nullptr, DIM, 0);
    launch_tiny(u, DIM, pool_wq, DIM, nullptr, qp, DIM, 1, DIM, DIM);
    head_ln_kernel<<<1, 256>>>(qp, pool_qn, HEADS);
    launch_bg(xn, DIM, wh + OFF_PK, DIM, 0, nullptr, nullptr, 0,
              kf, nullptr, DIM, 0, DIM, DIM, 0, 1, 1);
    head_ln_kernel<<<(NTOK*HEADS*32 + 255)/256, 256>>>(kf, pool_kn, NTOK*HEADS);
    launch_bg(xn, DIM, wh + OFF_PV, DIM, 0, nullptr, nullptr, 0,
              vf, nullptr, DIM, 0, DIM, DIM, 0, 1, 1);
    pool_attn_kernel<<<dim3(HEADS, BB), 256>>>(qp, kf, vf, po);
    launch_tiny(po, DIM, pool_wo, DIM, nullptr, pooled, DIM, BB, DIM, DIM);
    ln_kernel<<<BB, 128>>>(pooled, head_ln, nullptr, hn, nullptr, DIM, 0);
    launch_tiny(hn, DIM, head_w, DIM, nullptr, out, NC, BB, NC, DIM);
}